// round 1
// baseline (speedup 1.0000x reference)
#include <cuda_runtime.h>
#include <math.h>

// ---------------- problem constants ----------------
#define BB 32
#define TT 512
#define DD 512
#define LL 6
#define HH 8
#define HD 64
#define FF 2048      // 4*D
#define EH 4
#define EHD 128
#define MM 100000u
#define OVL 64
#define NTOK (BB*TT)   // 16384

// ---------------- scratch (device globals; no allocations allowed) ----------------
__device__ float g_x[NTOK*DD];
__device__ float g_nx[NTOK*DD];
__device__ float g_q[NTOK*DD];
__device__ float g_k[NTOK*DD];
__device__ float g_v[NTOK*DD];
__device__ float g_attn[NTOK*DD];
__device__ float g_ff[(size_t)NTOK*FF];
__device__ float g_ctx[BB*DD];
__device__ float g_logits[NTOK*EH];
__device__ float g_wv[BB*DD];
__device__ float g_u[BB*EH];

// ---------------- reduction helpers ----------------
__device__ __forceinline__ float warpReduceSum(float v) {
    #pragma unroll
    for (int o = 16; o; o >>= 1) v += __shfl_xor_sync(0xffffffffu, v, o);
    return v;
}
__device__ __forceinline__ float warpReduceMax(float v) {
    #pragma unroll
    for (int o = 16; o; o >>= 1) v = fmaxf(v, __shfl_xor_sync(0xffffffffu, v, o));
    return v;
}
// exactly 128 threads
__device__ __forceinline__ float blockReduceSum128(float v) {
    __shared__ float sm[4];
    __syncthreads();
    v = warpReduceSum(v);
    if ((threadIdx.x & 31) == 0) sm[threadIdx.x >> 5] = v;
    __syncthreads();
    return sm[0] + sm[1] + sm[2] + sm[3];
}
__device__ __forceinline__ float blockReduceMax128(float v) {
    __shared__ float sm[4];
    __syncthreads();
    v = warpReduceMax(v);
    if ((threadIdx.x & 31) == 0) sm[threadIdx.x >> 5] = v;
    __syncthreads();
    return fmaxf(fmaxf(sm[0], sm[1]), fmaxf(sm[2], sm[3]));
}

// ---------------- context projection: ctxadd[b,d] = concat(fast,slow)@ctx_W + ctx_b ----------------
__global__ void ctx_kernel(const float* __restrict__ fast, const float* __restrict__ slow,
                           const float* __restrict__ W, const float* __restrict__ bias,
                           float* __restrict__ out) {
    int b = blockIdx.x, d = threadIdx.x;           // 512 threads
    float acc = bias[d];
    const float* fb = fast + b*DD;
    const float* sb = slow + b*DD;
    for (int k = 0; k < DD; k++) acc += fb[k] * W[(size_t)k*DD + d];
    for (int k = 0; k < DD; k++) acc += sb[k] * W[(size_t)(k+DD)*DD + d];
    out[b*DD + d] = acc;
}

// ---------------- embedding + context + engram retrieval ----------------
__global__ void embed_kernel(const int* __restrict__ tokens, const int* __restrict__ prev,
                             const float* __restrict__ embed, const float* __restrict__ ctxadd,
                             const float* __restrict__ etab, const float* __restrict__ egate,
                             float* __restrict__ X) {
    int row = blockIdx.x;                 // b*T + t
    int b = row >> 9, t = row & 511;
    __shared__ unsigned int sidx[EH];
    int tid = threadIdx.x;                // 128 threads
    if (tid < EH) {
        unsigned int xseed = 131u + (unsigned)tid * 1009u;
        unsigned int hs = 0u;
        #pragma unroll
        for (int i = 0; i < 4; i++) {
            unsigned int p = xseed; xseed = xseed * 31u + 1u;
            int pos = t - i;
            unsigned int tok = (pos >= 0) ? (unsigned)tokens[b*TT + pos]
                                          : (unsigned)prev[b*OVL + OVL + pos];
            hs += tok * p;
        }
        sidx[tid] = hs % MM;
    }
    __syncthreads();
    int d0 = tid * 4;
    int eh = tid >> 5;
    int jj = d0 & 127;
    int tok = tokens[b*TT + t];
    float4 ev = *(const float4*)(embed + (size_t)tok*DD + d0);
    float4 cv = *(const float4*)(ctxadd + b*DD + d0);
    float4 rv = *(const float4*)(etab + ((size_t)sidx[eh]*EH + eh)*EHD + jj);
    float4 gv = *(const float4*)(egate + eh*EHD + jj);
    float4 o;
    o.x = ev.x + cv.x + rv.x * (1.f/(1.f+expf(-gv.x)));
    o.y = ev.y + cv.y + rv.y * (1.f/(1.f+expf(-gv.y)));
    o.z = ev.z + cv.z + rv.z * (1.f/(1.f+expf(-gv.z)));
    o.w = ev.w + cv.w + rv.w * (1.f/(1.f+expf(-gv.w)));
    *(float4*)(X + (size_t)row*DD + d0) = o;
}

// ---------------- RMSNorm ----------------
__global__ void rmsnorm_kernel(const float* __restrict__ X, const float* __restrict__ scale,
                               float* __restrict__ Out) {
    int row = blockIdx.x;
    float4 v = ((const float4*)(X + (size_t)row*DD))[threadIdx.x];
    float ss = v.x*v.x + v.y*v.y + v.z*v.z + v.w*v.w;
    ss = blockReduceSum128(ss);
    float inv = rsqrtf(ss * (1.f/DD) + 1e-6f);
    float4 sc = ((const float4*)scale)[threadIdx.x];
    float4 o;
    o.x = v.x*inv*sc.x; o.y = v.y*inv*sc.y; o.z = v.z*inv*sc.z; o.w = v.w*inv*sc.w;
    ((float4*)(Out + (size_t)row*DD))[threadIdx.x] = o;
}

// ---------------- SGEMM: C = A@B (+bias)(+res).  M%128==0, N%64==0, K%16==0 ----------------
// MODE 0: +bias; MODE 1: +bias +res; MODE 2: +res
template<int MODE>
__global__ void sgemm_kernel(const float* __restrict__ A, const float* __restrict__ Bm,
                             const float* __restrict__ bias, const float* __restrict__ Res,
                             float* __restrict__ C, int M, int N, int K) {
    __shared__ float As[16][132];
    __shared__ float Bs[16][68];
    int tid = threadIdx.x;
    int tx = tid & 15, ty = tid >> 4;
    int m0 = blockIdx.x * 128;
    int n0 = blockIdx.y * 64;
    float acc[8][4];
    #pragma unroll
    for (int i = 0; i < 8; i++)
        #pragma unroll
        for (int j = 0; j < 4; j++) acc[i][j] = 0.f;
    const int arow = tid >> 2;
    const int akp  = (tid & 3) * 4;
    const int brow = tid >> 4;
    const int bcol = (tid & 15) * 4;
    for (int k0 = 0; k0 < K; k0 += 16) {
        #pragma unroll
        for (int p = 0; p < 2; p++) {
            int r = arow + p*64;
            float4 v = *(const float4*)(A + (size_t)(m0 + r)*K + k0 + akp);
            As[akp+0][r] = v.x; As[akp+1][r] = v.y; As[akp+2][r] = v.z; As[akp+3][r] = v.w;
        }
        {
            float4 v = *(const float4*)(Bm + (size_t)(k0 + brow)*N + n0 + bcol);
            *(float4*)&Bs[brow][bcol] = v;
        }
        __syncthreads();
        #pragma unroll
        for (int k = 0; k < 16; k++) {
            float4 a0 = *(const float4*)&As[k][ty*8];
            float4 a1 = *(const float4*)&As[k][ty*8+4];
            float4 bv = *(const float4*)&Bs[k][tx*4];
            float a[8] = {a0.x,a0.y,a0.z,a0.w,a1.x,a1.y,a1.z,a1.w};
            float bvv[4] = {bv.x,bv.y,bv.z,bv.w};
            #pragma unroll
            for (int i = 0; i < 8; i++)
                #pragma unroll
                for (int j = 0; j < 4; j++) acc[i][j] += a[i]*bvv[j];
        }
        __syncthreads();
    }
    int row0 = m0 + ty*8;
    int col0 = n0 + tx*4;
    float4 bv4 = make_float4(0.f,0.f,0.f,0.f);
    if (MODE == 0 || MODE == 1) bv4 = *(const float4*)(bias + col0);
    #pragma unroll
    for (int i = 0; i < 8; i++) {
        size_t off = (size_t)(row0+i)*N + col0;
        float4 r;
        r.x = acc[i][0] + bv4.x; r.y = acc[i][1] + bv4.y;
        r.z = acc[i][2] + bv4.z; r.w = acc[i][3] + bv4.w;
        if (MODE == 1 || MODE == 2) {
            float4 rs = *(const float4*)(Res + off);
            r.x += rs.x; r.y += rs.y; r.z += rs.z; r.w += rs.w;
        }
        *(float4*)(C + off) = r;
    }
}

// ---------------- gated FFN GEMM: C = silu(A@Wg) * (A@Wv), Wg/Wv cols of W1 (K x 2N) ----------------
__global__ void gated_gemm_kernel(const float* __restrict__ A, const float* __restrict__ Bw,
                                  float* __restrict__ C, int M, int N, int K) {
    __shared__ float As[16][132];
    __shared__ float Bg[16][68];
    __shared__ float Bv[16][68];
    int tid = threadIdx.x;
    int tx = tid & 15, ty = tid >> 4;
    int m0 = blockIdx.x * 128;
    int n0 = blockIdx.y * 64;
    int ldb = 2*N;
    float accg[8][4], accv[8][4];
    #pragma unroll
    for (int i = 0; i < 8; i++)
        #pragma unroll
        for (int j = 0; j < 4; j++) { accg[i][j] = 0.f; accv[i][j] = 0.f; }
    const int arow = tid >> 2;
    const int akp  = (tid & 3) * 4;
    const int brow = tid >> 4;
    const int bcol = (tid & 15) * 4;
    for (int k0 = 0; k0 < K; k0 += 16) {
        #pragma unroll
        for (int p = 0; p < 2; p++) {
            int r = arow + p*64;
            float4 v = *(const float4*)(A + (size_t)(m0 + r)*K + k0 + akp);
            As[akp+0][r] = v.x; As[akp+1][r] = v.y; As[akp+2][r] = v.z; As[akp+3][r] = v.w;
        }
        {
            const float* bp = Bw + (size_t)(k0 + brow)*ldb + n0 + bcol;
            *(float4*)&Bg[brow][bcol] = *(const float4*)bp;
            *(float4*)&Bv[brow][bcol] = *(const float4*)(bp + N);
        }
        __syncthreads();
        #pragma unroll
        for (int k = 0; k < 16; k++) {
            float4 a0 = *(const float4*)&As[k][ty*8];
            float4 a1 = *(const float4*)&As[k][ty*8+4];
            float4 bg = *(const float4*)&Bg[k][tx*4];
            float4 bvv = *(const float4*)&Bv[k][tx*4];
            float a[8] = {a0.x,a0.y,a0.z,a0.w,a1.x,a1.y,a1.z,a1.w};
            float gg[4] = {bg.x,bg.y,bg.z,bg.w};
            float vv[4] = {bvv.x,bvv.y,bvv.z,bvv.w};
            #pragma unroll
            for (int i = 0; i < 8; i++)
                #pragma unroll
                for (int j = 0; j < 4; j++) {
                    accg[i][j] += a[i]*gg[j];
                    accv[i][j] += a[i]*vv[j];
                }
        }
        __syncthreads();
    }
    int row0 = m0 + ty*8;
    int col0 = n0 + tx*4;
    #pragma unroll
    for (int i = 0; i < 8; i++) {
        size_t off = (size_t)(row0+i)*N + col0;
        float4 r;
        float g0 = accg[i][0], g1 = accg[i][1], g2 = accg[i][2], g3 = accg[i][3];
        r.x = g0/(1.f+expf(-g0)) * accv[i][0];
        r.y = g1/(1.f+expf(-g1)) * accv[i][1];
        r.z = g2/(1.f+expf(-g2)) * accv[i][2];
        r.w = g3/(1.f+expf(-g3)) * accv[i][3];
        *(float4*)(C + off) = r;
    }
}

// ---------------- RoPE (in place on q and k) ----------------
__global__ void rope_kernel(float* __restrict__ Q, float* __restrict__ K) {
    int row = blockIdx.x;              // b*T + t
    int t = row & (TT-1);
    int h = threadIdx.x >> 5, j = threadIdx.x & 31;   // 256 threads
    float inv = expf(-(float)(2*j) * (9.210340371976184f / 64.f));
    float ang = (float)t * inv;
    float sn, cs;
    sincosf(ang, &sn, &cs);
    size_t base = (size_t)row*DD + h*HD + 2*j;
    float q0 = Q[base], q1 = Q[base+1];
    Q[base]   = q0*cs - q1*sn;
    Q[base+1] = q0*sn + q1*cs;
    float k0 = K[base], k1 = K[base+1];
    K[base]   = k0*cs - k1*sn;
    K[base+1] = k0*sn + k1*cs;
}

// ---------------- causal flash attention: BQ=64, BK=32, HD=64 ----------------
__global__ void flash_kernel(const float* __restrict__ Q, const float* __restrict__ K,
                             const float* __restrict__ V, float* __restrict__ O) {
    __shared__ float qs[64][68];
    __shared__ float ks[32][68];
    __shared__ float vs[32][68];
    __shared__ float ps[64][36];
    int bh = blockIdx.y;
    int b = bh >> 3, h = bh & 7;
    int q0 = blockIdx.x * 64;
    int tid = threadIdx.x;                // 256
    int tx = tid & 15, ty = tid >> 4;
    size_t base = ((size_t)b*TT)*DD + h*HD;
    for (int i = tid; i < 64*16; i += 256) {
        int r = i >> 4, dv = (i & 15) * 4;
        float4 v = *(const float4*)(Q + base + (size_t)(q0 + r)*DD + dv);
        qs[r][dv] = v.x; qs[r][dv+1] = v.y; qs[r][dv+2] = v.z; qs[r][dv+3] = v.w;
    }
    float m[4], l[4], o[4][4];
    #pragma unroll
    for (int i = 0; i < 4; i++) {
        m[i] = -1e30f; l[i] = 0.f;
        #pragma unroll
        for (int j = 0; j < 4; j++) o[i][j] = 0.f;
    }
    int r0 = ty*4, c0 = tx*2, d0 = tx*4;
    int nkt = (q0 + 64) >> 5;
    const float scl = 0.125f;             // 1/sqrt(64)
    for (int kt = 0; kt < nkt; kt++) {
        int k0 = kt * 32;
        __syncthreads();
        for (int i = tid; i < 32*16; i += 256) {
            int r = i >> 4, dv = (i & 15)*4;
            float4 kv = *(const float4*)(K + base + (size_t)(k0 + r)*DD + dv);
            ks[r][dv] = kv.x; ks[r][dv+1] = kv.y; ks[r][dv+2] = kv.z; ks[r][dv+3] = kv.w;
            float4 vv = *(const float4*)(V + base + (size_t)(k0 + r)*DD + dv);
            vs[r][dv] = vv.x; vs[r][dv+1] = vv.y; vs[r][dv+2] = vv.z; vs[r][dv+3] = vv.w;
        }
        __syncthreads();
        float s[4][2] = {{0.f,0.f},{0.f,0.f},{0.f,0.f},{0.f,0.f}};
        #pragma unroll 8
        for (int dd = 0; dd < 64; dd++) {
            float k0v = ks[c0][dd], k1v = ks[c0+1][dd];
            #pragma unroll
            for (int i = 0; i < 4; i++) {
                float qv = qs[r0+i][dd];
                s[i][0] += qv*k0v;
                s[i][1] += qv*k1v;
            }
        }
        float corr[4];
        #pragma unroll
        for (int i = 0; i < 4; i++) {
            int qq = q0 + r0 + i;
            #pragma unroll
            for (int j = 0; j < 2; j++) {
                int kk = k0 + c0 + j;
                s[i][j] = (kk <= qq) ? s[i][j]*scl : -1e9f;
            }
            float mx = fmaxf(s[i][0], s[i][1]);
            #pragma unroll
            for (int off = 8; off; off >>= 1) mx = fmaxf(mx, __shfl_xor_sync(0xffffffffu, mx, off));
            float mn = fmaxf(m[i], mx);
            float c = __expf(m[i] - mn);
            m[i] = mn;
            float p0 = __expf(s[i][0] - mn), p1 = __expf(s[i][1] - mn);
            ps[r0+i][c0]   = p0;
            ps[r0+i][c0+1] = p1;
            float sum = p0 + p1;
            #pragma unroll
            for (int off = 8; off; off >>= 1) sum += __shfl_xor_sync(0xffffffffu, sum, off);
            l[i] = l[i]*c + sum;
            corr[i] = c;
        }
        #pragma unroll
        for (int i = 0; i < 4; i++)
            #pragma unroll
            for (int j = 0; j < 4; j++) o[i][j] *= corr[i];
        __syncthreads();
        #pragma unroll 4
        for (int c = 0; c < 32; c++) {
            float4 vv = *(const float4*)&vs[c][d0];
            #pragma unroll
            for (int i = 0; i < 4; i++) {
                float pv = ps[r0+i][c];
                o[i][0] += pv*vv.x; o[i][1] += pv*vv.y;
                o[i][2] += pv*vv.z; o[i][3] += pv*vv.w;
            }
        }
    }
    #pragma unroll
    for (int i = 0; i < 4; i++) {
        float inv = 1.f / l[i];
        float4 r;
        r.x = o[i][0]*inv; r.y = o[i][1]*inv; r.z = o[i][2]*inv; r.w = o[i][3]*inv;
        *(float4*)(O + base + (size_t)(q0 + r0 + i)*DD + d0) = r;
    }
}

// ---------------- salience logits: (x @ sal_W + sal_b) / (softplus(temp)+0.3) ----------------
__global__ void logits_kernel(const float* __restrict__ X, const float* __restrict__ sal_W,
                              const float* __restrict__ sal_b, const float* __restrict__ temp,
                              float* __restrict__ out) {
    int row = blockIdx.x;
    int e = threadIdx.x >> 5, lane = threadIdx.x & 31;
    const float* xr = X + (size_t)row*DD;
    float acc = 0.f;
    for (int d = lane; d < DD; d += 32)
        acc += xr[d] * sal_W[d*EH + e];
    acc = warpReduceSum(acc);
    if (lane == 0) {
        float tp = log1pf(expf(temp[e])) + 0.3f;
        out[(size_t)row*EH + e] = (acc + sal_b[e]) / tp;
    }
}

// ---------------- masked softmax pool over T, per (b, e) ----------------
__global__ void pool_kernel(const int* __restrict__ tokens, const float* __restrict__ logits,
                            const float* __restrict__ X, const float* __restrict__ gate_W,
                            const float* __restrict__ gate_b,
                            float* __restrict__ wv_out, float* __restrict__ u_out) {
    int b = blockIdx.x >> 2, e = blockIdx.x & 3;
    int tid = threadIdx.x;                // 128
    __shared__ float ws[TT];
    float lg4[4]; int mv4[4];
    float lmax = -1e30f; float lvalid = 0.f;
    #pragma unroll
    for (int p = 0; p < 4; p++) {
        int t = tid + p*128;
        int mv = (tokens[b*TT + t] != 0);
        float lgv = logits[((size_t)b*TT + t)*EH + e];
        float sf = mv ? lgv : -1e9f;
        lg4[p] = sf; mv4[p] = mv;
        lmax = fmaxf(lmax, sf);
        lvalid += (float)mv;
    }
    float mx = blockReduceMax128(lmax);
    float lsum = 0.f;
    #pragma unroll
    for (int p = 0; p < 4; p++) {
        int t = tid + p*128;
        float ev = mv4[p] ? expf(lg4[p] - mx) : 0.f;
        ws[t] = ev;
        lsum += ev;
    }
    float ssum = blockReduceSum128(lsum);
    float nvalid = blockReduceSum128(lvalid);
    float wsc = 1.f / (ssum + 1e-6f);
    __syncthreads();
    float acc = 0.f;
    const float* xb = X + ((size_t)b*TT)*DD + e*EHD + tid;
    for (int t = 0; t < TT; t++)
        acc += ws[t] * xb[(size_t)t*DD];
    acc *= wsc;
    wv_out[b*DD + e*EHD + tid] = acc;
    float gsum = blockReduceSum128(acc * gate_W[tid]);
    if (tid == 0) {
        float gl = gsum + gate_b[0];
        float u = (nvalid > 0.f) ? 1.f/(1.f+expf(-gl)) : 0.f;
        u_out[b*EH + e] = u;
    }
}

// ---------------- fast/slow state update ----------------
__global__ void update_kernel(const float* __restrict__ wv, const float* __restrict__ u,
                              const float* __restrict__ sal_rms,
                              const float* __restrict__ fast, const float* __restrict__ slow,
                              float* __restrict__ out_fast, float* __restrict__ out_slow) {
    int b = blockIdx.x, tid = threadIdx.x;   // 128
    float4 v = ((const float4*)(wv + b*DD))[tid];
    float ss = blockReduceSum128(v.x*v.x + v.y*v.y + v.z*v.z + v.w*v.w);
    float inv = rsqrtf(ss * (1.f/DD) + 1e-6f);
    float4 sr = ((const float4*)sal_rms)[tid];
    int e = tid >> 5;
    float uu = u[b*EH + e];
    float4 f = ((const float4*)(fast + b*DD))[tid];
    float4 s = ((const float4*)(slow + b*DD))[tid];
    float4 wn;
    wn.x = v.x*inv*sr.x; wn.y = v.y*inv*sr.y; wn.z = v.z*inv*sr.z; wn.w = v.w*inv*sr.w;
    float4 nf, ns;
    nf.x = (1.f-uu)*f.x + uu*wn.x;  nf.y = (1.f-uu)*f.y + uu*wn.y;
    nf.z = (1.f-uu)*f.z + uu*wn.z;  nf.w = (1.f-uu)*f.w + uu*wn.w;
    float ud = 0.1f*uu;
    ns.x = (1.f-ud)*s.x + ud*wn.x;  ns.y = (1.f-ud)*s.y + ud*wn.y;
    ns.z = (1.f-ud)*s.z + ud*wn.z;  ns.w = (1.f-ud)*s.w + ud*wn.w;
    ((float4*)(out_fast + b*DD))[tid] = nf;
    ((float4*)(out_slow + b*DD))[tid] = ns;
}

// ---------------- launch ----------------
extern "C" void kernel_launch(void* const* d_in, const int* in_sizes, int n_in,
                              void* d_out, int out_size) {
    const int*   tokens = (const int*)  d_in[0];
    const int*   prev   = (const int*)  d_in[1];
    const float* fast   = (const float*)d_in[2];
    const float* slow   = (const float*)d_in[3];
    const float* embed  = (const float*)d_in[4];
    const float* ctx_W  = (const float*)d_in[5];
    const float* ctx_b  = (const float*)d_in[6];
    const float* etab   = (const float*)d_in[7];
    const float* egate  = (const float*)d_in[8];
    const float* ln1    = (const float*)d_in[9];
    const float* Wq     = (const float*)d_in[10];
    const float* bq     = (const float*)d_in[11];
    const float* Wk     = (const float*)d_in[12];
    const float* bk     = (const float*)d_in[13];
    const float* Wv     = (const float*)d_in[14];
    const float* bv     = (const float*)d_in[15];
    const float* Wo     = (const float*)d_in[16];
    const float* bo     = (const float*)d_in[17];
    const float* ln2    = (const float*)d_in[18];
    const float* W1     = (const float*)d_in[19];
    const float* W2     = (const float*)d_in[20];
    const float* ln_f   = (const float*)d_in[21];
    const float* sal_W  = (const float*)d_in[22];
    const float* sal_b  = (const float*)d_in[23];
    const float* temp   = (const float*)d_in[24];
    const float* gate_W = (const float*)d_in[25];
    const float* gate_b = (const float*)d_in[26];
    const float* sal_rms= (const float*)d_in[27];
    float* out = (float*)d_out;

    float *gx, *gnx, *gq, *gk, *gv, *gattn, *gff, *gctx, *glog, *gwv, *gu;
    cudaGetSymbolAddress((void**)&gx,   g_x);
    cudaGetSymbolAddress((void**)&gnx,  g_nx);
    cudaGetSymbolAddress((void**)&gq,   g_q);
    cudaGetSymbolAddress((void**)&gk,   g_k);
    cudaGetSymbolAddress((void**)&gv,   g_v);
    cudaGetSymbolAddress((void**)&gattn,g_attn);
    cudaGetSymbolAddress((void**)&gff,  g_ff);
    cudaGetSymbolAddress((void**)&gctx, g_ctx);
    cudaGetSymbolAddress((void**)&glog, g_logits);
    cudaGetSymbolAddress((void**)&gwv,  g_wv);
    cudaGetSymbolAddress((void**)&gu,   g_u);

    ctx_kernel<<<BB, 512>>>(fast, slow, ctx_W, ctx_b, gctx);
    embed_kernel<<<NTOK, 128>>>(tokens, prev, embed, gctx, etab, egate, gx);

    dim3 g512(NTOK/128, DD/64);
    dim3 g2048(NTOK/128, FF/64);
    for (int l = 0; l < LL; l++) {
        size_t wo = (size_t)l*DD*DD;
        rmsnorm_kernel<<<NTOK, 128>>>(gx, ln1 + l*DD, gnx);
        sgemm_kernel<0><<<g512, 256>>>(gnx, Wq + wo, bq + l*DD, nullptr, gq, NTOK, DD, DD);
        sgemm_kernel<0><<<g512, 256>>>(gnx, Wk + wo, bk + l*DD, nullptr, gk, NTOK, DD, DD);
        sgemm_kernel<0><<<g512, 256>>>(gnx, Wv + wo, bv + l*DD, nullptr, gv, NTOK, DD, DD);
        rope_kernel<<<NTOK, 256>>>(gq, gk);
        flash_kernel<<<dim3(TT/64, BB*HH), 256>>>(gq, gk, gv, gattn);
        sgemm_kernel<1><<<g512, 256>>>(gattn, Wo + wo, bo + l*DD, gx, gx, NTOK, DD, DD);
        rmsnorm_kernel<<<NTOK, 128>>>(gx, ln2 + l*DD, gnx);
        gated_gemm_kernel<<<g2048, 256>>>(gnx, W1 + (size_t)l*DD*2*FF, gff, NTOK, FF, DD);
        sgemm_kernel<2><<<g512, 256>>>(gff, W2 + (size_t)l*FF*DD, nullptr, gx, gx, NTOK, DD, FF);
    }
    rmsnorm_kernel<<<NTOK, 128>>>(gx, ln_f, out);
    logits_kernel<<<NTOK, 128>>>(out, sal_W, sal_b, temp, glog);
    pool_kernel<<<BB*EH, 128>>>(tokens, glog, out, gate_W, gate_b, gwv, gu);
    update_kernel<<<BB, 128>>>(gwv, gu, sal_rms, fast, slow,
                               out + (size_t)NTOK*DD,
                               out + (size_t)NTOK*DD + BB*DD);
}

// round 3
// speedup vs baseline: 1.6576x; 1.6576x over previous
#include <cuda_runtime.h>
#include <cuda_bf16.h>
#include <math.h>
#include <stdint.h>

// ---------------- problem constants ----------------
#define BB 32
#define TT 512
#define DD 512
#define LL 6
#define HH 8
#define HD 64
#define FF 2048      // 4*D
#define EH 4
#define EHD 128
#define MM 100000u
#define OVL 64
#define NTOK (BB*TT)   // 16384

// ---------------- scratch (device globals; no allocations allowed) ----------------
__device__ float g_x[NTOK*DD];
__device__ float g_q[NTOK*DD];
__device__ float g_k[NTOK*DD];
__device__ float g_v[NTOK*DD];
__device__ float g_ffg[(size_t)NTOK*FF];
__device__ float g_ffv[(size_t)NTOK*FF];
__device__ float g_ctx[BB*DD];
__device__ float g_logits[NTOK*EH];
__device__ float g_wv[BB*DD];
__device__ float g_u[BB*EH];
// bf16 split planes (hi/lo)
__device__ __nv_bfloat16 g_nxh[NTOK*DD];
__device__ __nv_bfloat16 g_nxl[NTOK*DD];
__device__ __nv_bfloat16 g_ath[NTOK*DD];
__device__ __nv_bfloat16 g_atl[NTOK*DD];
__device__ __nv_bfloat16 g_ffh[(size_t)NTOK*FF];
__device__ __nv_bfloat16 g_ffl[(size_t)NTOK*FF];
// transposed + split weights: [N][K] bf16 planes
__device__ __nv_bfloat16 g_wqh[LL*DD*DD];
__device__ __nv_bfloat16 g_wql[LL*DD*DD];
__device__ __nv_bfloat16 g_wkh[LL*DD*DD];
__device__ __nv_bfloat16 g_wkl[LL*DD*DD];
__device__ __nv_bfloat16 g_wvh[LL*DD*DD];
__device__ __nv_bfloat16 g_wvl[LL*DD*DD];
__device__ __nv_bfloat16 g_woh[LL*DD*DD];
__device__ __nv_bfloat16 g_wol[LL*DD*DD];
__device__ __nv_bfloat16 g_w1h[(size_t)LL*2*FF*DD];
__device__ __nv_bfloat16 g_w1l[(size_t)LL*2*FF*DD];
__device__ __nv_bfloat16 g_w2h[(size_t)LL*DD*FF];
__device__ __nv_bfloat16 g_w2l[(size_t)LL*DD*FF];

// ---------------- PTX helpers ----------------
__device__ __forceinline__ uint32_t smem_to_u32(const void* p) {
    uint32_t a;
    asm("{ .reg .u64 t; cvta.to.shared.u64 t, %1; cvt.u32.u64 %0, t; }" : "=r"(a) : "l"(p));
    return a;
}
__device__ __forceinline__ void cp16(uint32_t dst, const void* src) {
    asm volatile("cp.async.cg.shared.global [%0], [%1], 16;" :: "r"(dst), "l"(src));
}
#define CP_COMMIT() asm volatile("cp.async.commit_group;" ::: "memory")
#define CP_WAIT1()  asm volatile("cp.async.wait_group 1;" ::: "memory")

#define LDSM4(r, addr) \
    asm volatile("ldmatrix.sync.aligned.m8n8.x4.shared.b16 {%0,%1,%2,%3}, [%4];" \
        : "=r"((r)[0]), "=r"((r)[1]), "=r"((r)[2]), "=r"((r)[3]) : "r"(addr))

#define HMMA(c, a, b0, b1) \
    asm volatile("mma.sync.aligned.m16n8k16.row.col.f32.bf16.bf16.f32 " \
        "{%0,%1,%2,%3}, {%4,%5,%6,%7}, {%8,%9}, {%0,%1,%2,%3};" \
        : "+f"((c)[0]), "+f"((c)[1]), "+f"((c)[2]), "+f"((c)[3]) \
        : "r"((a)[0]), "r"((a)[1]), "r"((a)[2]), "r"((a)[3]), "r"(b0), "r"(b1))

__device__ __forceinline__ void bsplit(float x, __nv_bfloat16& h, __nv_bfloat16& l) {
    h = __float2bfloat16(x);
    l = __float2bfloat16(x - __bfloat162float(h));
}

// ---------------- reduction helpers ----------------
__device__ __forceinline__ float warpReduceSum(float v) {
    #pragma unroll
    for (int o = 16; o; o >>= 1) v += __shfl_xor_sync(0xffffffffu, v, o);
    return v;
}
__device__ __forceinline__ float warpReduceMax(float v) {
    #pragma unroll
    for (int o = 16; o; o >>= 1) v = fmaxf(v, __shfl_xor_sync(0xffffffffu, v, o));
    return v;
}
__device__ __forceinline__ float blockReduceSum128(float v) {
    __shared__ float sm[4];
    __syncthreads();
    v = warpReduceSum(v);
    if ((threadIdx.x & 31) == 0) sm[threadIdx.x >> 5] = v;
    __syncthreads();
    return sm[0] + sm[1] + sm[2] + sm[3];
}
__device__ __forceinline__ float blockReduceMax128(float v) {
    __shared__ float sm[4];
    __syncthreads();
    v = warpReduceMax(v);
    if ((threadIdx.x & 31) == 0) sm[threadIdx.x >> 5] = v;
    __syncthreads();
    return fmaxf(fmaxf(sm[0], sm[1]), fmaxf(sm[2], sm[3]));
}

// ---------------- weight transpose+split: dst[n][k] planes from src[k][n] ----------------
__global__ void tsplit_kernel(const float* __restrict__ src, int ldsrc, size_t srcStride,
                              __nv_bfloat16* __restrict__ hi, __nv_bfloat16* __restrict__ lo,
                              size_t dstStride, int K) {
    __shared__ float t[32][33];
    int l = blockIdx.z;
    const float* S = src + (size_t)l*srcStride;
    __nv_bfloat16* Hd = hi + (size_t)l*dstStride;
    __nv_bfloat16* Ld = lo + (size_t)l*dstStride;
    int n0 = blockIdx.x*32, k0 = blockIdx.y*32;
    int x = threadIdx.x, y = threadIdx.y;   // 32 x 8
    #pragma unroll
    for (int i = 0; i < 32; i += 8) t[y+i][x] = S[(size_t)(k0+y+i)*ldsrc + n0+x];
    __syncthreads();
    #pragma unroll
    for (int i = 0; i < 32; i += 8) {
        float v = t[x][y+i];
        __nv_bfloat16 h, lw;
        bsplit(v, h, lw);
        size_t off = (size_t)(n0+y+i)*K + k0+x;
        Hd[off] = h; Ld[off] = lw;
    }
}

// ---------------- split-bf16 HMMA GEMM ----------------
// C[M,N] = A[M,K] @ B^T, B stored [N][K].  A,B given as hi/lo bf16 planes.
// Product uses hi*hi + hi*lo + lo*hi (error ~2^-16).
// MODE 0: +bias ; 1: +bias +res ; 2: +res ; 3: plain
// smem per stage: 4 tiles (Ah, Al, Bh, Bl), each 128 rows x 32 halves, row stride 80B.
#define TILE_B 10240
#define STAGE_B 40960
#define HSMEM (2*STAGE_B)

__device__ __forceinline__ void load_stage(uint32_t sb,
        const __nv_bfloat16* Ah, const __nv_bfloat16* Al,
        const __nv_bfloat16* Bh, const __nv_bfloat16* Bl,
        int K, int kof, int tid) {
    #pragma unroll
    for (int i = 0; i < 2; i++) {
        int e = tid + i*256;              // 0..511
        int row = e >> 2, seg = e & 3;
        uint32_t off = (uint32_t)(row*80 + seg*16);
        size_t g = (size_t)row*K + kof + seg*8;
        cp16(sb + off,            Ah + g);
        cp16(sb + TILE_B + off,   Al + g);
        cp16(sb + 2*TILE_B + off, Bh + g);
        cp16(sb + 3*TILE_B + off, Bl + g);
    }
}

template<int MODE>
__global__ void __launch_bounds__(256)
hgemm(const __nv_bfloat16* __restrict__ Ah, const __nv_bfloat16* __restrict__ Al,
      const __nv_bfloat16* __restrict__ Bh, const __nv_bfloat16* __restrict__ Bl,
      const float* __restrict__ bias, const float* __restrict__ Res,
      float* __restrict__ C, int M, int N, int K) {
    extern __shared__ char dsm[];
    uint32_t sb = smem_to_u32(dsm);
    int tid = threadIdx.x, lane = tid & 31, wid = tid >> 5;
    int m0 = blockIdx.x * 128, n0 = blockIdx.y * 128;
    int wm = (wid & 1) * 64, wn = (wid >> 1) * 32;
    const __nv_bfloat16* Abh = Ah + (size_t)m0*K;
    const __nv_bfloat16* Abl = Al + (size_t)m0*K;
    const __nv_bfloat16* Bbh = Bh + (size_t)n0*K;
    const __nv_bfloat16* Bbl = Bl + (size_t)n0*K;
    int NC = K >> 5;

    load_stage(sb,           Abh, Abl, Bbh, Bbl, K, 0,  tid); CP_COMMIT();
    load_stage(sb + STAGE_B, Abh, Abl, Bbh, Bbl, K, 32, tid); CP_COMMIT();

    float acc[4][4][4];
    #pragma unroll
    for (int a = 0; a < 4; a++)
        #pragma unroll
        for (int b = 0; b < 4; b++)
            #pragma unroll
            for (int c = 0; c < 4; c++) acc[a][b][c] = 0.f;

    const int a_row = lane & 15;
    const int a_k   = (lane >> 4) * 8;
    const int b_row = (lane & 7) + ((lane >> 4) << 3);
    const int b_k   = ((lane >> 3) & 1) * 8;

    for (int i = 0; i < NC; i++) {
        CP_WAIT1();
        __syncthreads();
        uint32_t st = sb + (uint32_t)(i & 1) * STAGE_B;
        #pragma unroll
        for (int kk = 0; kk < 32; kk += 16) {
            uint32_t ah[4][4], al[4][4], bh2[2][4], bl2[2][4];
            #pragma unroll
            for (int mt = 0; mt < 4; mt++) {
                uint32_t ad = st + (uint32_t)((wm + mt*16 + a_row)*80 + (kk + a_k)*2);
                LDSM4(ah[mt], ad);
                LDSM4(al[mt], ad + TILE_B);
            }
            #pragma unroll
            for (int np = 0; np < 2; np++) {
                uint32_t bd = st + 2*TILE_B + (uint32_t)((wn + np*16 + b_row)*80 + (kk + b_k)*2);
                LDSM4(bh2[np], bd);
                LDSM4(bl2[np], bd + TILE_B);
            }
            #pragma unroll
            for (int mt = 0; mt < 4; mt++)
                #pragma unroll
                for (int nt = 0; nt < 4; nt++) {
                    uint32_t b0h = bh2[nt>>1][(nt&1)*2],  b1h = bh2[nt>>1][(nt&1)*2+1];
                    uint32_t b0l = bl2[nt>>1][(nt&1)*2],  b1l = bl2[nt>>1][(nt&1)*2+1];
                    HMMA(acc[mt][nt], ah[mt], b0h, b1h);
                    HMMA(acc[mt][nt], ah[mt], b0l, b1l);
                    HMMA(acc[mt][nt], al[mt], b0h, b1h);
                }
        }
        __syncthreads();
        if (i + 2 < NC)
            load_stage(st, Abh, Abl, Bbh, Bbl, K, (i+2)*32, tid);
        CP_COMMIT();
    }

    int gid = lane >> 2, ctg = lane & 3;
    #pragma unroll
    for (int mt = 0; mt < 4; mt++)
        #pragma unroll
        for (int nt = 0; nt < 4; nt++) {
            int r0 = m0 + wm + mt*16 + gid;
            int cc = n0 + wn + nt*8 + ctg*2;
            float2 v0 = make_float2(acc[mt][nt][0], acc[mt][nt][1]);
            float2 v1 = make_float2(acc[mt][nt][2], acc[mt][nt][3]);
            if (MODE == 0 || MODE == 1) {
                float2 bb = *(const float2*)(bias + cc);
                v0.x += bb.x; v0.y += bb.y; v1.x += bb.x; v1.y += bb.y;
            }
            if (MODE == 1 || MODE == 2) {
                float2 ra = *(const float2*)(Res + (size_t)r0*N + cc);
                float2 rb = *(const float2*)(Res + (size_t)(r0+8)*N + cc);
                v0.x += ra.x; v0.y += ra.y; v1.x += rb.x; v1.y += rb.y;
            }
            *(float2*)(C + (size_t)r0*N + cc) = v0;
            *(float2*)(C + (size_t)(r0+8)*N + cc) = v1;
        }
}

// ---------------- context projection ----------------
__global__ void ctx_kernel(const float* __restrict__ fast, const float* __restrict__ slow,
                           const float* __restrict__ W, const float* __restrict__ bias,
                           float* __restrict__ out) {
    int b = blockIdx.x, d = threadIdx.x;
    float acc = bias[d];
    const float* fb = fast + b*DD;
    const float* sb = slow + b*DD;
    for (int k = 0; k < DD; k++) acc += fb[k] * W[(size_t)k*DD + d];
    for (int k = 0; k < DD; k++) acc += sb[k] * W[(size_t)(k+DD)*DD + d];
    out[b*DD + d] = acc;
}

// ---------------- embedding + context + engram retrieval ----------------
__global__ void embed_kernel(const int* __restrict__ tokens, const int* __restrict__ prev,
                             const float* __restrict__ embed, const float* __restrict__ ctxadd,
                             const float* __restrict__ etab, const float* __restrict__ egate,
                             float* __restrict__ X) {
    int row = blockIdx.x;
    int b = row >> 9, t = row & 511;
    __shared__ unsigned int sidx[EH];
    int tid = threadIdx.x;
    if (tid < EH) {
        unsigned int xseed = 131u + (unsigned)tid * 1009u;
        unsigned int hs = 0u;
        #pragma unroll
        for (int i = 0; i < 4; i++) {
            unsigned int p = xseed; xseed = xseed * 31u + 1u;
            int pos = t - i;
            unsigned int tok = (pos >= 0) ? (unsigned)tokens[b*TT + pos]
                                          : (unsigned)prev[b*OVL + OVL + pos];
            hs += tok * p;
        }
        sidx[tid] = hs % MM;
    }
    __syncthreads();
    int d0 = tid * 4;
    int eh = tid >> 5;
    int jj = d0 & 127;
    int tok = tokens[b*TT + t];
    float4 ev = *(const float4*)(embed + (size_t)tok*DD + d0);
    float4 cv = *(const float4*)(ctxadd + b*DD + d0);
    float4 rv = *(const float4*)(etab + ((size_t)sidx[eh]*EH + eh)*EHD + jj);
    float4 gv = *(const float4*)(egate + eh*EHD + jj);
    float4 o;
    o.x = ev.x + cv.x + rv.x * (1.f/(1.f+expf(-gv.x)));
    o.y = ev.y + cv.y + rv.y * (1.f/(1.f+expf(-gv.y)));
    o.z = ev.z + cv.z + rv.z * (1.f/(1.f+expf(-gv.z)));
    o.w = ev.w + cv.w + rv.w * (1.f/(1.f+expf(-gv.w)));
    *(float4*)(X + (size_t)row*DD + d0) = o;
}

// ---------------- RMSNorm -> split bf16 planes ----------------
__global__ void rmsnorm_split_kernel(const float* __restrict__ X, const float* __restrict__ scale,
                                     __nv_bfloat16* __restrict__ H, __nv_bfloat16* __restrict__ Lo) {
    int row = blockIdx.x;
    float4 v = ((const float4*)(X + (size_t)row*DD))[threadIdx.x];
    float ss = v.x*v.x + v.y*v.y + v.z*v.z + v.w*v.w;
    ss = blockReduceSum128(ss);
    float inv = rsqrtf(ss * (1.f/DD) + 1e-6f);
    float4 sc = ((const float4*)scale)[threadIdx.x];
    float o0 = v.x*inv*sc.x, o1 = v.y*inv*sc.y, o2 = v.z*inv*sc.z, o3 = v.w*inv*sc.w;
    __nv_bfloat16 h[4], l[4];
    bsplit(o0, h[0], l[0]); bsplit(o1, h[1], l[1]);
    bsplit(o2, h[2], l[2]); bsplit(o3, h[3], l[3]);
    size_t off = (size_t)row*DD + threadIdx.x*4;
    *(__nv_bfloat162*)(H + off)     = __nv_bfloat162(h[0], h[1]);
    *(__nv_bfloat162*)(H + off + 2) = __nv_bfloat162(h[2], h[3]);
    *(__nv_bfloat162*)(Lo + off)     = __nv_bfloat162(l[0], l[1]);
    *(__nv_bfloat162*)(Lo + off + 2) = __nv_bfloat162(l[2], l[3]);
}

// ---------------- final RMSNorm (fp32 out) ----------------
__global__ void rmsnorm_kernel(const float* __restrict__ X, const float* __restrict__ scale,
                               float* __restrict__ Out) {
    int row = blockIdx.x;
    float4 v = ((const float4*)(X + (size_t)row*DD))[threadIdx.x];
    float ss = v.x*v.x + v.y*v.y + v.z*v.z + v.w*v.w;
    ss = blockReduceSum128(ss);
    float inv = rsqrtf(ss * (1.f/DD) + 1e-6f);
    float4 sc = ((const float4*)scale)[threadIdx.x];
    float4 o;
    o.x = v.x*inv*sc.x; o.y = v.y*inv*sc.y; o.z = v.z*inv*sc.z; o.w = v.w*inv*sc.w;
    ((float4*)(Out + (size_t)row*DD))[threadIdx.x] = o;
}

// ---------------- silu(g)*v -> split bf16 planes ----------------
__global__ void silu_split_kernel(const float* __restrict__ G, const float* __restrict__ V,
                                  __nv_bfloat16* __restrict__ H, __nv_bfloat16* __restrict__ Lo) {
    size_t i = (size_t)blockIdx.x*256 + threadIdx.x;
    float4 g = ((const float4*)G)[i];
    float4 v = ((const float4*)V)[i];
    float s0 = g.x/(1.f+expf(-g.x))*v.x;
    float s1 = g.y/(1.f+expf(-g.y))*v.y;
    float s2 = g.z/(1.f+expf(-g.z))*v.z;
    float s3 = g.w/(1.f+expf(-g.w))*v.w;
    __nv_bfloat16 h[4], l[4];
    bsplit(s0, h[0], l[0]); bsplit(s1, h[1], l[1]);
    bsplit(s2, h[2], l[2]); bsplit(s3, h[3], l[3]);
    size_t off = i*4;
    *(__nv_bfloat162*)(H + off)     = __nv_bfloat162(h[0], h[1]);
    *(__nv_bfloat162*)(H + off + 2) = __nv_bfloat162(h[2], h[3]);
    *(__nv_bfloat162*)(Lo + off)     = __nv_bfloat162(l[0], l[1]);
    *(__nv_bfloat162*)(Lo + off + 2) = __nv_bfloat162(l[2], l[3]);
}

// ---------------- RoPE ----------------
__global__ void rope_kernel(float* __restrict__ Q, float* __restrict__ K) {
    int row = blockIdx.x;
    int t = row & (TT-1);
    int h = threadIdx.x >> 5, j = threadIdx.x & 31;
    float inv = expf(-(float)(2*j) * (9.210340371976184f / 64.f));
    float ang = (float)t * inv;
    float sn, cs;
    sincosf(ang, &sn, &cs);
    size_t base = (size_t)row*DD + h*HD + 2*j;
    float q0 = Q[base], q1 = Q[base+1];
    Q[base]   = q0*cs - q1*sn;
    Q[base+1] = q0*sn + q1*cs;
    float k0 = K[base], k1 = K[base+1];
    K[base]   = k0*cs - k1*sn;
    K[base+1] = k0*sn + k1*cs;
}

// ---------------- causal flash attention -> split bf16 output ----------------
__global__ void flash_kernel(const float* __restrict__ Q, const float* __restrict__ K,
                             const float* __restrict__ V,
                             __nv_bfloat16* __restrict__ Oh, __nv_bfloat16* __restrict__ Ol) {
    __shared__ float qs[64][68];
    __shared__ float ks[32][68];
    __shared__ float vs[32][68];
    __shared__ float ps[64][36];
    int bh = blockIdx.y;
    int b = bh >> 3, h = bh & 7;
    int q0 = blockIdx.x * 64;
    int tid = threadIdx.x;
    int tx = tid & 15, ty = tid >> 4;
    size_t base = ((size_t)b*TT)*DD + h*HD;
    for (int i = tid; i < 64*16; i += 256) {
        int r = i >> 4, dv = (i & 15) * 4;
        float4 v = *(const float4*)(Q + base + (size_t)(q0 + r)*DD + dv);
        qs[r][dv] = v.x; qs[r][dv+1] = v.y; qs[r][dv+2] = v.z; qs[r][dv+3] = v.w;
    }
    float m[4], l[4], o[4][4];
    #pragma unroll
    for (int i = 0; i < 4; i++) {
        m[i] = -1e30f; l[i] = 0.f;
        #pragma unroll
        for (int j = 0; j < 4; j++) o[i][j] = 0.f;
    }
    int r0 = ty*4, c0 = tx*2, d0 = tx*4;
    int nkt = (q0 + 64) >> 5;
    const float scl = 0.125f;
    for (int kt = 0; kt < nkt; kt++) {
        int k0 = kt * 32;
        __syncthreads();
        for (int i = tid; i < 32*16; i += 256) {
            int r = i >> 4, dv = (i & 15)*4;
            float4 kv = *(const float4*)(K + base + (size_t)(k0 + r)*DD + dv);
            ks[r][dv] = kv.x; ks[r][dv+1] = kv.y; ks[r][dv+2] = kv.z; ks[r][dv+3] = kv.w;
            float4 vv = *(const float4*)(V + base + (size_t)(k0 + r)*DD + dv);
            vs[r][dv] = vv.x; vs[r][dv+1] = vv.y; vs[r][dv+2] = vv.z; vs[r][dv+3] = vv.w;
        }
        __syncthreads();
        float s[4][2] = {{0.f,0.f},{0.f,0.f},{0.f,0.f},{0.f,0.f}};
        #pragma unroll 8
        for (int dd = 0; dd < 64; dd++) {
            float k0v = ks[c0][dd], k1v = ks[c0+1][dd];
            #pragma unroll
            for (int i = 0; i < 4; i++) {
                float qv = qs[r0+i][dd];
                s[i][0] += qv*k0v;
                s[i][1] += qv*k1v;
            }
        }
        float corr[4];
        #pragma unroll
        for (int i = 0; i < 4; i++) {
            int qq = q0 + r0 + i;
            #pragma unroll
            for (int j = 0; j < 2; j++) {
                int kk = k0 + c0 + j;
                s[i][j] = (kk <= qq) ? s[i][j]*scl : -1e9f;
            }
            float mx = fmaxf(s[i][0], s[i][1]);
            #pragma unroll
            for (int off = 8; off; off >>= 1) mx = fmaxf(mx, __shfl_xor_sync(0xffffffffu, mx, off));
            float mn = fmaxf(m[i], mx);
            float c = __expf(m[i] - mn);
            m[i] = mn;
            float p0 = __expf(s[i][0] - mn), p1 = __expf(s[i][1] - mn);
            ps[r0+i][c0]   = p0;
            ps[r0+i][c0+1] = p1;
            float sum = p0 + p1;
            #pragma unroll
            for (int off = 8; off; off >>= 1) sum += __shfl_xor_sync(0xffffffffu, sum, off);
            l[i] = l[i]*c + sum;
            corr[i] = c;
        }
        #pragma unroll
        for (int i = 0; i < 4; i++)
            #pragma unroll
            for (int j = 0; j < 4; j++) o[i][j] *= corr[i];
        __syncthreads();
        #pragma unroll 4
        for (int c = 0; c < 32; c++) {
            float4 vv = *(const float4*)&vs[c][d0];
            #pragma unroll
            for (int i = 0; i < 4; i++) {
                float pv = ps[r0+i][c];
                o[i][0] += pv*vv.x; o[i][1] += pv*vv.y;
                o[i][2] += pv*vv.z; o[i][3] += pv*vv.w;
            }
        }
    }
    #pragma unroll
    for (int i = 0; i < 4; i++) {
        float inv = 1.f / l[i];
        float v0 = o[i][0]*inv, v1 = o[i][1]*inv, v2 = o[i][2]*inv, v3 = o[i][3]*inv;
        __nv_bfloat16 hh[4], ll[4];
        bsplit(v0, hh[0], ll[0]); bsplit(v1, hh[1], ll[1]);
        bsplit(v2, hh[2], ll[2]); bsplit(v3, hh[3], ll[3]);
        size_t off = base + (size_t)(q0 + r0 + i)*DD + d0;
        *(__nv_bfloat162*)(Oh + off)     = __nv_bfloat162(hh[0], hh[1]);
        *(__nv_bfloat162*)(Oh + off + 2) = __nv_bfloat162(hh[2], hh[3]);
        *(__nv_bfloat162*)(Ol + off)     = __nv_bfloat162(ll[0], ll[1]);
        *(__nv_bfloat162*)(Ol + off + 2) = __nv_bfloat162(ll[2], ll[3]);
    }
}

// ---------------- salience logits ----------------
__global__ void logits_kernel(const float* __restrict__ X, const float* __restrict__ sal_W,
                              const float* __restrict__ sal_b, const float* __restrict__ temp,
                              float* __restrict__ out) {
    int row = blockIdx.x;
    int e = threadIdx.x >> 5, lane = threadIdx.x & 31;
    const float* xr = X + (size_t)row*DD;
    float acc = 0.f;
    for (int d = lane; d < DD; d += 32)
        acc += xr[d] * sal_W[d*EH + e];
    acc = warpReduceSum(acc);
    if (lane == 0) {
        float tp = log1pf(expf(temp[e])) + 0.3f;
        out[(size_t)row*EH + e] = (acc + sal_b[e]) / tp;
    }
}

// ---------------- masked softmax pool ----------------
__global__ void pool_kernel(const int* __restrict__ tokens, const float* __restrict__ logits,
                            const float* __restrict__ X, const float* __restrict__ gate_W,
                            const float* __restrict__ gate_b,
                            float* __restrict__ wv_out, float* __restrict__ u_out) {
    int b = blockIdx.x >> 2, e = blockIdx.x & 3;
    int tid = threadIdx.x;
    __shared__ float ws[TT];
    float lg4[4]; int mv4[4];
    float lmax = -1e30f; float lvalid = 0.f;
    #pragma unroll
    for (int p = 0; p < 4; p++) {
        int t = tid + p*128;
        int mv = (tokens[b*TT + t] != 0);
        float lgv = logits[((size_t)b*TT + t)*EH + e];
        float sf = mv ? lgv : -1e9f;
        lg4[p] = sf; mv4[p] = mv;
        lmax = fmaxf(lmax, sf);
        lvalid += (float)mv;
    }
    float mx = blockReduceMax128(lmax);
    float lsum = 0.f;
    #pragma unroll
    for (int p = 0; p < 4; p++) {
        int t = tid + p*128;
        float ev = mv4[p] ? expf(lg4[p] - mx) : 0.f;
        ws[t] = ev;
        lsum += ev;
    }
    float ssum = blockReduceSum128(lsum);
    float nvalid = blockReduceSum128(lvalid);
    float wsc = 1.f / (ssum + 1e-6f);
    __syncthreads();
    float acc = 0.f;
    const float* xb = X + ((size_t)b*TT)*DD + e*EHD + tid;
    for (int t = 0; t < TT; t++)
        acc += ws[t] * xb[(size_t)t*DD];
    acc *= wsc;
    wv_out[b*DD + e*EHD + tid] = acc;
    float gsum = blockReduceSum128(acc * gate_W[tid]);
    if (tid == 0) {
        float gl = gsum + gate_b[0];
        float u = (nvalid > 0.f) ? 1.f/(1.f+expf(-gl)) : 0.f;
        u_out[b*EH + e] = u;
    }
}

// ---------------- fast/slow state update ----------------
__global__ void update_kernel(const float* __restrict__ wv, const float* __restrict__ u,
                              const float* __restrict__ sal_rms,
                              const float* __restrict__ fast, const float* __restrict__ slow,
                              float* __restrict__ out_fast, float* __restrict__ out_slow) {
    int b = blockIdx.x, tid = threadIdx.x;
    float4 v = ((const float4*)(wv + b*DD))[tid];
    float ss = blockReduceSum128(v.x*v.x + v.y*v.y + v.z*v.z + v.w*v.w);
    float inv = rsqrtf(ss * (1.f/DD) + 1e-6f);
    float4 sr = ((const float4*)sal_rms)[tid];
    int e = tid >> 5;
    float uu = u[b*EH + e];
    float4 f = ((const float4*)(fast + b*DD))[tid];
    float4 s = ((const float4*)(slow + b*DD))[tid];
    float4 wn;
    wn.x = v.x*inv*sr.x; wn.y = v.y*inv*sr.y; wn.z = v.z*inv*sr.z; wn.w = v.w*inv*sr.w;
    float4 nf, ns;
    nf.x = (1.f-uu)*f.x + uu*wn.x;  nf.y = (1.f-uu)*f.y + uu*wn.y;
    nf.z = (1.f-uu)*f.z + uu*wn.z;  nf.w = (1.f-uu)*f.w + uu*wn.w;
    float ud = 0.1f*uu;
    ns.x = (1.f-ud)*s.x + ud*wn.x;  ns.y = (1.f-ud)*s.y + ud*wn.y;
    ns.z = (1.f-ud)*s.z + ud*wn.z;  ns.w = (1.f-ud)*s.w + ud*wn.w;
    ((float4*)(out_fast + b*DD))[tid] = nf;
    ((float4*)(out_slow + b*DD))[tid] = ns;
}

// ---------------- launch ----------------
extern "C" void kernel_launch(void* const* d_in, const int* in_sizes, int n_in,
                              void* d_out, int out_size) {
    const int*   tokens = (const int*)  d_in[0];
    const int*   prev   = (const int*)  d_in[1];
    const float* fast   = (const float*)d_in[2];
    const float* slow   = (const float*)d_in[3];
    const float* embed  = (const float*)d_in[4];
    const float* ctx_W  = (const float*)d_in[5];
    const float* ctx_b  = (const float*)d_in[6];
    const float* etab   = (const float*)d_in[7];
    const float* egate  = (const float*)d_in[8];
    const float* ln1    = (const float*)d_in[9];
    const float* Wq     = (const float*)d_in[10];
    const float* bq     = (const float*)d_in[11];
    const float* Wk     = (const float*)d_in[12];
    const float* bk     = (const float*)d_in[13];
    const float* Wv     = (const float*)d_in[14];
    const float* bv     = (const float*)d_in[15];
    const float* Wo     = (const float*)d_in[16];
    const float* bo     = (const float*)d_in[17];
    const float* ln2    = (const float*)d_in[18];
    const float* W1     = (const float*)d_in[19];
    const float* W2     = (const float*)d_in[20];
    const float* ln_f   = (const float*)d_in[21];
    const float* sal_W  = (const float*)d_in[22];
    const float* sal_b  = (const float*)d_in[23];
    const float* temp   = (const float*)d_in[24];
    const float* gate_W = (const float*)d_in[25];
    const float* gate_b = (const float*)d_in[26];
    const float* sal_rms= (const float*)d_in[27];
    float* out = (float*)d_out;

    float *gx, *gq, *gk, *gv, *gffg, *gffv, *gctx, *glog, *gwv, *gu;
    __nv_bfloat16 *nxh, *nxl, *ath, *atl, *ffh, *ffl;
    __nv_bfloat16 *wqh, *wql, *wkh, *wkl, *wvh, *wvl, *woh, *wol, *w1h, *w1l, *w2h, *w2l;
    cudaGetSymbolAddress((void**)&gx,   g_x);
    cudaGetSymbolAddress((void**)&gq,   g_q);
    cudaGetSymbolAddress((void**)&gk,   g_k);
    cudaGetSymbolAddress((void**)&gv,   g_v);
    cudaGetSymbolAddress((void**)&gffg, g_ffg);
    cudaGetSymbolAddress((void**)&gffv, g_ffv);
    cudaGetSymbolAddress((void**)&gctx, g_ctx);
    cudaGetSymbolAddress((void**)&glog, g_logits);
    cudaGetSymbolAddress((void**)&gwv,  g_wv);
    cudaGetSymbolAddress((void**)&gu,   g_u);
    cudaGetSymbolAddress((void**)&nxh,  g_nxh);
    cudaGetSymbolAddress((void**)&nxl,  g_nxl);
    cudaGetSymbolAddress((void**)&ath,  g_ath);
    cudaGetSymbolAddress((void**)&atl,  g_atl);
    cudaGetSymbolAddress((void**)&ffh,  g_ffh);
    cudaGetSymbolAddress((void**)&ffl,  g_ffl);
    cudaGetSymbolAddress((void**)&wqh,  g_wqh);
    cudaGetSymbolAddress((void**)&wql,  g_wql);
    cudaGetSymbolAddress((void**)&wkh,  g_wkh);
    cudaGetSymbolAddress((void**)&wkl,  g_wkl);
    cudaGetSymbolAddress((void**)&wvh,  g_wvh);
    cudaGetSymbolAddress((void**)&wvl,  g_wvl);
    cudaGetSymbolAddress((void**)&woh,  g_woh);
    cudaGetSymbolAddress((void**)&wol,  g_wol);
    cudaGetSymbolAddress((void**)&w1h,  g_w1h);
    cudaGetSymbolAddress((void**)&w1l,  g_w1l);
    cudaGetSymbolAddress((void**)&w2h,  g_w2h);
    cudaGetSymbolAddress((void**)&w2l,  g_w2l);

    cudaFuncSetAttribute(hgemm<0>, cudaFuncAttributeMaxDynamicSharedMemorySize, HSMEM);
    cudaFuncSetAttribute(hgemm<1>, cudaFuncAttributeMaxDynamicSharedMemorySize, HSMEM);
    cudaFuncSetAttribute(hgemm<2>, cudaFuncAttributeMaxDynamicSharedMemorySize, HSMEM);
    cudaFuncSetAttribute(hgemm<3>, cudaFuncAttributeMaxDynamicSharedMemorySize, HSMEM);

    // weight transpose+split
    dim3 tb(32, 8);
    tsplit_kernel<<<dim3(DD/32, DD/32, LL), tb>>>(Wq, DD, (size_t)DD*DD, wqh, wql, (size_t)DD*DD, DD);
    tsplit_kernel<<<dim3(DD/32, DD/32, LL), tb>>>(Wk, DD, (size_t)DD*DD, wkh, wkl, (size_t)DD*DD, DD);
    tsplit_kernel<<<dim3(DD/32, DD/32, LL), tb>>>(Wv, DD, (size_t)DD*DD, wvh, wvl, (size_t)DD*DD, DD);
    tsplit_kernel<<<dim3(DD/32, DD/32, LL), tb>>>(Wo, DD, (size_t)DD*DD, woh, wol, (size_t)DD*DD, DD);
    // W1 [D, 2FF]: gate cols [0,FF) -> rows [0,FF); value cols [FF,2FF) -> rows [FF,2FF)
    tsplit_kernel<<<dim3(FF/32, DD/32, LL), tb>>>(W1,      2*FF, (size_t)DD*2*FF, w1h,                w1l,                (size_t)2*FF*DD, DD);
    tsplit_kernel<<<dim3(FF/32, DD/32, LL), tb>>>(W1 + FF, 2*FF, (size_t)DD*2*FF, w1h + (size_t)FF*DD, w1l + (size_t)FF*DD, (size_t)2*FF*DD, DD);
    tsplit_kernel<<<dim3(DD/32, FF/32, LL), tb>>>(W2, DD, (size_t)FF*DD, w2h, w2l, (size_t)DD*FF, FF);

    ctx_kernel<<<BB, 512>>>(fast, slow, ctx_W, ctx_b, gctx);
    embed_kernel<<<NTOK, 128>>>(tokens, prev, embed, gctx, etab, egate, gx);

    dim3 gD(NTOK/128, DD/128);     // 128 x 4
    dim3 gF(NTOK/128, FF/128);     // 128 x 16
    for (int l = 0; l < LL; l++) {
        size_t wo = (size_t)l*DD*DD;
        size_t w1o = (size_t)l*2*FF*DD;
        size_t w2o = (size_t)l*DD*FF;
        rmsnorm_split_kernel<<<NTOK, 128>>>(gx, ln1 + l*DD, nxh, nxl);
        hgemm<0><<<gD, 256, HSMEM>>>(nxh, nxl, wqh + wo, wql + wo, bq + l*DD, nullptr, gq, NTOK, DD, DD);
        hgemm<0><<<gD, 256, HSMEM>>>(nxh, nxl, wkh + wo, wkl + wo, bk + l*DD, nullptr, gk, NTOK, DD, DD);
        hgemm<0><<<gD, 256, HSMEM>>>(nxh, nxl, wvh + wo, wvl + wo, bv + l*DD, nullptr, gv, NTOK, DD, DD);
        rope_kernel<<<NTOK, 256>>>(gq, gk);
        flash_kernel<<<dim3(TT/64, BB*HH), 256>>>(gq, gk, gv, ath, atl);
        hgemm<1><<<gD, 256, HSMEM>>>(ath, atl, woh + wo, wol + wo, bo + l*DD, gx, gx, NTOK, DD, DD);
        rmsnorm_split_kernel<<<NTOK, 128>>>(gx, ln2 + l*DD, nxh, nxl);
        hgemm<3><<<gF, 256, HSMEM>>>(nxh, nxl, w1h + w1o, w1l + w1o, nullptr, nullptr, gffg, NTOK, FF, DD);
        hgemm<3><<<gF, 256, HSMEM>>>(nxh, nxl, w1h + w1o + (size_t)FF*DD, w1l + w1o + (size_t)FF*DD,
                                     nullptr, nullptr, gffv, NTOK, FF, DD);
        silu_split_kernel<<<(NTOK*(FF/4))/256, 256>>>(gffg, gffv, ffh, ffl);
        hgemm<2><<<gD, 256, HSMEM>>>(ffh, ffl, w2h + w2o, w2l + w2o, nullptr, gx, gx, NTOK, DD, FF);
    }
    rmsnorm_kernel<<<NTOK, 128>>>(gx, ln_f, out);
    logits_kernel<<<NTOK, 128>>>(out, sal_W, sal_b, temp, glog);
    pool_kernel<<<BB*EH, 128>>>(tokens, glog, out, gate_W, gate_b, gwv, gu);
    update_kernel<<<BB, 128>>>(gwv, gu, sal_rms, fast, slow,
                               out + (size_t)NTOK*DD,
                               out + (size_t)NTOK*DD + BB*DD);
}

// round 4
// speedup vs baseline: 1.7067x; 1.0296x over previous
#include <cuda_runtime.h>
#include <cuda_bf16.h>
#include <math.h>
#include <stdint.h>

// ---------------- problem constants ----------------
#define BB 32
#define TT 512
#define DD 512
#define LL 6
#define HH 8
#define HD 64
#define FF 2048      // 4*D
#define EH 4
#define EHD 128
#define MM 100000u
#define OVL 64
#define NTOK (BB*TT)   // 16384

// ---------------- scratch (device globals; no allocations allowed) ----------------
__device__ float g_x[NTOK*DD];
__device__ float g_qkv[(size_t)NTOK*3*DD];
__device__ float g_ffg[(size_t)NTOK*FF];
__device__ float g_ctx[BB*DD];
__device__ float g_logits[NTOK*EH];
__device__ float g_wv[BB*DD];
__device__ float g_u[BB*EH];
__device__ float g_bqkv[LL*3*DD];
// bf16 split planes (hi/lo)
__device__ __nv_bfloat16 g_nxh[NTOK*DD];
__device__ __nv_bfloat16 g_nxl[NTOK*DD];
__device__ __nv_bfloat16 g_ath[NTOK*DD];
__device__ __nv_bfloat16 g_atl[NTOK*DD];
__device__ __nv_bfloat16 g_ffh[(size_t)NTOK*FF];
__device__ __nv_bfloat16 g_ffl[(size_t)NTOK*FF];
// transposed + split weights: [N][K] bf16 planes
__device__ __nv_bfloat16 g_wqkvoh[(size_t)LL*4*DD*DD];   // per layer: rows [0,512)=Wq^T, [512,1024)=Wk^T, [1024,1536)=Wv^T, [1536,2048)=Wo^T
__device__ __nv_bfloat16 g_wqkvol[(size_t)LL*4*DD*DD];
__device__ __nv_bfloat16 g_w1h[(size_t)LL*2*FF*DD];
__device__ __nv_bfloat16 g_w1l[(size_t)LL*2*FF*DD];
__device__ __nv_bfloat16 g_w2h[(size_t)LL*DD*FF];
__device__ __nv_bfloat16 g_w2l[(size_t)LL*DD*FF];

// ---------------- PTX helpers ----------------
__device__ __forceinline__ uint32_t smem_to_u32(const void* p) {
    uint32_t a;
    asm("{ .reg .u64 t; cvta.to.shared.u64 t, %1; cvt.u32.u64 %0, t; }" : "=r"(a) : "l"(p));
    return a;
}
__device__ __forceinline__ void cp16(uint32_t dst, const void* src) {
    asm volatile("cp.async.cg.shared.global [%0], [%1], 16;" :: "r"(dst), "l"(src));
}
#define CP_COMMIT() asm volatile("cp.async.commit_group;" ::: "memory")
#define CP_WAIT1()  asm volatile("cp.async.wait_group 1;" ::: "memory")

#define LDSM4(r, addr) \
    asm volatile("ldmatrix.sync.aligned.m8n8.x4.shared.b16 {%0,%1,%2,%3}, [%4];" \
        : "=r"((r)[0]), "=r"((r)[1]), "=r"((r)[2]), "=r"((r)[3]) : "r"(addr))

#define HMMA(c, a, b0, b1) \
    asm volatile("mma.sync.aligned.m16n8k16.row.col.f32.bf16.bf16.f32 " \
        "{%0,%1,%2,%3}, {%4,%5,%6,%7}, {%8,%9}, {%0,%1,%2,%3};" \
        : "+f"((c)[0]), "+f"((c)[1]), "+f"((c)[2]), "+f"((c)[3]) \
        : "r"((a)[0]), "r"((a)[1]), "r"((a)[2]), "r"((a)[3]), "r"(b0), "r"(b1))

__device__ __forceinline__ void bsplit(float x, __nv_bfloat16& h, __nv_bfloat16& l) {
    h = __float2bfloat16(x);
    l = __float2bfloat16(x - __bfloat162float(h));
}

// ---------------- reduction helpers ----------------
__device__ __forceinline__ float warpReduceSum(float v) {
    #pragma unroll
    for (int o = 16; o; o >>= 1) v += __shfl_xor_sync(0xffffffffu, v, o);
    return v;
}
__device__ __forceinline__ float warpReduceMax(float v) {
    #pragma unroll
    for (int o = 16; o; o >>= 1) v = fmaxf(v, __shfl_xor_sync(0xffffffffu, v, o));
    return v;
}
__device__ __forceinline__ float blockReduceSum128(float v) {
    __shared__ float sm[4];
    __syncthreads();
    v = warpReduceSum(v);
    if ((threadIdx.x & 31) == 0) sm[threadIdx.x >> 5] = v;
    __syncthreads();
    return sm[0] + sm[1] + sm[2] + sm[3];
}
__device__ __forceinline__ float blockReduceMax128(float v) {
    __shared__ float sm[4];
    __syncthreads();
    v = warpReduceMax(v);
    if ((threadIdx.x & 31) == 0) sm[threadIdx.x >> 5] = v;
    __syncthreads();
    return fmaxf(fmaxf(sm[0], sm[1]), fmaxf(sm[2], sm[3]));
}

// ---------------- bias stack: [L][1536] = concat(bq, bk, bv) ----------------
__global__ void bstack_kernel(const float* __restrict__ bq, const float* __restrict__ bk,
                              const float* __restrict__ bv, float* __restrict__ out) {
    int l = blockIdx.x, i = threadIdx.x;   // 512 threads
    out[l*1536 + i]        = bq[l*DD + i];
    out[l*1536 + 512 + i]  = bk[l*DD + i];
    out[l*1536 + 1024 + i] = bv[l*DD + i];
}

// ---------------- weight transpose+split (generic): dst[n][k] from src[k][n] ----------------
__global__ void tsplit_kernel(const float* __restrict__ src, int ldsrc, size_t srcStride,
                              __nv_bfloat16* __restrict__ hi, __nv_bfloat16* __restrict__ lo,
                              size_t dstStride, int K) {
    __shared__ float t[32][33];
    int l = blockIdx.z;
    const float* S = src + (size_t)l*srcStride;
    __nv_bfloat16* Hd = hi + (size_t)l*dstStride;
    __nv_bfloat16* Ld = lo + (size_t)l*dstStride;
    int n0 = blockIdx.x*32, k0 = blockIdx.y*32;
    int x = threadIdx.x, y = threadIdx.y;   // 32 x 8
    #pragma unroll
    for (int i = 0; i < 32; i += 8) t[y+i][x] = S[(size_t)(k0+y+i)*ldsrc + n0+x];
    __syncthreads();
    #pragma unroll
    for (int i = 0; i < 32; i += 8) {
        float v = t[x][y+i];
        __nv_bfloat16 h, lw;
        bsplit(v, h, lw);
        size_t off = (size_t)(n0+y+i)*K + k0+x;
        Hd[off] = h; Ld[off] = lw;
    }
}

// ---------------- 4-source transpose+split (Wq/Wk/Wv/Wo stacked) ----------------
__global__ void tsplit4_kernel(const float* __restrict__ s0, const float* __restrict__ s1,
                               const float* __restrict__ s2, const float* __restrict__ s3,
                               __nv_bfloat16* __restrict__ hi, __nv_bfloat16* __restrict__ lo) {
    __shared__ float t[32][33];
    int z = blockIdx.z;                 // z = l*4 + sel
    int l = z >> 2, sel = z & 3;
    const float* S = (sel == 0 ? s0 : sel == 1 ? s1 : sel == 2 ? s2 : s3) + (size_t)l*DD*DD;
    __nv_bfloat16* Hd = hi + (size_t)z*DD*DD;
    __nv_bfloat16* Ld = lo + (size_t)z*DD*DD;
    int n0 = blockIdx.x*32, k0 = blockIdx.y*32;
    int x = threadIdx.x, y = threadIdx.y;
    #pragma unroll
    for (int i = 0; i < 32; i += 8) t[y+i][x] = S[(size_t)(k0+y+i)*DD + n0+x];
    __syncthreads();
    #pragma unroll
    for (int i = 0; i < 32; i += 8) {
        float v = t[x][y+i];
        __nv_bfloat16 h, lw;
        bsplit(v, h, lw);
        size_t off = (size_t)(n0+y+i)*DD + k0+x;
        Hd[off] = h; Ld[off] = lw;
    }
}

// ---------------- W1 transpose+split (gate/value halves via z) ----------------
__global__ void tsplitW1_kernel(const float* __restrict__ W1,
                                __nv_bfloat16* __restrict__ hi, __nv_bfloat16* __restrict__ lo) {
    __shared__ float t[32][33];
    int z = blockIdx.z;                  // z = l*2 + half
    int l = z >> 1, half = z & 1;
    const float* S = W1 + (size_t)l*DD*2*FF + (size_t)half*FF;
    size_t doff = (size_t)l*2*FF*DD + (size_t)half*FF*DD;
    __nv_bfloat16* Hd = hi + doff;
    __nv_bfloat16* Ld = lo + doff;
    int n0 = blockIdx.x*32, k0 = blockIdx.y*32;
    int x = threadIdx.x, y = threadIdx.y;
    #pragma unroll
    for (int i = 0; i < 32; i += 8) t[y+i][x] = S[(size_t)(k0+y+i)*(2*FF) + n0+x];
    __syncthreads();
    #pragma unroll
    for (int i = 0; i < 32; i += 8) {
        float v = t[x][y+i];
        __nv_bfloat16 h, lw;
        bsplit(v, h, lw);
        size_t off = (size_t)(n0+y+i)*DD + k0+x;
        Hd[off] = h; Ld[off] = lw;
    }
}

// ---------------- split-bf16 HMMA GEMM ----------------
// C[M,N] = A[M,K] @ B^T.  MODE 0: +bias ; 1: +bias +res ; 2: plain (gate)
//                         3: OutH/L = split(silu(Gg)*acc) ; 4: +res
#define TILE_B 10240
#define STAGE_B 40960
#define HSMEM (2*STAGE_B)

__device__ __forceinline__ void load_stage(uint32_t sb,
        const __nv_bfloat16* Ah, const __nv_bfloat16* Al,
        const __nv_bfloat16* Bh, const __nv_bfloat16* Bl,
        int K, int kof, int tid) {
    #pragma unroll
    for (int i = 0; i < 2; i++) {
        int e = tid + i*256;              // 0..511
        int row = e >> 2, seg = e & 3;
        uint32_t off = (uint32_t)(row*80 + seg*16);
        size_t g = (size_t)row*K + kof + seg*8;
        cp16(sb + off,            Ah + g);
        cp16(sb + TILE_B + off,   Al + g);
        cp16(sb + 2*TILE_B + off, Bh + g);
        cp16(sb + 3*TILE_B + off, Bl + g);
    }
}

template<int MODE>
__global__ void __launch_bounds__(256)
hgemm(const __nv_bfloat16* __restrict__ Ah, const __nv_bfloat16* __restrict__ Al,
      const __nv_bfloat16* __restrict__ Bh, const __nv_bfloat16* __restrict__ Bl,
      const float* __restrict__ bias, const float* __restrict__ Res,
      const float* __restrict__ Gg,
      float* __restrict__ C, __nv_bfloat16* __restrict__ OutH, __nv_bfloat16* __restrict__ OutL,
      int M, int N, int K) {
    extern __shared__ char dsm[];
    uint32_t sb = smem_to_u32(dsm);
    int tid = threadIdx.x, lane = tid & 31, wid = tid >> 5;
    int m0 = blockIdx.x * 128, n0 = blockIdx.y * 128;
    int wm = (wid & 1) * 64, wn = (wid >> 1) * 32;
    const __nv_bfloat16* Abh = Ah + (size_t)m0*K;
    const __nv_bfloat16* Abl = Al + (size_t)m0*K;
    const __nv_bfloat16* Bbh = Bh + (size_t)n0*K;
    const __nv_bfloat16* Bbl = Bl + (size_t)n0*K;
    int NC = K >> 5;

    load_stage(sb,           Abh, Abl, Bbh, Bbl, K, 0,  tid); CP_COMMIT();
    load_stage(sb + STAGE_B, Abh, Abl, Bbh, Bbl, K, 32, tid); CP_COMMIT();

    float acc[4][4][4];
    #pragma unroll
    for (int a = 0; a < 4; a++)
        #pragma unroll
        for (int b = 0; b < 4; b++)
            #pragma unroll
            for (int c = 0; c < 4; c++) acc[a][b][c] = 0.f;

    const int a_row = lane & 15;
    const int a_k   = (lane >> 4) * 8;
    const int b_row = (lane & 7) + ((lane >> 4) << 3);
    const int b_k   = ((lane >> 3) & 1) * 8;

    for (int i = 0; i < NC; i++) {
        CP_WAIT1();
        __syncthreads();
        uint32_t st = sb + (uint32_t)(i & 1) * STAGE_B;
        #pragma unroll
        for (int kk = 0; kk < 32; kk += 16) {
            uint32_t ah[4][4], al[4][4], bh2[2][4], bl2[2][4];
            #pragma unroll
            for (int mt = 0; mt < 4; mt++) {
                uint32_t ad = st + (uint32_t)((wm + mt*16 + a_row)*80 + (kk + a_k)*2);
                LDSM4(ah[mt], ad);
                LDSM4(al[mt], ad + TILE_B);
            }
            #pragma unroll
            for (int np = 0; np < 2; np++) {
                uint32_t bd = st + 2*TILE_B + (uint32_t)((wn + np*16 + b_row)*80 + (kk + b_k)*2);
                LDSM4(bh2[np], bd);
                LDSM4(bl2[np], bd + TILE_B);
            }
            #pragma unroll
            for (int mt = 0; mt < 4; mt++)
                #pragma unroll
                for (int nt = 0; nt < 4; nt++) {
                    uint32_t b0h = bh2[nt>>1][(nt&1)*2],  b1h = bh2[nt>>1][(nt&1)*2+1];
                    uint32_t b0l = bl2[nt>>1][(nt&1)*2],  b1l = bl2[nt>>1][(nt&1)*2+1];
                    HMMA(acc[mt][nt], ah[mt], b0h, b1h);
                    HMMA(acc[mt][nt], ah[mt], b0l, b1l);
                    HMMA(acc[mt][nt], al[mt], b0h, b1h);
                }
        }
        __syncthreads();
        if (i + 2 < NC)
            load_stage(st, Abh, Abl, Bbh, Bbl, K, (i+2)*32, tid);
        CP_COMMIT();
    }

    int gid = lane >> 2, ctg = lane & 3;
    #pragma unroll
    for (int mt = 0; mt < 4; mt++)
        #pragma unroll
        for (int nt = 0; nt < 4; nt++) {
            int r0 = m0 + wm + mt*16 + gid;
            int cc = n0 + wn + nt*8 + ctg*2;
            float2 v0 = make_float2(acc[mt][nt][0], acc[mt][nt][1]);
            float2 v1 = make_float2(acc[mt][nt][2], acc[mt][nt][3]);
            if (MODE == 0 || MODE == 1) {
                float2 bb = *(const float2*)(bias + cc);
                v0.x += bb.x; v0.y += bb.y; v1.x += bb.x; v1.y += bb.y;
            }
            if (MODE == 1 || MODE == 4) {
                float2 ra = *(const float2*)(Res + (size_t)r0*N + cc);
                float2 rb = *(const float2*)(Res + (size_t)(r0+8)*N + cc);
                v0.x += ra.x; v0.y += ra.y; v1.x += rb.x; v1.y += rb.y;
            }
            if (MODE == 3) {
                float2 ga = *(const float2*)(Gg + (size_t)r0*N + cc);
                float2 gb = *(const float2*)(Gg + (size_t)(r0+8)*N + cc);
                float s0 = ga.x/(1.f+expf(-ga.x))*v0.x;
                float s1 = ga.y/(1.f+expf(-ga.y))*v0.y;
                float s2 = gb.x/(1.f+expf(-gb.x))*v1.x;
                float s3 = gb.y/(1.f+expf(-gb.y))*v1.y;
                __nv_bfloat16 h0,l0,h1,l1,h2,l2,h3,l3;
                bsplit(s0,h0,l0); bsplit(s1,h1,l1); bsplit(s2,h2,l2); bsplit(s3,h3,l3);
                *(__nv_bfloat162*)(OutH + (size_t)r0*N + cc)     = __nv_bfloat162(h0, h1);
                *(__nv_bfloat162*)(OutL + (size_t)r0*N + cc)     = __nv_bfloat162(l0, l1);
                *(__nv_bfloat162*)(OutH + (size_t)(r0+8)*N + cc) = __nv_bfloat162(h2, h3);
                *(__nv_bfloat162*)(OutL + (size_t)(r0+8)*N + cc) = __nv_bfloat162(l2, l3);
            } else {
                *(float2*)(C + (size_t)r0*N + cc) = v0;
                *(float2*)(C + (size_t)(r0+8)*N + cc) = v1;
            }
        }
}

// ---------------- context projection ----------------
__global__ void ctx_kernel(const float* __restrict__ fast, const float* __restrict__ slow,
                           const float* __restrict__ W, const float* __restrict__ bias,
                           float* __restrict__ out) {
    int b = blockIdx.x, d = threadIdx.x;
    float acc = bias[d];
    const float* fb = fast + b*DD;
    const float* sb = slow + b*DD;
    for (int k = 0; k < DD; k++) acc += fb[k] * W[(size_t)k*DD + d];
    for (int k = 0; k < DD; k++) acc += sb[k] * W[(size_t)(k+DD)*DD + d];
    out[b*DD + d] = acc;
}

// ---------------- embedding + context + engram retrieval ----------------
__global__ void embed_kernel(const int* __restrict__ tokens, const int* __restrict__ prev,
                             const float* __restrict__ embed, const float* __restrict__ ctxadd,
                             const float* __restrict__ etab, const float* __restrict__ egate,
                             float* __restrict__ X) {
    int row = blockIdx.x;
    int b = row >> 9, t = row & 511;
    __shared__ unsigned int sidx[EH];
    int tid = threadIdx.x;
    if (tid < EH) {
        unsigned int xseed = 131u + (unsigned)tid * 1009u;
        unsigned int hs = 0u;
        #pragma unroll
        for (int i = 0; i < 4; i++) {
            unsigned int p = xseed; xseed = xseed * 31u + 1u;
            int pos = t - i;
            unsigned int tok = (pos >= 0) ? (unsigned)tokens[b*TT + pos]
                                          : (unsigned)prev[b*OVL + OVL + pos];
            hs += tok * p;
        }
        sidx[tid] = hs % MM;
    }
    __syncthreads();
    int d0 = tid * 4;
    int eh = tid >> 5;
    int jj = d0 & 127;
    int tok = tokens[b*TT + t];
    float4 ev = *(const float4*)(embed + (size_t)tok*DD + d0);
    float4 cv = *(const float4*)(ctxadd + b*DD + d0);
    float4 rv = *(const float4*)(etab + ((size_t)sidx[eh]*EH + eh)*EHD + jj);
    float4 gv = *(const float4*)(egate + eh*EHD + jj);
    float4 o;
    o.x = ev.x + cv.x + rv.x * (1.f/(1.f+expf(-gv.x)));
    o.y = ev.y + cv.y + rv.y * (1.f/(1.f+expf(-gv.y)));
    o.z = ev.z + cv.z + rv.z * (1.f/(1.f+expf(-gv.z)));
    o.w = ev.w + cv.w + rv.w * (1.f/(1.f+expf(-gv.w)));
    *(float4*)(X + (size_t)row*DD + d0) = o;
}

// ---------------- RMSNorm -> split bf16 planes ----------------
__global__ void rmsnorm_split_kernel(const float* __restrict__ X, const float* __restrict__ scale,
                                     __nv_bfloat16* __restrict__ H, __nv_bfloat16* __restrict__ Lo) {
    int row = blockIdx.x;
    float4 v = ((const float4*)(X + (size_t)row*DD))[threadIdx.x];
    float ss = v.x*v.x + v.y*v.y + v.z*v.z + v.w*v.w;
    ss = blockReduceSum128(ss);
    float inv = rsqrtf(ss * (1.f/DD) + 1e-6f);
    float4 sc = ((const float4*)scale)[threadIdx.x];
    float o0 = v.x*inv*sc.x, o1 = v.y*inv*sc.y, o2 = v.z*inv*sc.z, o3 = v.w*inv*sc.w;
    __nv_bfloat16 h[4], l[4];
    bsplit(o0, h[0], l[0]); bsplit(o1, h[1], l[1]);
    bsplit(o2, h[2], l[2]); bsplit(o3, h[3], l[3]);
    size_t off = (size_t)row*DD + threadIdx.x*4;
    *(__nv_bfloat162*)(H + off)     = __nv_bfloat162(h[0], h[1]);
    *(__nv_bfloat162*)(H + off + 2) = __nv_bfloat162(h[2], h[3]);
    *(__nv_bfloat162*)(Lo + off)     = __nv_bfloat162(l[0], l[1]);
    *(__nv_bfloat162*)(Lo + off + 2) = __nv_bfloat162(l[2], l[3]);
}

// ---------------- final RMSNorm (fp32 out) ----------------
__global__ void rmsnorm_kernel(const float* __restrict__ X, const float* __restrict__ scale,
                               float* __restrict__ Out) {
    int row = blockIdx.x;
    float4 v = ((const float4*)(X + (size_t)row*DD))[threadIdx.x];
    float ss = v.x*v.x + v.y*v.y + v.z*v.z + v.w*v.w;
    ss = blockReduceSum128(ss);
    float inv = rsqrtf(ss * (1.f/DD) + 1e-6f);
    float4 sc = ((const float4*)scale)[threadIdx.x];
    float4 o;
    o.x = v.x*inv*sc.x; o.y = v.y*inv*sc.y; o.z = v.z*inv*sc.z; o.w = v.w*inv*sc.w;
    ((float4*)(Out + (size_t)row*DD))[threadIdx.x] = o;
}

// ---------------- RoPE on fused qkv buffer (q: cols [0,512), k: [512,1024)) ----------------
__global__ void rope_kernel(float* __restrict__ QKV) {
    int row = blockIdx.x;
    int t = row & (TT-1);
    int h = threadIdx.x >> 5, j = threadIdx.x & 31;   // 256 threads
    float inv = expf(-(float)(2*j) * (9.210340371976184f / 64.f));
    float ang = (float)t * inv;
    float sn, cs;
    sincosf(ang, &sn, &cs);
    size_t base = (size_t)row*1536 + h*HD + 2*j;
    float q0 = QKV[base], q1 = QKV[base+1];
    QKV[base]   = q0*cs - q1*sn;
    QKV[base+1] = q0*sn + q1*cs;
    float k0 = QKV[base+512], k1 = QKV[base+513];
    QKV[base+512] = k0*cs - k1*sn;
    QKV[base+513] = k0*sn + k1*cs;
}

// ---------------- causal flash attention: BQ=64, BK=64, HD=64, 256 threads ----------------
__global__ void __launch_bounds__(256) flash_kernel(const float* __restrict__ QKV,
        __nv_bfloat16* __restrict__ Oh, __nv_bfloat16* __restrict__ Ol) {
    extern __shared__ float fsm[];
    float (*qs)[68] = (float(*)[68])fsm;
    float (*ks)[68] = (float(*)[68])(fsm + 64*68);
    float (*vs)[68] = (float(*)[68])(fsm + 2*64*68);
    float (*ps)[68] = (float(*)[68])(fsm + 3*64*68);
    int bh = blockIdx.y;
    int b = bh >> 3, h = bh & 7;
    int q0 = blockIdx.x * 64;
    int tid = threadIdx.x;
    int tx = tid & 15, ty = tid >> 4;
    size_t base = ((size_t)b*TT)*1536 + h*HD;
    for (int i = tid; i < 64*16; i += 256) {
        int r = i >> 4, dv = (i & 15) * 4;
        *(float4*)&qs[r][dv] = *(const float4*)(QKV + base + (size_t)(q0 + r)*1536 + dv);
    }
    float m[4], l[4], o[4][4];
    #pragma unroll
    for (int i = 0; i < 4; i++) {
        m[i] = -1e30f; l[i] = 0.f;
        #pragma unroll
        for (int j = 0; j < 4; j++) o[i][j] = 0.f;
    }
    int r0 = ty*4, d0 = tx*4;
    int nkt = (q0 >> 6) + 1;
    const float scl = 0.125f;
    for (int kt = 0; kt < nkt; kt++) {
        int k0 = kt * 64;
        __syncthreads();
        for (int i = tid; i < 64*16; i += 256) {
            int r = i >> 4, dv = (i & 15)*4;
            size_t g = base + (size_t)(k0 + r)*1536 + dv;
            *(float4*)&ks[r][dv] = *(const float4*)(QKV + g + 512);
            *(float4*)&vs[r][dv] = *(const float4*)(QKV + g + 1024);
        }
        __syncthreads();
        float s[4][4];
        #pragma unroll
        for (int i = 0; i < 4; i++)
            #pragma unroll
            for (int j = 0; j < 4; j++) s[i][j] = 0.f;
        #pragma unroll 8
        for (int dd = 0; dd < 64; dd += 2) {
            float2 k2[4], q2[4];
            #pragma unroll
            for (int j = 0; j < 4; j++) k2[j] = *(const float2*)&ks[tx + 16*j][dd];
            #pragma unroll
            for (int i = 0; i < 4; i++) q2[i] = *(const float2*)&qs[r0 + i][dd];
            #pragma unroll
            for (int i = 0; i < 4; i++)
                #pragma unroll
                for (int j = 0; j < 4; j++)
                    s[i][j] += q2[i].x*k2[j].x + q2[i].y*k2[j].y;
        }
        bool diag = (kt == nkt - 1);
        float corr[4];
        #pragma unroll
        for (int i = 0; i < 4; i++) {
            int qq = q0 + r0 + i;
            #pragma unroll
            for (int j = 0; j < 4; j++) {
                int kk = k0 + tx + 16*j;
                s[i][j] = (!diag || kk <= qq) ? s[i][j]*scl : -1e9f;
            }
            float mx = fmaxf(fmaxf(s[i][0], s[i][1]), fmaxf(s[i][2], s[i][3]));
            #pragma unroll
            for (int off = 8; off; off >>= 1) mx = fmaxf(mx, __shfl_xor_sync(0xffffffffu, mx, off));
            float mn = fmaxf(m[i], mx);
            float c = __expf(m[i] - mn);
            m[i] = mn;
            float sum = 0.f;
            #pragma unroll
            for (int j = 0; j < 4; j++) {
                float p = __expf(s[i][j] - mn);
                ps[r0 + i][tx + 16*j] = p;
                sum += p;
            }
            #pragma unroll
            for (int off = 8; off; off >>= 1) sum += __shfl_xor_sync(0xffffffffu, sum, off);
            l[i] = l[i]*c + sum;
            corr[i] = c;
        }
        #pragma unroll
        for (int i = 0; i < 4; i++)
            #pragma unroll
            for (int j = 0; j < 4; j++) o[i][j] *= corr[i];
        __syncthreads();
        #pragma unroll 4
        for (int c = 0; c < 64; c++) {
            float4 v4 = *(const float4*)&vs[c][d0];
            #pragma unroll
            for (int i = 0; i < 4; i++) {
                float pv = ps[r0 + i][c];
                o[i][0] += pv*v4.x; o[i][1] += pv*v4.y;
                o[i][2] += pv*v4.z; o[i][3] += pv*v4.w;
            }
        }
    }
    #pragma unroll
    for (int i = 0; i < 4; i++) {
        float inv = 1.f / l[i];
        float v0 = o[i][0]*inv, v1 = o[i][1]*inv, v2 = o[i][2]*inv, v3 = o[i][3]*inv;
        __nv_bfloat16 hh[4], ll[4];
        bsplit(v0, hh[0], ll[0]); bsplit(v1, hh[1], ll[1]);
        bsplit(v2, hh[2], ll[2]); bsplit(v3, hh[3], ll[3]);
        size_t off = ((size_t)(b*TT + q0 + r0 + i))*DD + h*HD + d0;
        *(__nv_bfloat162*)(Oh + off)     = __nv_bfloat162(hh[0], hh[1]);
        *(__nv_bfloat162*)(Oh + off + 2) = __nv_bfloat162(hh[2], hh[3]);
        *(__nv_bfloat162*)(Ol + off)     = __nv_bfloat162(ll[0], ll[1]);
        *(__nv_bfloat162*)(Ol + off + 2) = __nv_bfloat162(ll[2], ll[3]);
    }
}

// ---------------- salience logits ----------------
__global__ void logits_kernel(const float* __restrict__ X, const float* __restrict__ sal_W,
                              const float* __restrict__ sal_b, const float* __restrict__ temp,
                              float* __restrict__ out) {
    int row = blockIdx.x;
    int e = threadIdx.x >> 5, lane = threadIdx.x & 31;
    const float* xr = X + (size_t)row*DD;
    float acc = 0.f;
    for (int d = lane; d < DD; d += 32)
        acc += xr[d] * sal_W[d*EH + e];
    acc = warpReduceSum(acc);
    if (lane == 0) {
        float tp = log1pf(expf(temp[e])) + 0.3f;
        out[(size_t)row*EH + e] = (acc + sal_b[e]) / tp;
    }
}

// ---------------- masked softmax pool ----------------
__global__ void pool_kernel(const int* __restrict__ tokens, const float* __restrict__ logits,
                            const float* __restrict__ X, const float* __restrict__ gate_W,
                            const float* __restrict__ gate_b,
                            float* __restrict__ wv_out, float* __restrict__ u_out) {
    int b = blockIdx.x >> 2, e = blockIdx.x & 3;
    int tid = threadIdx.x;
    __shared__ float ws[TT];
    float lg4[4]; int mv4[4];
    float lmax = -1e30f; float lvalid = 0.f;
    #pragma unroll
    for (int p = 0; p < 4; p++) {
        int t = tid + p*128;
        int mv = (tokens[b*TT + t] != 0);
        float lgv = logits[((size_t)b*TT + t)*EH + e];
        float sf = mv ? lgv : -1e9f;
        lg4[p] = sf; mv4[p] = mv;
        lmax = fmaxf(lmax, sf);
        lvalid += (float)mv;
    }
    float mx = blockReduceMax128(lmax);
    float lsum = 0.f;
    #pragma unroll
    for (int p = 0; p < 4; p++) {
        int t = tid + p*128;
        float ev = mv4[p] ? expf(lg4[p] - mx) : 0.f;
        ws[t] = ev;
        lsum += ev;
    }
    float ssum = blockReduceSum128(lsum);
    float nvalid = blockReduceSum128(lvalid);
    float wsc = 1.f / (ssum + 1e-6f);
    __syncthreads();
    float acc = 0.f;
    const float* xb = X + ((size_t)b*TT)*DD + e*EHD + tid;
    for (int t = 0; t < TT; t++)
        acc += ws[t] * xb[(size_t)t*DD];
    acc *= wsc;
    wv_out[b*DD + e*EHD + tid] = acc;
    float gsum = blockReduceSum128(acc * gate_W[tid]);
    if (tid == 0) {
        float gl = gsum + gate_b[0];
        float u = (nvalid > 0.f) ? 1.f/(1.f+expf(-gl)) : 0.f;
        u_out[b*EH + e] = u;
    }
}

// ---------------- fast/slow state update ----------------
__global__ void update_kernel(const float* __restrict__ wv, const float* __restrict__ u,
                              const float* __restrict__ sal_rms,
                              const float* __restrict__ fast, const float* __restrict__ slow,
                              float* __restrict__ out_fast, float* __restrict__ out_slow) {
    int b = blockIdx.x, tid = threadIdx.x;
    float4 v = ((const float4*)(wv + b*DD))[tid];
    float ss = blockReduceSum128(v.x*v.x + v.y*v.y + v.z*v.z + v.w*v.w);
    float inv = rsqrtf(ss * (1.f/DD) + 1e-6f);
    float4 sr = ((const float4*)sal_rms)[tid];
    int e = tid >> 5;
    float uu = u[b*EH + e];
    float4 f = ((const float4*)(fast + b*DD))[tid];
    float4 s = ((const float4*)(slow + b*DD))[tid];
    float4 wn;
    wn.x = v.x*inv*sr.x; wn.y = v.y*inv*sr.y; wn.z = v.z*inv*sr.z; wn.w = v.w*inv*sr.w;
    float4 nf, ns;
    nf.x = (1.f-uu)*f.x + uu*wn.x;  nf.y = (1.f-uu)*f.y + uu*wn.y;
    nf.z = (1.f-uu)*f.z + uu*wn.z;  nf.w = (1.f-uu)*f.w + uu*wn.w;
    float ud = 0.1f*uu;
    ns.x = (1.f-ud)*s.x + ud*wn.x;  ns.y = (1.f-ud)*s.y + ud*wn.y;
    ns.z = (1.f-ud)*s.z + ud*wn.z;  ns.w = (1.f-ud)*s.w + ud*wn.w;
    ((float4*)(out_fast + b*DD))[tid] = nf;
    ((float4*)(out_slow + b*DD))[tid] = ns;
}

// ---------------- launch ----------------
extern "C" void kernel_launch(void* const* d_in, const int* in_sizes, int n_in,
                              void* d_out, int out_size) {
    const int*   tokens = (const int*)  d_in[0];
    const int*   prev   = (const int*)  d_in[1];
    const float* fast   = (const float*)d_in[2];
    const float* slow   = (const float*)d_in[3];
    const float* embed  = (const float*)d_in[4];
    const float* ctx_W  = (const float*)d_in[5];
    const float* ctx_b  = (const float*)d_in[6];
    const float* etab   = (const float*)d_in[7];
    const float* egate  = (const float*)d_in[8];
    const float* ln1    = (const float*)d_in[9];
    const float* Wq     = (const float*)d_in[10];
    const float* bq     = (const float*)d_in[11];
    const float* Wk     = (const float*)d_in[12];
    const float* bk     = (const float*)d_in[13];
    const float* Wv     = (const float*)d_in[14];
    const float* bv     = (const float*)d_in[15];
    const float* Wo     = (const float*)d_in[16];
    const float* bo     = (const float*)d_in[17];
    const float* ln2    = (const float*)d_in[18];
    const float* W1     = (const float*)d_in[19];
    const float* W2     = (const float*)d_in[20];
    const float* ln_f   = (const float*)d_in[21];
    const float* sal_W  = (const float*)d_in[22];
    const float* sal_b  = (const float*)d_in[23];
    const float* temp   = (const float*)d_in[24];
    const float* gate_W = (const float*)d_in[25];
    const float* gate_b = (const float*)d_in[26];
    const float* sal_rms= (const float*)d_in[27];
    float* out = (float*)d_out;

    float *gx, *gqkv, *gffg, *gctx, *glog, *gwv, *gu, *gbqkv;
    __nv_bfloat16 *nxh, *nxl, *ath, *atl, *ffh, *ffl;
    __nv_bfloat16 *wAh, *wAl, *w1h, *w1l, *w2h, *w2l;
    cudaGetSymbolAddress((void**)&gx,   g_x);
    cudaGetSymbolAddress((void**)&gqkv, g_qkv);
    cudaGetSymbolAddress((void**)&gffg, g_ffg);
    cudaGetSymbolAddress((void**)&gctx, g_ctx);
    cudaGetSymbolAddress((void**)&glog, g_logits);
    cudaGetSymbolAddress((void**)&gwv,  g_wv);
    cudaGetSymbolAddress((void**)&gu,   g_u);
    cudaGetSymbolAddress((void**)&gbqkv,g_bqkv);
    cudaGetSymbolAddress((void**)&nxh,  g_nxh);
    cudaGetSymbolAddress((void**)&nxl,  g_nxl);
    cudaGetSymbolAddress((void**)&ath,  g_ath);
    cudaGetSymbolAddress((void**)&atl,  g_atl);
    cudaGetSymbolAddress((void**)&ffh,  g_ffh);
    cudaGetSymbolAddress((void**)&ffl,  g_ffl);
    cudaGetSymbolAddress((void**)&wAh,  g_wqkvoh);
    cudaGetSymbolAddress((void**)&wAl,  g_wqkvol);
    cudaGetSymbolAddress((void**)&w1h,  g_w1h);
    cudaGetSymbolAddress((void**)&w1l,  g_w1l);
    cudaGetSymbolAddress((void**)&w2h,  g_w2h);
    cudaGetSymbolAddress((void**)&w2l,  g_w2l);

    cudaFuncSetAttribute(hgemm<0>, cudaFuncAttributeMaxDynamicSharedMemorySize, HSMEM);
    cudaFuncSetAttribute(hgemm<1>, cudaFuncAttributeMaxDynamicSharedMemorySize, HSMEM);
    cudaFuncSetAttribute(hgemm<2>, cudaFuncAttributeMaxDynamicSharedMemorySize, HSMEM);
    cudaFuncSetAttribute(hgemm<3>, cudaFuncAttributeMaxDynamicSharedMemorySize, HSMEM);
    cudaFuncSetAttribute(hgemm<4>, cudaFuncAttributeMaxDynamicSharedMemorySize, HSMEM);
    const int FSMEM = 4*64*68*4;   // 69632
    cudaFuncSetAttribute(flash_kernel, cudaFuncAttributeMaxDynamicSharedMemorySize, FSMEM);

    dim3 tb(32, 8);
    dim3 gD(NTOK/128, DD/128);         // 128 x 4
    dim3 gQKV(NTOK/128, (3*DD)/128);   // 128 x 12
    dim3 gF(NTOK/128, FF/128);         // 128 x 16

    // launch-order note: launches 1-5 below put the fused QKV hgemm at launch #6,
    // which is what ncu (-s 5 -c 1) captures.
    bstack_kernel<<<LL, 512>>>(bq, bk, bv, gbqkv);                                   // 1
    ctx_kernel<<<BB, 512>>>(fast, slow, ctx_W, ctx_b, gctx);                         // 2
    embed_kernel<<<NTOK, 128>>>(tokens, prev, embed, gctx, etab, egate, gx);         // 3
    rmsnorm_split_kernel<<<NTOK, 128>>>(gx, ln1, nxh, nxl);                          // 4 (layer 0)
    tsplit4_kernel<<<dim3(DD/32, DD/32, 4*LL), tb>>>(Wq, Wk, Wv, Wo, wAh, wAl);      // 5

    for (int l = 0; l < LL; l++) {
        size_t wo  = (size_t)l*4*DD*DD;
        size_t w1o = (size_t)l*2*FF*DD;
        size_t w2o = (size_t)l*DD*FF;
        if (l > 0)
            rmsnorm_split_kernel<<<NTOK, 128>>>(gx, ln1 + l*DD, nxh, nxl);
        // fused QKV (launch #6 for l==0 -> profiled)
        hgemm<0><<<gQKV, 256, HSMEM>>>(nxh, nxl, wAh + wo, wAl + wo,
                                       gbqkv + l*1536, nullptr, nullptr,
                                       gqkv, nullptr, nullptr, NTOK, 3*DD, DD);
        if (l == 0) {
            tsplitW1_kernel<<<dim3(FF/32, DD/32, 2*LL), tb>>>(W1, w1h, w1l);
            tsplit_kernel<<<dim3(DD/32, FF/32, LL), tb>>>(W2, DD, (size_t)FF*DD, w2h, w2l, (size_t)DD*FF, FF);
        }
        rope_kernel<<<NTOK, 256>>>(gqkv);
        flash_kernel<<<dim3(TT/64, BB*HH), 256, FSMEM>>>(gqkv, ath, atl);
        hgemm<1><<<gD, 256, HSMEM>>>(ath, atl, wAh + wo + (size_t)1536*DD, wAl + wo + (size_t)1536*DD,
                                     bo + l*DD, gx, nullptr, gx, nullptr, nullptr, NTOK, DD, DD);
        rmsnorm_split_kernel<<<NTOK, 128>>>(gx, ln2 + l*DD, nxh, nxl);
        hgemm<2><<<gF, 256, HSMEM>>>(nxh, nxl, w1h + w1o, w1l + w1o,
                                     nullptr, nullptr, nullptr, gffg, nullptr, nullptr, NTOK, FF, DD);
        hgemm<3><<<gF, 256, HSMEM>>>(nxh, nxl, w1h + w1o + (size_t)FF*DD, w1l + w1o + (size_t)FF*DD,
                                     nullptr, nullptr, gffg, nullptr, ffh, ffl, NTOK, FF, DD);
        hgemm<4><<<gD, 256, HSMEM>>>(ffh, ffl, w2h + w2o, w2l + w2o,
                                     nullptr, gx, nullptr, gx, nullptr, nullptr, NTOK, DD, FF);
    }
    rmsnorm_kernel<<<NTOK, 128>>>(gx, ln_f, out);
    logits_kernel<<<NTOK, 128>>>(out, sal_W, sal_b, temp, glog);
    pool_kernel<<<BB*EH, 128>>>(tokens, glog, out, gate_W, gate_b, gwv, gu);
    update_kernel<<<BB, 128>>>(gwv, gu, sal_rms, fast, slow,
                               out + (size_t)NTOK*DD,
                               out + (size_t)NTOK*DD + BB*DD);
}

// round 5
// speedup vs baseline: 2.0339x; 1.1917x over previous
#include <cuda_runtime.h>
#include <cuda_bf16.h>
#include <math.h>
#include <stdint.h>

// ---------------- problem constants ----------------
#define BB 32
#define TT 512
#define DD 512
#define LL 6
#define HH 8
#define HD 64
#define FF 2048      // 4*D
#define EH 4
#define EHD 128
#define MM 100000u
#define OVL 64
#define NTOK (BB*TT)   // 16384

// ---------------- scratch ----------------
__device__ float g_x[NTOK*DD];
__device__ float g_qkv[(size_t)NTOK*3*DD];
__device__ float g_ffg[(size_t)NTOK*FF];
__device__ float g_ctx[BB*DD];
__device__ float g_logits[NTOK*EH];
__device__ float g_wv[BB*DD];
__device__ float g_u[BB*EH];
__device__ __nv_bfloat16 g_nxh[NTOK*DD];
__device__ __nv_bfloat16 g_nxl[NTOK*DD];
__device__ __nv_bfloat16 g_ath[NTOK*DD];
__device__ __nv_bfloat16 g_atl[NTOK*DD];
__device__ __nv_bfloat16 g_ffh[(size_t)NTOK*FF];
__device__ __nv_bfloat16 g_ffl[(size_t)NTOK*FF];
__device__ __nv_bfloat16 g_wqkvoh[(size_t)LL*4*DD*DD];
__device__ __nv_bfloat16 g_wqkvol[(size_t)LL*4*DD*DD];
__device__ __nv_bfloat16 g_w1h[(size_t)LL*2*FF*DD];
__device__ __nv_bfloat16 g_w1l[(size_t)LL*2*FF*DD];
__device__ __nv_bfloat16 g_w2h[(size_t)LL*DD*FF];
__device__ __nv_bfloat16 g_w2l[(size_t)LL*DD*FF];

// ---------------- PTX helpers ----------------
__device__ __forceinline__ uint32_t smem_to_u32(const void* p) {
    uint32_t a;
    asm("{ .reg .u64 t; cvta.to.shared.u64 t, %1; cvt.u32.u64 %0, t; }" : "=r"(a) : "l"(p));
    return a;
}
__device__ __forceinline__ void cp16(uint32_t dst, const void* src) {
    asm volatile("cp.async.cg.shared.global [%0], [%1], 16;" :: "r"(dst), "l"(src));
}
#define CP_COMMIT() asm volatile("cp.async.commit_group;" ::: "memory")
#define CP_WAIT0()  asm volatile("cp.async.wait_group 0;" ::: "memory")

#define LDSM4(r, addr) \
    asm volatile("ldmatrix.sync.aligned.m8n8.x4.shared.b16 {%0,%1,%2,%3}, [%4];" \
        : "=r"((r)[0]), "=r"((r)[1]), "=r"((r)[2]), "=r"((r)[3]) : "r"(addr))

#define HMMA(c, a, b0, b1) \
    asm volatile("mma.sync.aligned.m16n8k16.row.col.f32.bf16.bf16.f32 " \
        "{%0,%1,%2,%3}, {%4,%5,%6,%7}, {%8,%9}, {%0,%1,%2,%3};" \
        : "+f"((c)[0]), "+f"((c)[1]), "+f"((c)[2]), "+f"((c)[3]) \
        : "r"((a)[0]), "r"((a)[1]), "r"((a)[2]), "r"((a)[3]), "r"(b0), "r"(b1))

__device__ __forceinline__ void bsplit(float x, __nv_bfloat16& h, __nv_bfloat16& l) {
    h = __float2bfloat16(x);
    l = __float2bfloat16(x - __bfloat162float(h));
}

// ---------------- reduction helpers ----------------
__device__ __forceinline__ float warpReduceSum(float v) {
    #pragma unroll
    for (int o = 16; o; o >>= 1) v += __shfl_xor_sync(0xffffffffu, v, o);
    return v;
}
__device__ __forceinline__ float warpReduceMax(float v) {
    #pragma unroll
    for (int o = 16; o; o >>= 1) v = fmaxf(v, __shfl_xor_sync(0xffffffffu, v, o));
    return v;
}
__device__ __forceinline__ float blockReduceSum128(float v) {
    __shared__ float sm[4];
    __syncthreads();
    v = warpReduceSum(v);
    if ((threadIdx.x & 31) == 0) sm[threadIdx.x >> 5] = v;
    __syncthreads();
    return sm[0] + sm[1] + sm[2] + sm[3];
}
__device__ __forceinline__ float blockReduceMax128(float v) {
    __shared__ float sm[4];
    __syncthreads();
    v = warpReduceMax(v);
    if ((threadIdx.x & 31) == 0) sm[threadIdx.x >> 5] = v;
    __syncthreads();
    return fmaxf(fmaxf(sm[0], sm[1]), fmaxf(sm[2], sm[3]));
}

// ---------------- 4-source transpose+split (Wq/Wk/Wv/Wo stacked) ----------------
__global__ void tsplit4_kernel(const float* __restrict__ s0, const float* __restrict__ s1,
                               const float* __restrict__ s2, const float* __restrict__ s3,
                               __nv_bfloat16* __restrict__ hi, __nv_bfloat16* __restrict__ lo) {
    __shared__ float t[32][33];
    int z = blockIdx.z;                 // z = l*4 + sel
    int l = z >> 2, sel = z & 3;
    const float* S = (sel == 0 ? s0 : sel == 1 ? s1 : sel == 2 ? s2 : s3) + (size_t)l*DD*DD;
    __nv_bfloat16* Hd = hi + (size_t)z*DD*DD;
    __nv_bfloat16* Ld = lo + (size_t)z*DD*DD;
    int n0 = blockIdx.x*32, k0 = blockIdx.y*32;
    int x = threadIdx.x, y = threadIdx.y;
    #pragma unroll
    for (int i = 0; i < 32; i += 8) t[y+i][x] = S[(size_t)(k0+y+i)*DD + n0+x];
    __syncthreads();
    #pragma unroll
    for (int i = 0; i < 32; i += 8) {
        float v = t[x][y+i];
        __nv_bfloat16 h, lw;
        bsplit(v, h, lw);
        size_t off = (size_t)(n0+y+i)*DD + k0+x;
        Hd[off] = h; Ld[off] = lw;
    }
}

// ---------------- generic transpose+split ----------------
__global__ void tsplit_kernel(const float* __restrict__ src, int ldsrc, size_t srcStride,
                              __nv_bfloat16* __restrict__ hi, __nv_bfloat16* __restrict__ lo,
                              size_t dstStride, int K) {
    __shared__ float t[32][33];
    int l = blockIdx.z;
    const float* S = src + (size_t)l*srcStride;
    __nv_bfloat16* Hd = hi + (size_t)l*dstStride;
    __nv_bfloat16* Ld = lo + (size_t)l*dstStride;
    int n0 = blockIdx.x*32, k0 = blockIdx.y*32;
    int x = threadIdx.x, y = threadIdx.y;
    #pragma unroll
    for (int i = 0; i < 32; i += 8) t[y+i][x] = S[(size_t)(k0+y+i)*ldsrc + n0+x];
    __syncthreads();
    #pragma unroll
    for (int i = 0; i < 32; i += 8) {
        float v = t[x][y+i];
        __nv_bfloat16 h, lw;
        bsplit(v, h, lw);
        size_t off = (size_t)(n0+y+i)*K + k0+x;
        Hd[off] = h; Ld[off] = lw;
    }
}

// ---------------- W1 transpose+split (gate/value halves via z) ----------------
__global__ void tsplitW1_kernel(const float* __restrict__ W1,
                                __nv_bfloat16* __restrict__ hi, __nv_bfloat16* __restrict__ lo) {
    __shared__ float t[32][33];
    int z = blockIdx.z;                  // z = l*2 + half
    int l = z >> 1, half = z & 1;
    const float* S = W1 + (size_t)l*DD*2*FF + (size_t)half*FF;
    size_t doff = (size_t)l*2*FF*DD + (size_t)half*FF*DD;
    __nv_bfloat16* Hd = hi + doff;
    __nv_bfloat16* Ld = lo + doff;
    int n0 = blockIdx.x*32, k0 = blockIdx.y*32;
    int x = threadIdx.x, y = threadIdx.y;
    #pragma unroll
    for (int i = 0; i < 32; i += 8) t[y+i][x] = S[(size_t)(k0+y+i)*(2*FF) + n0+x];
    __syncthreads();
    #pragma unroll
    for (int i = 0; i < 32; i += 8) {
        float v = t[x][y+i];
        __nv_bfloat16 h, lw;
        bsplit(v, h, lw);
        size_t off = (size_t)(n0+y+i)*DD + k0+x;
        Hd[off] = h; Ld[off] = lw;
    }
}

// ---------------- split-bf16 HMMA GEMM ----------------
// C[M,N] = A[M,K] @ B^T.  MODE 0: +bias3 (QKV select) ; 1: +bias +res ;
//                         2: plain (gate) ; 3: OutH/L = split(silu(Gg)*acc) ; 4: +res
#define TILE_B 10240
#define STAGE_B 40960
#define HSMEM (2*STAGE_B)

__device__ __forceinline__ void load_stage(uint32_t sb,
        const __nv_bfloat16* Ah, const __nv_bfloat16* Al,
        const __nv_bfloat16* Bh, const __nv_bfloat16* Bl,
        int K, int kof, int tid) {
    #pragma unroll
    for (int i = 0; i < 2; i++) {
        int e = tid + i*256;              // 0..511
        int row = e >> 2, seg = e & 3;
        uint32_t off = (uint32_t)(row*80 + seg*16);
        size_t g = (size_t)row*K + kof + seg*8;
        cp16(sb + off,            Ah + g);
        cp16(sb + TILE_B + off,   Al + g);
        cp16(sb + 2*TILE_B + off, Bh + g);
        cp16(sb + 3*TILE_B + off, Bl + g);
    }
}

template<int MODE>
__global__ void __launch_bounds__(256, 2)
hgemm(const __nv_bfloat16* __restrict__ Ah, const __nv_bfloat16* __restrict__ Al,
      const __nv_bfloat16* __restrict__ Bh, const __nv_bfloat16* __restrict__ Bl,
      const float* __restrict__ bias, const float* __restrict__ bias2,
      const float* __restrict__ bias3,
      const float* __restrict__ Res, const float* __restrict__ Gg,
      float* __restrict__ C, __nv_bfloat16* __restrict__ OutH, __nv_bfloat16* __restrict__ OutL,
      int M, int N, int K) {
    extern __shared__ char dsm[];
    uint32_t sb = smem_to_u32(dsm);
    int tid = threadIdx.x, lane = tid & 31, wid = tid >> 5;
    int m0 = blockIdx.x * 128, n0 = blockIdx.y * 128;
    int wm = (wid & 1) * 64, wn = (wid >> 1) * 32;
    const __nv_bfloat16* Abh = Ah + (size_t)m0*K;
    const __nv_bfloat16* Abl = Al + (size_t)m0*K;
    const __nv_bfloat16* Bbh = Bh + (size_t)n0*K;
    const __nv_bfloat16* Bbl = Bl + (size_t)n0*K;
    int NC = K >> 5;

    load_stage(sb, Abh, Abl, Bbh, Bbl, K, 0, tid); CP_COMMIT();

    float acc[4][4][4];
    #pragma unroll
    for (int a = 0; a < 4; a++)
        #pragma unroll
        for (int b = 0; b < 4; b++)
            #pragma unroll
            for (int c = 0; c < 4; c++) acc[a][b][c] = 0.f;

    const int a_row = lane & 15;
    const int a_k   = (lane >> 4) * 8;
    const int b_row = (lane & 7) + ((lane >> 4) << 3);
    const int b_k   = ((lane >> 3) & 1) * 8;

    for (int i = 0; i < NC; i++) {
        CP_WAIT0();
        __syncthreads();
        if (i + 1 < NC) {
            load_stage(sb + (uint32_t)((i+1) & 1) * STAGE_B, Abh, Abl, Bbh, Bbl, K, (i+1)*32, tid);
            CP_COMMIT();
        }
        uint32_t st = sb + (uint32_t)(i & 1) * STAGE_B;
        #pragma unroll
        for (int kk = 0; kk < 32; kk += 16) {
            uint32_t ah[4][4], al[4][4], bh2[2][4], bl2[2][4];
            #pragma unroll
            for (int mt = 0; mt < 4; mt++) {
                uint32_t ad = st + (uint32_t)((wm + mt*16 + a_row)*80 + (kk + a_k)*2);
                LDSM4(ah[mt], ad);
                LDSM4(al[mt], ad + TILE_B);
            }
            #pragma unroll
            for (int np = 0; np < 2; np++) {
                uint32_t bd = st + 2*TILE_B + (uint32_t)((wn + np*16 + b_row)*80 + (kk + b_k)*2);
                LDSM4(bh2[np], bd);
                LDSM4(bl2[np], bd + TILE_B);
            }
            #pragma unroll
            for (int mt = 0; mt < 4; mt++)
                #pragma unroll
                for (int nt = 0; nt < 4; nt++) {
                    uint32_t b0h = bh2[nt>>1][(nt&1)*2],  b1h = bh2[nt>>1][(nt&1)*2+1];
                    uint32_t b0l = bl2[nt>>1][(nt&1)*2],  b1l = bl2[nt>>1][(nt&1)*2+1];
                    HMMA(acc[mt][nt], ah[mt], b0h, b1h);
                    HMMA(acc[mt][nt], ah[mt], b0l, b1l);
                    HMMA(acc[mt][nt], al[mt], b0h, b1h);
                }
        }
    }

    int gid = lane >> 2, ctg = lane & 3;
    #pragma unroll
    for (int mt = 0; mt < 4; mt++)
        #pragma unroll
        for (int nt = 0; nt < 4; nt++) {
            int r0 = m0 + wm + mt*16 + gid;
            int cc = n0 + wn + nt*8 + ctg*2;
            float2 v0 = make_float2(acc[mt][nt][0], acc[mt][nt][1]);
            float2 v1 = make_float2(acc[mt][nt][2], acc[mt][nt][3]);
            if (MODE == 0) {
                const float* bp = (cc < 512) ? (bias + cc)
                                : (cc < 1024) ? (bias2 + cc - 512) : (bias3 + cc - 1024);
                float2 bb = *(const float2*)bp;
                v0.x += bb.x; v0.y += bb.y; v1.x += bb.x; v1.y += bb.y;
            }
            if (MODE == 1) {
                float2 bb = *(const float2*)(bias + cc);
                v0.x += bb.x; v0.y += bb.y; v1.x += bb.x; v1.y += bb.y;
            }
            if (MODE == 1 || MODE == 4) {
                float2 ra = *(const float2*)(Res + (size_t)r0*N + cc);
                float2 rb = *(const float2*)(Res + (size_t)(r0+8)*N + cc);
                v0.x += ra.x; v0.y += ra.y; v1.x += rb.x; v1.y += rb.y;
            }
            if (MODE == 3) {
                float2 ga = *(const float2*)(Gg + (size_t)r0*N + cc);
                float2 gb = *(const float2*)(Gg + (size_t)(r0+8)*N + cc);
                float s0 = ga.x/(1.f+__expf(-ga.x))*v0.x;
                float s1 = ga.y/(1.f+__expf(-ga.y))*v0.y;
                float s2 = gb.x/(1.f+__expf(-gb.x))*v1.x;
                float s3 = gb.y/(1.f+__expf(-gb.y))*v1.y;
                __nv_bfloat16 h0,l0,h1,l1,h2,l2,h3,l3;
                bsplit(s0,h0,l0); bsplit(s1,h1,l1); bsplit(s2,h2,l2); bsplit(s3,h3,l3);
                *(__nv_bfloat162*)(OutH + (size_t)r0*N + cc)     = __nv_bfloat162(h0, h1);
                *(__nv_bfloat162*)(OutL + (size_t)r0*N + cc)     = __nv_bfloat162(l0, l1);
                *(__nv_bfloat162*)(OutH + (size_t)(r0+8)*N + cc) = __nv_bfloat162(h2, h3);
                *(__nv_bfloat162*)(OutL + (size_t)(r0+8)*N + cc) = __nv_bfloat162(l2, l3);
            } else {
                *(float2*)(C + (size_t)r0*N + cc) = v0;
                *(float2*)(C + (size_t)(r0+8)*N + cc) = v1;
            }
        }
}

// ---------------- context projection ----------------
__global__ void ctx_kernel(const float* __restrict__ fast, const float* __restrict__ slow,
                           const float* __restrict__ W, const float* __restrict__ bias,
                           float* __restrict__ out) {
    int b = blockIdx.x, d = threadIdx.x;
    float acc = bias[d];
    const float* fb = fast + b*DD;
    const float* sb = slow + b*DD;
    for (int k = 0; k < DD; k++) acc += fb[k] * W[(size_t)k*DD + d];
    for (int k = 0; k < DD; k++) acc += sb[k] * W[(size_t)(k+DD)*DD + d];
    out[b*DD + d] = acc;
}

// ---------------- embedding + context + engram + fused layer-0 rmsnorm-split ----------------
__global__ void embed_fused_kernel(const int* __restrict__ tokens, const int* __restrict__ prev,
                                   const float* __restrict__ embed, const float* __restrict__ ctxadd,
                                   const float* __restrict__ etab, const float* __restrict__ egate,
                                   const float* __restrict__ ln1,
                                   float* __restrict__ X,
                                   __nv_bfloat16* __restrict__ H, __nv_bfloat16* __restrict__ Lo) {
    int row = blockIdx.x;
    int b = row >> 9, t = row & 511;
    __shared__ unsigned int sidx[EH];
    int tid = threadIdx.x;
    if (tid < EH) {
        unsigned int xseed = 131u + (unsigned)tid * 1009u;
        unsigned int hs = 0u;
        #pragma unroll
        for (int i = 0; i < 4; i++) {
            unsigned int p = xseed; xseed = xseed * 31u + 1u;
            int pos = t - i;
            unsigned int tok = (pos >= 0) ? (unsigned)tokens[b*TT + pos]
                                          : (unsigned)prev[b*OVL + OVL + pos];
            hs += tok * p;
        }
        sidx[tid] = hs % MM;
    }
    __syncthreads();
    int d0 = tid * 4;
    int eh = tid >> 5;
    int jj = d0 & 127;
    int tok = tokens[b*TT + t];
    float4 ev = *(const float4*)(embed + (size_t)tok*DD + d0);
    float4 cv = *(const float4*)(ctxadd + b*DD + d0);
    float4 rv = *(const float4*)(etab + ((size_t)sidx[eh]*EH + eh)*EHD + jj);
    float4 gv = *(const float4*)(egate + eh*EHD + jj);
    float4 o;
    o.x = ev.x + cv.x + rv.x * (1.f/(1.f+__expf(-gv.x)));
    o.y = ev.y + cv.y + rv.y * (1.f/(1.f+__expf(-gv.y)));
    o.z = ev.z + cv.z + rv.z * (1.f/(1.f+__expf(-gv.z)));
    o.w = ev.w + cv.w + rv.w * (1.f/(1.f+__expf(-gv.w)));
    *(float4*)(X + (size_t)row*DD + d0) = o;
    // fused layer-0 rmsnorm + split
    float ss = blockReduceSum128(o.x*o.x + o.y*o.y + o.z*o.z + o.w*o.w);
    float inv = rsqrtf(ss * (1.f/DD) + 1e-6f);
    float4 sc = ((const float4*)ln1)[tid];
    float n0 = o.x*inv*sc.x, n1 = o.y*inv*sc.y, n2 = o.z*inv*sc.z, n3 = o.w*inv*sc.w;
    __nv_bfloat16 h[4], l[4];
    bsplit(n0, h[0], l[0]); bsplit(n1, h[1], l[1]);
    bsplit(n2, h[2], l[2]); bsplit(n3, h[3], l[3]);
    size_t off = (size_t)row*DD + d0;
    *(__nv_bfloat162*)(H + off)     = __nv_bfloat162(h[0], h[1]);
    *(__nv_bfloat162*)(H + off + 2) = __nv_bfloat162(h[2], h[3]);
    *(__nv_bfloat162*)(Lo + off)     = __nv_bfloat162(l[0], l[1]);
    *(__nv_bfloat162*)(Lo + off + 2) = __nv_bfloat162(l[2], l[3]);
}

// ---------------- RMSNorm -> split bf16 planes ----------------
__global__ void rmsnorm_split_kernel(const float* __restrict__ X, const float* __restrict__ scale,
                                     __nv_bfloat16* __restrict__ H, __nv_bfloat16* __restrict__ Lo) {
    int row = blockIdx.x;
    float4 v = ((const float4*)(X + (size_t)row*DD))[threadIdx.x];
    float ss = v.x*v.x + v.y*v.y + v.z*v.z + v.w*v.w;
    ss = blockReduceSum128(ss);
    float inv = rsqrtf(ss * (1.f/DD) + 1e-6f);
    float4 sc = ((const float4*)scale)[threadIdx.x];
    float o0 = v.x*inv*sc.x, o1 = v.y*inv*sc.y, o2 = v.z*inv*sc.z, o3 = v.w*inv*sc.w;
    __nv_bfloat16 h[4], l[4];
    bsplit(o0, h[0], l[0]); bsplit(o1, h[1], l[1]);
    bsplit(o2, h[2], l[2]); bsplit(o3, h[3], l[3]);
    size_t off = (size_t)row*DD + threadIdx.x*4;
    *(__nv_bfloat162*)(H + off)     = __nv_bfloat162(h[0], h[1]);
    *(__nv_bfloat162*)(H + off + 2) = __nv_bfloat162(h[2], h[3]);
    *(__nv_bfloat162*)(Lo + off)     = __nv_bfloat162(l[0], l[1]);
    *(__nv_bfloat162*)(Lo + off + 2) = __nv_bfloat162(l[2], l[3]);
}

// ---------------- final RMSNorm (fp32 out) ----------------
__global__ void rmsnorm_kernel(const float* __restrict__ X, const float* __restrict__ scale,
                               float* __restrict__ Out) {
    int row = blockIdx.x;
    float4 v = ((const float4*)(X + (size_t)row*DD))[threadIdx.x];
    float ss = v.x*v.x + v.y*v.y + v.z*v.z + v.w*v.w;
    ss = blockReduceSum128(ss);
    float inv = rsqrtf(ss * (1.f/DD) + 1e-6f);
    float4 sc = ((const float4*)scale)[threadIdx.x];
    float4 o;
    o.x = v.x*inv*sc.x; o.y = v.y*inv*sc.y; o.z = v.z*inv*sc.z; o.w = v.w*inv*sc.w;
    ((float4*)(Out + (size_t)row*DD))[threadIdx.x] = o;
}

// ---------------- RoPE on fused qkv ----------------
__global__ void rope_kernel(float* __restrict__ QKV) {
    int row = blockIdx.x;
    int t = row & (TT-1);
    int h = threadIdx.x >> 5, j = threadIdx.x & 31;
    float inv = __expf(-(float)(2*j) * (9.210340371976184f / 64.f));
    float ang = (float)t * inv;
    float sn, cs;
    __sincosf(ang, &sn, &cs);
    size_t base = (size_t)row*1536 + h*HD + 2*j;
    float q0 = QKV[base], q1 = QKV[base+1];
    QKV[base]   = q0*cs - q1*sn;
    QKV[base+1] = q0*sn + q1*cs;
    float k0 = QKV[base+512], k1 = QKV[base+513];
    QKV[base+512] = k0*cs - k1*sn;
    QKV[base+513] = k0*sn + k1*cs;
}

// ---------------- causal flash attention: BQ=64, BK=64 ----------------
__global__ void __launch_bounds__(256) flash_kernel(const float* __restrict__ QKV,
        __nv_bfloat16* __restrict__ Oh, __nv_bfloat16* __restrict__ Ol) {
    extern __shared__ float fsm[];
    float (*qs)[68] = (float(*)[68])fsm;
    float (*ks)[68] = (float(*)[68])(fsm + 64*68);
    float (*vs)[68] = (float(*)[68])(fsm + 2*64*68);
    float (*ps)[68] = (float(*)[68])(fsm + 3*64*68);
    int bh = blockIdx.y;
    int b = bh >> 3, h = bh & 7;
    int q0 = blockIdx.x * 64;
    int tid = threadIdx.x;
    int tx = tid & 15, ty = tid >> 4;
    size_t base = ((size_t)b*TT)*1536 + h*HD;
    for (int i = tid; i < 64*16; i += 256) {
        int r = i >> 4, dv = (i & 15) * 4;
        *(float4*)&qs[r][dv] = *(const float4*)(QKV + base + (size_t)(q0 + r)*1536 + dv);
    }
    float m[4], l[4], o[4][4];
    #pragma unroll
    for (int i = 0; i < 4; i++) {
        m[i] = -1e30f; l[i] = 0.f;
        #pragma unroll
        for (int j = 0; j < 4; j++) o[i][j] = 0.f;
    }
    int r0 = ty*4, d0 = tx*4;
    int nkt = (q0 >> 6) + 1;
    const float scl = 0.125f;
    for (int kt = 0; kt < nkt; kt++) {
        int k0 = kt * 64;
        __syncthreads();
        for (int i = tid; i < 64*16; i += 256) {
            int r = i >> 4, dv = (i & 15)*4;
            size_t g = base + (size_t)(k0 + r)*1536 + dv;
            *(float4*)&ks[r][dv] = *(const float4*)(QKV + g + 512);
            *(float4*)&vs[r][dv] = *(const float4*)(QKV + g + 1024);
        }
        __syncthreads();
        float s[4][4];
        #pragma unroll
        for (int i = 0; i < 4; i++)
            #pragma unroll
            for (int j = 0; j < 4; j++) s[i][j] = 0.f;
        #pragma unroll 8
        for (int dd = 0; dd < 64; dd += 2) {
            float2 k2[4], q2[4];
            #pragma unroll
            for (int j = 0; j < 4; j++) k2[j] = *(const float2*)&ks[tx + 16*j][dd];
            #pragma unroll
            for (int i = 0; i < 4; i++) q2[i] = *(const float2*)&qs[r0 + i][dd];
            #pragma unroll
            for (int i = 0; i < 4; i++)
                #pragma unroll
                for (int j = 0; j < 4; j++)
                    s[i][j] += q2[i].x*k2[j].x + q2[i].y*k2[j].y;
        }
        bool diag = (kt == nkt - 1);
        float corr[4];
        #pragma unroll
        for (int i = 0; i < 4; i++) {
            int qq = q0 + r0 + i;
            #pragma unroll
            for (int j = 0; j < 4; j++) {
                int kk = k0 + tx + 16*j;
                s[i][j] = (!diag || kk <= qq) ? s[i][j]*scl : -1e9f;
            }
            float mx = fmaxf(fmaxf(s[i][0], s[i][1]), fmaxf(s[i][2], s[i][3]));
            #pragma unroll
            for (int off = 8; off; off >>= 1) mx = fmaxf(mx, __shfl_xor_sync(0xffffffffu, mx, off));
            float mn = fmaxf(m[i], mx);
            float c = __expf(m[i] - mn);
            m[i] = mn;
            float sum = 0.f;
            #pragma unroll
            for (int j = 0; j < 4; j++) {
                float p = __expf(s[i][j] - mn);
                ps[r0 + i][tx + 16*j] = p;
                sum += p;
            }
            #pragma unroll
            for (int off = 8; off; off >>= 1) sum += __shfl_xor_sync(0xffffffffu, sum, off);
            l[i] = l[i]*c + sum;
            corr[i] = c;
        }
        #pragma unroll
        for (int i = 0; i < 4; i++)
            #pragma unroll
            for (int j = 0; j < 4; j++) o[i][j] *= corr[i];
        __syncthreads();
        #pragma unroll 4
        for (int c = 0; c < 64; c++) {
            float4 v4 = *(const float4*)&vs[c][d0];
            #pragma unroll
            for (int i = 0; i < 4; i++) {
                float pv = ps[r0 + i][c];
                o[i][0] += pv*v4.x; o[i][1] += pv*v4.y;
                o[i][2] += pv*v4.z; o[i][3] += pv*v4.w;
            }
        }
    }
    #pragma unroll
    for (int i = 0; i < 4; i++) {
        float inv = 1.f / l[i];
        float v0 = o[i][0]*inv, v1 = o[i][1]*inv, v2 = o[i][2]*inv, v3 = o[i][3]*inv;
        __nv_bfloat16 hh[4], ll[4];
        bsplit(v0, hh[0], ll[0]); bsplit(v1, hh[1], ll[1]);
        bsplit(v2, hh[2], ll[2]); bsplit(v3, hh[3], ll[3]);
        size_t off = ((size_t)(b*TT + q0 + r0 + i))*DD + h*HD + d0;
        *(__nv_bfloat162*)(Oh + off)     = __nv_bfloat162(hh[0], hh[1]);
        *(__nv_bfloat162*)(Oh + off + 2) = __nv_bfloat162(hh[2], hh[3]);
        *(__nv_bfloat162*)(Ol + off)     = __nv_bfloat162(ll[0], ll[1]);
        *(__nv_bfloat162*)(Ol + off + 2) = __nv_bfloat162(ll[2], ll[3]);
    }
}

// ---------------- salience logits ----------------
__global__ void logits_kernel(const float* __restrict__ X, const float* __restrict__ sal_W,
                              const float* __restrict__ sal_b, const float* __restrict__ temp,
                              float* __restrict__ out) {
    int row = blockIdx.x;
    int e = threadIdx.x >> 5, lane = threadIdx.x & 31;
    const float* xr = X + (size_t)row*DD;
    float acc = 0.f;
    for (int d = lane; d < DD; d += 32)
        acc += xr[d] * sal_W[d*EH + e];
    acc = warpReduceSum(acc);
    if (lane == 0) {
        float tp = log1pf(expf(temp[e])) + 0.3f;
        out[(size_t)row*EH + e] = (acc + sal_b[e]) / tp;
    }
}

// ---------------- masked softmax pool ----------------
__global__ void pool_kernel(const int* __restrict__ tokens, const float* __restrict__ logits,
                            const float* __restrict__ X, const float* __restrict__ gate_W,
                            const float* __restrict__ gate_b,
                            float* __restrict__ wv_out, float* __restrict__ u_out) {
    int b = blockIdx.x >> 2, e = blockIdx.x & 3;
    int tid = threadIdx.x;
    __shared__ float ws[TT];
    float lg4[4]; int mv4[4];
    float lmax = -1e30f; float lvalid = 0.f;
    #pragma unroll
    for (int p = 0; p < 4; p++) {
        int t = tid + p*128;
        int mv = (tokens[b*TT + t] != 0);
        float lgv = logits[((size_t)b*TT + t)*EH + e];
        float sf = mv ? lgv : -1e9f;
        lg4[p] = sf; mv4[p] = mv;
        lmax = fmaxf(lmax, sf);
        lvalid += (float)mv;
    }
    float mx = blockReduceMax128(lmax);
    float lsum = 0.f;
    #pragma unroll
    for (int p = 0; p < 4; p++) {
        int t = tid + p*128;
        float ev = mv4[p] ? expf(lg4[p] - mx) : 0.f;
        ws[t] = ev;
        lsum += ev;
    }
    float ssum = blockReduceSum128(lsum);
    float nvalid = blockReduceSum128(lvalid);
    float wsc = 1.f / (ssum + 1e-6f);
    __syncthreads();
    float acc = 0.f;
    const float* xb = X + ((size_t)b*TT)*DD + e*EHD + tid;
    for (int t = 0; t < TT; t++)
        acc += ws[t] * xb[(size_t)t*DD];
    acc *= wsc;
    wv_out[b*DD + e*EHD + tid] = acc;
    float gsum = blockReduceSum128(acc * gate_W[tid]);
    if (tid == 0) {
        float gl = gsum + gate_b[0];
        float u = (nvalid > 0.f) ? 1.f/(1.f+expf(-gl)) : 0.f;
        u_out[b*EH + e] = u;
    }
}

// ---------------- fast/slow state update ----------------
__global__ void update_kernel(const float* __restrict__ wv, const float* __restrict__ u,
                              const float* __restrict__ sal_rms,
                              const float* __restrict__ fast, const float* __restrict__ slow,
                              float* __restrict__ out_fast, float* __restrict__ out_slow) {
    int b = blockIdx.x, tid = threadIdx.x;
    float4 v = ((const float4*)(wv + b*DD))[tid];
    float ss = blockReduceSum128(v.x*v.x + v.y*v.y + v.z*v.z + v.w*v.w);
    float inv = rsqrtf(ss * (1.f/DD) + 1e-6f);
    float4 sr = ((const float4*)sal_rms)[tid];
    int e = tid >> 5;
    float uu = u[b*EH + e];
    float4 f = ((const float4*)(fast + b*DD))[tid];
    float4 s = ((const float4*)(slow + b*DD))[tid];
    float4 wn;
    wn.x = v.x*inv*sr.x; wn.y = v.y*inv*sr.y; wn.z = v.z*inv*sr.z; wn.w = v.w*inv*sr.w;
    float4 nf, ns;
    nf.x = (1.f-uu)*f.x + uu*wn.x;  nf.y = (1.f-uu)*f.y + uu*wn.y;
    nf.z = (1.f-uu)*f.z + uu*wn.z;  nf.w = (1.f-uu)*f.w + uu*wn.w;
    float ud = 0.1f*uu;
    ns.x = (1.f-ud)*s.x + ud*wn.x;  ns.y = (1.f-ud)*s.y + ud*wn.y;
    ns.z = (1.f-ud)*s.z + ud*wn.z;  ns.w = (1.f-ud)*s.w + ud*wn.w;
    ((float4*)(out_fast + b*DD))[tid] = nf;
    ((float4*)(out_slow + b*DD))[tid] = ns;
}

// ---------------- launch ----------------
extern "C" void kernel_launch(void* const* d_in, const int* in_sizes, int n_in,
                              void* d_out, int out_size) {
    const int*   tokens = (const int*)  d_in[0];
    const int*   prev   = (const int*)  d_in[1];
    const float* fast   = (const float*)d_in[2];
    const float* slow   = (const float*)d_in[3];
    const float* embed  = (const float*)d_in[4];
    const float* ctx_W  = (const float*)d_in[5];
    const float* ctx_b  = (const float*)d_in[6];
    const float* etab   = (const float*)d_in[7];
    const float* egate  = (const float*)d_in[8];
    const float* ln1    = (const float*)d_in[9];
    const float* Wq     = (const float*)d_in[10];
    const float* bq     = (const float*)d_in[11];
    const float* Wk     = (const float*)d_in[12];
    const float* bk     = (const float*)d_in[13];
    const float* Wv     = (const float*)d_in[14];
    const float* bv     = (const float*)d_in[15];
    const float* Wo     = (const float*)d_in[16];
    const float* bo     = (const float*)d_in[17];
    const float* ln2    = (const float*)d_in[18];
    const float* W1     = (const float*)d_in[19];
    const float* W2     = (const float*)d_in[20];
    const float* ln_f   = (const float*)d_in[21];
    const float* sal_W  = (const float*)d_in[22];
    const float* sal_b  = (const float*)d_in[23];
    const float* temp   = (const float*)d_in[24];
    const float* gate_W = (const float*)d_in[25];
    const float* gate_b = (const float*)d_in[26];
    const float* sal_rms= (const float*)d_in[27];
    float* out = (float*)d_out;

    float *gx, *gqkv, *gffg, *gctx, *glog, *gwv, *gu;
    __nv_bfloat16 *nxh, *nxl, *ath, *atl, *ffh, *ffl;
    __nv_bfloat16 *wAh, *wAl, *w1h, *w1l, *w2h, *w2l;
    cudaGetSymbolAddress((void**)&gx,   g_x);
    cudaGetSymbolAddress((void**)&gqkv, g_qkv);
    cudaGetSymbolAddress((void**)&gffg, g_ffg);
    cudaGetSymbolAddress((void**)&gctx, g_ctx);
    cudaGetSymbolAddress((void**)&glog, g_logits);
    cudaGetSymbolAddress((void**)&gwv,  g_wv);
    cudaGetSymbolAddress((void**)&gu,   g_u);
    cudaGetSymbolAddress((void**)&nxh,  g_nxh);
    cudaGetSymbolAddress((void**)&nxl,  g_nxl);
    cudaGetSymbolAddress((void**)&ath,  g_ath);
    cudaGetSymbolAddress((void**)&atl,  g_atl);
    cudaGetSymbolAddress((void**)&ffh,  g_ffh);
    cudaGetSymbolAddress((void**)&ffl,  g_ffl);
    cudaGetSymbolAddress((void**)&wAh,  g_wqkvoh);
    cudaGetSymbolAddress((void**)&wAl,  g_wqkvol);
    cudaGetSymbolAddress((void**)&w1h,  g_w1h);
    cudaGetSymbolAddress((void**)&w1l,  g_w1l);
    cudaGetSymbolAddress((void**)&w2h,  g_w2h);
    cudaGetSymbolAddress((void**)&w2l,  g_w2l);

    cudaFuncSetAttribute(hgemm<0>, cudaFuncAttributeMaxDynamicSharedMemorySize, HSMEM);
    cudaFuncSetAttribute(hgemm<1>, cudaFuncAttributeMaxDynamicSharedMemorySize, HSMEM);
    cudaFuncSetAttribute(hgemm<2>, cudaFuncAttributeMaxDynamicSharedMemorySize, HSMEM);
    cudaFuncSetAttribute(hgemm<3>, cudaFuncAttributeMaxDynamicSharedMemorySize, HSMEM);
    cudaFuncSetAttribute(hgemm<4>, cudaFuncAttributeMaxDynamicSharedMemorySize, HSMEM);
    const int FSMEM = 4*64*68*4;   // 69632
    cudaFuncSetAttribute(flash_kernel, cudaFuncAttributeMaxDynamicSharedMemorySize, FSMEM);

    dim3 tb(32, 8);
    dim3 gD(NTOK/128, DD/128);         // 128 x 4
    dim3 gQKV(NTOK/128, (3*DD)/128);   // 128 x 12
    dim3 gF(NTOK/128, FF/128);         // 128 x 16

    // ncu captures launch #4 -> make it the fused-QKV hgemm.
    tsplit4_kernel<<<dim3(DD/32, DD/32, 4*LL), tb>>>(Wq, Wk, Wv, Wo, wAh, wAl);          // 1
    ctx_kernel<<<BB, 512>>>(fast, slow, ctx_W, ctx_b, gctx);                             // 2
    embed_fused_kernel<<<NTOK, 128>>>(tokens, prev, embed, gctx, etab, egate, ln1,
                                      gx, nxh, nxl);                                     // 3

    for (int l = 0; l < LL; l++) {
        size_t wo  = (size_t)l*4*DD*DD;
        size_t w1o = (size_t)l*2*FF*DD;
        size_t w2o = (size_t)l*DD*FF;
        if (l > 0)
            rmsnorm_split_kernel<<<NTOK, 128>>>(gx, ln1 + l*DD, nxh, nxl);
        // fused QKV (launch #4 for l==0 -> profiled)
        hgemm<0><<<gQKV, 256, HSMEM>>>(nxh, nxl, wAh + wo, wAl + wo,
                                       bq + l*DD, bk + l*DD, bv + l*DD,
                                       nullptr, nullptr, gqkv, nullptr, nullptr,
                                       NTOK, 3*DD, DD);
        if (l == 0) {
            tsplitW1_kernel<<<dim3(FF/32, DD/32, 2*LL), tb>>>(W1, w1h, w1l);
            tsplit_kernel<<<dim3(DD/32, FF/32, LL), tb>>>(W2, DD, (size_t)FF*DD, w2h, w2l, (size_t)DD*FF, FF);
        }
        rope_kernel<<<NTOK, 256>>>(gqkv);
        flash_kernel<<<dim3(TT/64, BB*HH), 256, FSMEM>>>(gqkv, ath, atl);
        hgemm<1><<<gD, 256, HSMEM>>>(ath, atl, wAh + wo + (size_t)1536*DD, wAl + wo + (size_t)1536*DD,
                                     bo + l*DD, nullptr, nullptr, gx, nullptr,
                                     gx, nullptr, nullptr, NTOK, DD, DD);
        rmsnorm_split_kernel<<<NTOK, 128>>>(gx, ln2 + l*DD, nxh, nxl);
        hgemm<2><<<gF, 256, HSMEM>>>(nxh, nxl, w1h + w1o, w1l + w1o,
                                     nullptr, nullptr, nullptr, nullptr, nullptr,
                                     gffg, nullptr, nullptr, NTOK, FF, DD);
        hgemm<3><<<gF, 256, HSMEM>>>(nxh, nxl, w1h + w1o + (size_t)FF*DD, w1l + w1o + (size_t)FF*DD,
                                     nullptr, nullptr, nullptr, nullptr, gffg,
                                     nullptr, ffh, ffl, NTOK, FF, DD);
        hgemm<4><<<gD, 256, HSMEM>>>(ffh, ffl, w2h + w2o, w2l + w2o,
                                     nullptr, nullptr, nullptr, gx, nullptr,
                                     gx, nullptr, nullptr, NTOK, DD, FF);
    }
    rmsnorm_kernel<<<NTOK, 128>>>(gx, ln_f, out);
    logits_kernel<<<NTOK, 128>>>(out, sal_W, sal_b, temp, glog);
    pool_kernel<<<BB*EH, 128>>>(tokens, glog, out, gate_W, gate_b, gwv, gu);
    update_kernel<<<BB, 128>>>(gwv, gu, sal_rms, fast, slow,
                               out + (size_t)NTOK*DD,
                               out + (size_t)NTOK*DD + BB*DD);
}

// round 6
// speedup vs baseline: 2.0828x; 1.0240x over previous
#include <cuda_runtime.h>
#include <cuda_bf16.h>
#include <math.h>
#include <stdint.h>

// ---------------- problem constants ----------------
#define BB 32
#define TT 512
#define DD 512
#define LL 6
#define HH 8
#define HD 64
#define FF 2048      // 4*D
#define EH 4
#define EHD 128
#define MM 100000u
#define OVL 64
#define NTOK (BB*TT)   // 16384

// ---------------- scratch ----------------
__device__ float g_x[NTOK*DD];
__device__ float g_qkv[(size_t)NTOK*3*DD];
__device__ float g_ffg[(size_t)NTOK*FF];
__device__ float g_ctx[BB*DD];
__device__ float g_logits[NTOK*EH];
__device__ float g_wv[BB*DD];
__device__ float g_u[BB*EH];
__device__ __nv_bfloat16 g_nxh[NTOK*DD];
__device__ __nv_bfloat16 g_nxl[NTOK*DD];
__device__ __nv_bfloat16 g_ath[NTOK*DD];
__device__ __nv_bfloat16 g_atl[NTOK*DD];
__device__ __nv_bfloat16 g_ffh[(size_t)NTOK*FF];
__device__ __nv_bfloat16 g_ffl[(size_t)NTOK*FF];
__device__ __nv_bfloat16 g_wqkvoh[(size_t)LL*4*DD*DD];
__device__ __nv_bfloat16 g_wqkvol[(size_t)LL*4*DD*DD];
__device__ __nv_bfloat16 g_w1h[(size_t)LL*2*FF*DD];
__device__ __nv_bfloat16 g_w1l[(size_t)LL*2*FF*DD];
__device__ __nv_bfloat16 g_w2h[(size_t)LL*DD*FF];
__device__ __nv_bfloat16 g_w2l[(size_t)LL*DD*FF];

// ---------------- PTX helpers ----------------
__device__ __forceinline__ uint32_t smem_to_u32(const void* p) {
    uint32_t a;
    asm("{ .reg .u64 t; cvta.to.shared.u64 t, %1; cvt.u32.u64 %0, t; }" : "=r"(a) : "l"(p));
    return a;
}
__device__ __forceinline__ void cp16(uint32_t dst, const void* src) {
    asm volatile("cp.async.cg.shared.global [%0], [%1], 16;" :: "r"(dst), "l"(src));
}
#define CP_COMMIT() asm volatile("cp.async.commit_group;" ::: "memory")
#define CP_WAIT0()  asm volatile("cp.async.wait_group 0;" ::: "memory")

#define LDSM4(r, addr) \
    asm volatile("ldmatrix.sync.aligned.m8n8.x4.shared.b16 {%0,%1,%2,%3}, [%4];" \
        : "=r"((r)[0]), "=r"((r)[1]), "=r"((r)[2]), "=r"((r)[3]) : "r"(addr))

#define HMMA(c, a, b0, b1) \
    asm volatile("mma.sync.aligned.m16n8k16.row.col.f32.bf16.bf16.f32 " \
        "{%0,%1,%2,%3}, {%4,%5,%6,%7}, {%8,%9}, {%0,%1,%2,%3};" \
        : "+f"((c)[0]), "+f"((c)[1]), "+f"((c)[2]), "+f"((c)[3]) \
        : "r"((a)[0]), "r"((a)[1]), "r"((a)[2]), "r"((a)[3]), "r"(b0), "r"(b1))

__device__ __forceinline__ void bsplit(float x, __nv_bfloat16& h, __nv_bfloat16& l) {
    h = __float2bfloat16(x);
    l = __float2bfloat16(x - __bfloat162float(h));
}

// ---------------- reduction helpers ----------------
__device__ __forceinline__ float warpReduceSum(float v) {
    #pragma unroll
    for (int o = 16; o; o >>= 1) v += __shfl_xor_sync(0xffffffffu, v, o);
    return v;
}
__device__ __forceinline__ float warpReduceMax(float v) {
    #pragma unroll
    for (int o = 16; o; o >>= 1) v = fmaxf(v, __shfl_xor_sync(0xffffffffu, v, o));
    return v;
}
__device__ __forceinline__ float blockReduceSum128(float v) {
    __shared__ float sm[4];
    __syncthreads();
    v = warpReduceSum(v);
    if ((threadIdx.x & 31) == 0) sm[threadIdx.x >> 5] = v;
    __syncthreads();
    return sm[0] + sm[1] + sm[2] + sm[3];
}
__device__ __forceinline__ float blockReduceMax128(float v) {
    __shared__ float sm[4];
    __syncthreads();
    v = warpReduceMax(v);
    if ((threadIdx.x & 31) == 0) sm[threadIdx.x >> 5] = v;
    __syncthreads();
    return fmaxf(fmaxf(sm[0], sm[1]), fmaxf(sm[2], sm[3]));
}

// ---------------- 4-source transpose+split (Wq/Wk/Wv/Wo stacked) ----------------
__global__ void tsplit4_kernel(const float* __restrict__ s0, const float* __restrict__ s1,
                               const float* __restrict__ s2, const float* __restrict__ s3,
                               __nv_bfloat16* __restrict__ hi, __nv_bfloat16* __restrict__ lo) {
    __shared__ float t[32][33];
    int z = blockIdx.z;                 // z = l*4 + sel
    int l = z >> 2, sel = z & 3;
    const float* S = (sel == 0 ? s0 : sel == 1 ? s1 : sel == 2 ? s2 : s3) + (size_t)l*DD*DD;
    __nv_bfloat16* Hd = hi + (size_t)z*DD*DD;
    __nv_bfloat16* Ld = lo + (size_t)z*DD*DD;
    int n0 = blockIdx.x*32, k0 = blockIdx.y*32;
    int x = threadIdx.x, y = threadIdx.y;
    #pragma unroll
    for (int i = 0; i < 32; i += 8) t[y+i][x] = S[(size_t)(k0+y+i)*DD + n0+x];
    __syncthreads();
    #pragma unroll
    for (int i = 0; i < 32; i += 8) {
        float v = t[x][y+i];
        __nv_bfloat16 h, lw;
        bsplit(v, h, lw);
        size_t off = (size_t)(n0+y+i)*DD + k0+x;
        Hd[off] = h; Ld[off] = lw;
    }
}

// ---------------- generic transpose+split ----------------
__global__ void tsplit_kernel(const float* __restrict__ src, int ldsrc, size_t srcStride,
                              __nv_bfloat16* __restrict__ hi, __nv_bfloat16* __restrict__ lo,
                              size_t dstStride, int K) {
    __shared__ float t[32][33];
    int l = blockIdx.z;
    const float* S = src + (size_t)l*srcStride;
    __nv_bfloat16* Hd = hi + (size_t)l*dstStride;
    __nv_bfloat16* Ld = lo + (size_t)l*dstStride;
    int n0 = blockIdx.x*32, k0 = blockIdx.y*32;
    int x = threadIdx.x, y = threadIdx.y;
    #pragma unroll
    for (int i = 0; i < 32; i += 8) t[y+i][x] = S[(size_t)(k0+y+i)*ldsrc + n0+x];
    __syncthreads();
    #pragma unroll
    for (int i = 0; i < 32; i += 8) {
        float v = t[x][y+i];
        __nv_bfloat16 h, lw;
        bsplit(v, h, lw);
        size_t off = (size_t)(n0+y+i)*K + k0+x;
        Hd[off] = h; Ld[off] = lw;
    }
}

// ---------------- W1 transpose+split (gate/value halves via z) ----------------
__global__ void tsplitW1_kernel(const float* __restrict__ W1,
                                __nv_bfloat16* __restrict__ hi, __nv_bfloat16* __restrict__ lo) {
    __shared__ float t[32][33];
    int z = blockIdx.z;                  // z = l*2 + half
    int l = z >> 1, half = z & 1;
    const float* S = W1 + (size_t)l*DD*2*FF + (size_t)half*FF;
    size_t doff = (size_t)l*2*FF*DD + (size_t)half*FF*DD;
    __nv_bfloat16* Hd = hi + doff;
    __nv_bfloat16* Ld = lo + doff;
    int n0 = blockIdx.x*32, k0 = blockIdx.y*32;
    int x = threadIdx.x, y = threadIdx.y;
    #pragma unroll
    for (int i = 0; i < 32; i += 8) t[y+i][x] = S[(size_t)(k0+y+i)*(2*FF) + n0+x];
    __syncthreads();
    #pragma unroll
    for (int i = 0; i < 32; i += 8) {
        float v = t[x][y+i];
        __nv_bfloat16 h, lw;
        bsplit(v, h, lw);
        size_t off = (size_t)(n0+y+i)*DD + k0+x;
        Hd[off] = h; Ld[off] = lw;
    }
}

// ---------------- split-bf16 HMMA GEMM ----------------
// C[M,N] = A[M,K] @ B^T.  MODE 0: +bias3 (QKV select) ; 1: +bias +res ;
//                         2: plain (gate) ; 3: OutH/L = split(silu(Gg)*acc) ; 4: +res
#define TILE_B 10240
#define STAGE_B 40960
#define HSMEM (2*STAGE_B)

__device__ __forceinline__ void load_stage(uint32_t sb,
        const __nv_bfloat16* Ah, const __nv_bfloat16* Al,
        const __nv_bfloat16* Bh, const __nv_bfloat16* Bl,
        int K, int kof, int tid) {
    #pragma unroll
    for (int i = 0; i < 2; i++) {
        int e = tid + i*256;              // 0..511
        int row = e >> 2, seg = e & 3;
        uint32_t off = (uint32_t)(row*80 + seg*16);
        size_t g = (size_t)row*K + kof + seg*8;
        cp16(sb + off,            Ah + g);
        cp16(sb + TILE_B + off,   Al + g);
        cp16(sb + 2*TILE_B + off, Bh + g);
        cp16(sb + 3*TILE_B + off, Bl + g);
    }
}

template<int MODE>
__global__ void __launch_bounds__(256, 2)
hgemm(const __nv_bfloat16* __restrict__ Ah, const __nv_bfloat16* __restrict__ Al,
      const __nv_bfloat16* __restrict__ Bh, const __nv_bfloat16* __restrict__ Bl,
      const float* __restrict__ bias, const float* __restrict__ bias2,
      const float* __restrict__ bias3,
      const float* __restrict__ Res, const float* __restrict__ Gg,
      float* __restrict__ C, __nv_bfloat16* __restrict__ OutH, __nv_bfloat16* __restrict__ OutL,
      int M, int N, int K) {
    extern __shared__ char dsm[];
    uint32_t sb = smem_to_u32(dsm);
    int tid = threadIdx.x, lane = tid & 31, wid = tid >> 5;
    int m0 = blockIdx.x * 128, n0 = blockIdx.y * 128;
    int wm = (wid & 1) * 64, wn = (wid >> 1) * 32;
    const __nv_bfloat16* Abh = Ah + (size_t)m0*K;
    const __nv_bfloat16* Abl = Al + (size_t)m0*K;
    const __nv_bfloat16* Bbh = Bh + (size_t)n0*K;
    const __nv_bfloat16* Bbl = Bl + (size_t)n0*K;
    int NC = K >> 5;

    load_stage(sb, Abh, Abl, Bbh, Bbl, K, 0, tid); CP_COMMIT();

    float acc[4][4][4];
    #pragma unroll
    for (int a = 0; a < 4; a++)
        #pragma unroll
        for (int b = 0; b < 4; b++)
            #pragma unroll
            for (int c = 0; c < 4; c++) acc[a][b][c] = 0.f;

    const int a_row = lane & 15;
    const int a_k   = (lane >> 4) * 8;
    const int b_row = (lane & 7) + ((lane >> 4) << 3);
    const int b_k   = ((lane >> 3) & 1) * 8;

    for (int i = 0; i < NC; i++) {
        CP_WAIT0();
        __syncthreads();
        if (i + 1 < NC) {
            load_stage(sb + (uint32_t)((i+1) & 1) * STAGE_B, Abh, Abl, Bbh, Bbl, K, (i+1)*32, tid);
            CP_COMMIT();
        }
        uint32_t st = sb + (uint32_t)(i & 1) * STAGE_B;
        #pragma unroll
        for (int kk = 0; kk < 32; kk += 16) {
            // staged fragment passes to keep register live-set < 128:
            // (1) ah,bh -> hi*hi   (2) +bl -> hi*lo   (3) +al (bl dead) -> lo*hi
            uint32_t ah[4][4], bh2[2][4];
            #pragma unroll
            for (int mt = 0; mt < 4; mt++) {
                uint32_t ad = st + (uint32_t)((wm + mt*16 + a_row)*80 + (kk + a_k)*2);
                LDSM4(ah[mt], ad);
            }
            #pragma unroll
            for (int np = 0; np < 2; np++) {
                uint32_t bd = st + 2*TILE_B + (uint32_t)((wn + np*16 + b_row)*80 + (kk + b_k)*2);
                LDSM4(bh2[np], bd);
            }
            #pragma unroll
            for (int mt = 0; mt < 4; mt++)
                #pragma unroll
                for (int nt = 0; nt < 4; nt++)
                    HMMA(acc[mt][nt], ah[mt], bh2[nt>>1][(nt&1)*2], bh2[nt>>1][(nt&1)*2+1]);
            {
                uint32_t bl2[2][4];
                #pragma unroll
                for (int np = 0; np < 2; np++) {
                    uint32_t bd = st + 3*TILE_B + (uint32_t)((wn + np*16 + b_row)*80 + (kk + b_k)*2);
                    LDSM4(bl2[np], bd);
                }
                #pragma unroll
                for (int mt = 0; mt < 4; mt++)
                    #pragma unroll
                    for (int nt = 0; nt < 4; nt++)
                        HMMA(acc[mt][nt], ah[mt], bl2[nt>>1][(nt&1)*2], bl2[nt>>1][(nt&1)*2+1]);
            }
            {
                uint32_t al[4][4];
                #pragma unroll
                for (int mt = 0; mt < 4; mt++) {
                    uint32_t ad = st + TILE_B + (uint32_t)((wm + mt*16 + a_row)*80 + (kk + a_k)*2);
                    LDSM4(al[mt], ad);
                }
                #pragma unroll
                for (int mt = 0; mt < 4; mt++)
                    #pragma unroll
                    for (int nt = 0; nt < 4; nt++)
                        HMMA(acc[mt][nt], al[mt], bh2[nt>>1][(nt&1)*2], bh2[nt>>1][(nt&1)*2+1]);
            }
        }
    }

    int gid = lane >> 2, ctg = lane & 3;
    #pragma unroll
    for (int mt = 0; mt < 4; mt++)
        #pragma unroll
        for (int nt = 0; nt < 4; nt++) {
            int r0 = m0 + wm + mt*16 + gid;
            int cc = n0 + wn + nt*8 + ctg*2;
            float2 v0 = make_float2(acc[mt][nt][0], acc[mt][nt][1]);
            float2 v1 = make_float2(acc[mt][nt][2], acc[mt][nt][3]);
            if (MODE == 0) {
                const float* bp = (cc < 512) ? (bias + cc)
                                : (cc < 1024) ? (bias2 + cc - 512) : (bias3 + cc - 1024);
                float2 bb = *(const float2*)bp;
                v0.x += bb.x; v0.y += bb.y; v1.x += bb.x; v1.y += bb.y;
            }
            if (MODE == 1) {
                float2 bb = *(const float2*)(bias + cc);
                v0.x += bb.x; v0.y += bb.y; v1.x += bb.x; v1.y += bb.y;
            }
            if (MODE == 1 || MODE == 4) {
                float2 ra = *(const float2*)(Res + (size_t)r0*N + cc);
                float2 rb = *(const float2*)(Res + (size_t)(r0+8)*N + cc);
                v0.x += ra.x; v0.y += ra.y; v1.x += rb.x; v1.y += rb.y;
            }
            if (MODE == 3) {
                float2 ga = *(const float2*)(Gg + (size_t)r0*N + cc);
                float2 gb = *(const float2*)(Gg + (size_t)(r0+8)*N + cc);
                float s0 = ga.x/(1.f+__expf(-ga.x))*v0.x;
                float s1 = ga.y/(1.f+__expf(-ga.y))*v0.y;
                float s2 = gb.x/(1.f+__expf(-gb.x))*v1.x;
                float s3 = gb.y/(1.f+__expf(-gb.y))*v1.y;
                __nv_bfloat16 h0,l0,h1,l1,h2,l2,h3,l3;
                bsplit(s0,h0,l0); bsplit(s1,h1,l1); bsplit(s2,h2,l2); bsplit(s3,h3,l3);
                *(__nv_bfloat162*)(OutH + (size_t)r0*N + cc)     = __nv_bfloat162(h0, h1);
                *(__nv_bfloat162*)(OutL + (size_t)r0*N + cc)     = __nv_bfloat162(l0, l1);
                *(__nv_bfloat162*)(OutH + (size_t)(r0+8)*N + cc) = __nv_bfloat162(h2, h3);
                *(__nv_bfloat162*)(OutL + (size_t)(r0+8)*N + cc) = __nv_bfloat162(l2, l3);
            } else {
                *(float2*)(C + (size_t)r0*N + cc) = v0;
                *(float2*)(C + (size_t)(r0+8)*N + cc) = v1;
            }
        }
}

// ---------------- context projection ----------------
__global__ void ctx_kernel(const float* __restrict__ fast, const float* __restrict__ slow,
                           const float* __restrict__ W, const float* __restrict__ bias,
                           float* __restrict__ out) {
    int b = blockIdx.x, d = threadIdx.x;
    float acc = bias[d];
    const float* fb = fast + b*DD;
    const float* sb = slow + b*DD;
    for (int k = 0; k < DD; k++) acc += fb[k] * W[(size_t)k*DD + d];
    for (int k = 0; k < DD; k++) acc += sb[k] * W[(size_t)(k+DD)*DD + d];
    out[b*DD + d] = acc;
}

// ---------------- embedding + context + engram + fused layer-0 rmsnorm-split ----------------
__global__ void embed_fused_kernel(const int* __restrict__ tokens, const int* __restrict__ prev,
                                   const float* __restrict__ embed, const float* __restrict__ ctxadd,
                                   const float* __restrict__ etab, const float* __restrict__ egate,
                                   const float* __restrict__ ln1,
                                   float* __restrict__ X,
                                   __nv_bfloat16* __restrict__ H, __nv_bfloat16* __restrict__ Lo) {
    int row = blockIdx.x;
    int b = row >> 9, t = row & 511;
    __shared__ unsigned int sidx[EH];
    int tid = threadIdx.x;
    if (tid < EH) {
        unsigned int xseed = 131u + (unsigned)tid * 1009u;
        unsigned int hs = 0u;
        #pragma unroll
        for (int i = 0; i < 4; i++) {
            unsigned int p = xseed; xseed = xseed * 31u + 1u;
            int pos = t - i;
            unsigned int tok = (pos >= 0) ? (unsigned)tokens[b*TT + pos]
                                          : (unsigned)prev[b*OVL + OVL + pos];
            hs += tok * p;
        }
        sidx[tid] = hs % MM;
    }
    __syncthreads();
    int d0 = tid * 4;
    int eh = tid >> 5;
    int jj = d0 & 127;
    int tok = tokens[b*TT + t];
    float4 ev = *(const float4*)(embed + (size_t)tok*DD + d0);
    float4 cv = *(const float4*)(ctxadd + b*DD + d0);
    float4 rv = *(const float4*)(etab + ((size_t)sidx[eh]*EH + eh)*EHD + jj);
    float4 gv = *(const float4*)(egate + eh*EHD + jj);
    float4 o;
    o.x = ev.x + cv.x + rv.x * (1.f/(1.f+__expf(-gv.x)));
    o.y = ev.y + cv.y + rv.y * (1.f/(1.f+__expf(-gv.y)));
    o.z = ev.z + cv.z + rv.z * (1.f/(1.f+__expf(-gv.z)));
    o.w = ev.w + cv.w + rv.w * (1.f/(1.f+__expf(-gv.w)));
    *(float4*)(X + (size_t)row*DD + d0) = o;
    float ss = blockReduceSum128(o.x*o.x + o.y*o.y + o.z*o.z + o.w*o.w);
    float inv = rsqrtf(ss * (1.f/DD) + 1e-6f);
    float4 sc = ((const float4*)ln1)[tid];
    float n0 = o.x*inv*sc.x, n1 = o.y*inv*sc.y, n2 = o.z*inv*sc.z, n3 = o.w*inv*sc.w;
    __nv_bfloat16 h[4], l[4];
    bsplit(n0, h[0], l[0]); bsplit(n1, h[1], l[1]);
    bsplit(n2, h[2], l[2]); bsplit(n3, h[3], l[3]);
    size_t off = (size_t)row*DD + d0;
    *(__nv_bfloat162*)(H + off)     = __nv_bfloat162(h[0], h[1]);
    *(__nv_bfloat162*)(H + off + 2) = __nv_bfloat162(h[2], h[3]);
    *(__nv_bfloat162*)(Lo + off)     = __nv_bfloat162(l[0], l[1]);
    *(__nv_bfloat162*)(Lo + off + 2) = __nv_bfloat162(l[2], l[3]);
}

// ---------------- RMSNorm -> split bf16 planes ----------------
__global__ void rmsnorm_split_kernel(const float* __restrict__ X, const float* __restrict__ scale,
                                     __nv_bfloat16* __restrict__ H, __nv_bfloat16* __restrict__ Lo) {
    int row = blockIdx.x;
    float4 v = ((const float4*)(X + (size_t)row*DD))[threadIdx.x];
    float ss = v.x*v.x + v.y*v.y + v.z*v.z + v.w*v.w;
    ss = blockReduceSum128(ss);
    float inv = rsqrtf(ss * (1.f/DD) + 1e-6f);
    float4 sc = ((const float4*)scale)[threadIdx.x];
    float o0 = v.x*inv*sc.x, o1 = v.y*inv*sc.y, o2 = v.z*inv*sc.z, o3 = v.w*inv*sc.w;
    __nv_bfloat16 h[4], l[4];
    bsplit(o0, h[0], l[0]); bsplit(o1, h[1], l[1]);
    bsplit(o2, h[2], l[2]); bsplit(o3, h[3], l[3]);
    size_t off = (size_t)row*DD + threadIdx.x*4;
    *(__nv_bfloat162*)(H + off)     = __nv_bfloat162(h[0], h[1]);
    *(__nv_bfloat162*)(H + off + 2) = __nv_bfloat162(h[2], h[3]);
    *(__nv_bfloat162*)(Lo + off)     = __nv_bfloat162(l[0], l[1]);
    *(__nv_bfloat162*)(Lo + off + 2) = __nv_bfloat162(l[2], l[3]);
}

// ---------------- final RMSNorm (fp32 out) ----------------
__global__ void rmsnorm_kernel(const float* __restrict__ X, const float* __restrict__ scale,
                               float* __restrict__ Out) {
    int row = blockIdx.x;
    float4 v = ((const float4*)(X + (size_t)row*DD))[threadIdx.x];
    float ss = v.x*v.x + v.y*v.y + v.z*v.z + v.w*v.w;
    ss = blockReduceSum128(ss);
    float inv = rsqrtf(ss * (1.f/DD) + 1e-6f);
    float4 sc = ((const float4*)scale)[threadIdx.x];
    float4 o;
    o.x = v.x*inv*sc.x; o.y = v.y*inv*sc.y; o.z = v.z*inv*sc.z; o.w = v.w*inv*sc.w;
    ((float4*)(Out + (size_t)row*DD))[threadIdx.x] = o;
}

// ---------------- rope helper: rotate float4 (two complex pairs) at (t, dv) ----------------
__device__ __forceinline__ float4 rope4(float4 v, int t, int dv) {
    const float c = 9.210340371976184f / 64.f;   // ln(10000)/64
    float inv0 = __expf(-(float)dv * c);         // 2j = dv
    float inv1 = __expf(-(float)(dv+2) * c);
    float s0, c0, s1, c1;
    __sincosf((float)t * inv0, &s0, &c0);
    __sincosf((float)t * inv1, &s1, &c1);
    float4 r;
    r.x = v.x*c0 - v.y*s0;  r.y = v.x*s0 + v.y*c0;
    r.z = v.z*c1 - v.w*s1;  r.w = v.z*s1 + v.w*c1;
    return r;
}

// ---------------- causal flash attention w/ fused RoPE: BQ=64, BK=64 ----------------
__global__ void __launch_bounds__(256) flash_kernel(const float* __restrict__ QKV,
        __nv_bfloat16* __restrict__ Oh, __nv_bfloat16* __restrict__ Ol) {
    extern __shared__ float fsm[];
    float (*qs)[68] = (float(*)[68])fsm;
    float (*ks)[68] = (float(*)[68])(fsm + 64*68);
    float (*vs)[68] = (float(*)[68])(fsm + 2*64*68);
    float (*ps)[68] = (float(*)[68])(fsm + 3*64*68);
    int bh = blockIdx.y;
    int b = bh >> 3, h = bh & 7;
    int q0 = blockIdx.x * 64;
    int tid = threadIdx.x;
    int tx = tid & 15, ty = tid >> 4;
    size_t base = ((size_t)b*TT)*1536 + h*HD;
    for (int i = tid; i < 64*16; i += 256) {
        int r = i >> 4, dv = (i & 15) * 4;
        float4 v = *(const float4*)(QKV + base + (size_t)(q0 + r)*1536 + dv);
        *(float4*)&qs[r][dv] = rope4(v, q0 + r, dv);
    }
    float m[4], l[4], o[4][4];
    #pragma unroll
    for (int i = 0; i < 4; i++) {
        m[i] = -1e30f; l[i] = 0.f;
        #pragma unroll
        for (int j = 0; j < 4; j++) o[i][j] = 0.f;
    }
    int r0 = ty*4, d0 = tx*4;
    int nkt = (q0 >> 6) + 1;
    const float scl = 0.125f;
    for (int kt = 0; kt < nkt; kt++) {
        int k0 = kt * 64;
        __syncthreads();
        for (int i = tid; i < 64*16; i += 256) {
            int r = i >> 4, dv = (i & 15)*4;
            size_t g = base + (size_t)(k0 + r)*1536 + dv;
            float4 kv = *(const float4*)(QKV + g + 512);
            *(float4*)&ks[r][dv] = rope4(kv, k0 + r, dv);
            *(float4*)&vs[r][dv] = *(const float4*)(QKV + g + 1024);
        }
        __syncthreads();
        float s[4][4];
        #pragma unroll
        for (int i = 0; i < 4; i++)
            #pragma unroll
            for (int j = 0; j < 4; j++) s[i][j] = 0.f;
        #pragma unroll 8
        for (int dd = 0; dd < 64; dd += 2) {
            float2 k2[4], q2[4];
            #pragma unroll
            for (int j = 0; j < 4; j++) k2[j] = *(const float2*)&ks[tx + 16*j][dd];
            #pragma unroll
            for (int i = 0; i < 4; i++) q2[i] = *(const float2*)&qs[r0 + i][dd];
            #pragma unroll
            for (int i = 0; i < 4; i++)
                #pragma unroll
                for (int j = 0; j < 4; j++)
                    s[i][j] += q2[i].x*k2[j].x + q2[i].y*k2[j].y;
        }
        bool diag = (kt == nkt - 1);
        float corr[4];
        #pragma unroll
        for (int i = 0; i < 4; i++) {
            int qq = q0 + r0 + i;
            #pragma unroll
            for (int j = 0; j < 4; j++) {
                int kk = k0 + tx + 16*j;
                s[i][j] = (!diag || kk <= qq) ? s[i][j]*scl : -1e9f;
            }
            float mx = fmaxf(fmaxf(s[i][0], s[i][1]), fmaxf(s[i][2], s[i][3]));
            #pragma unroll
            for (int off = 8; off; off >>= 1) mx = fmaxf(mx, __shfl_xor_sync(0xffffffffu, mx, off));
            float mn = fmaxf(m[i], mx);
            float c = __expf(m[i] - mn);
            m[i] = mn;
            float sum = 0.f;
            #pragma unroll
            for (int j = 0; j < 4; j++) {
                float p = __expf(s[i][j] - mn);
                ps[r0 + i][tx + 16*j] = p;
                sum += p;
            }
            #pragma unroll
            for (int off = 8; off; off >>= 1) sum += __shfl_xor_sync(0xffffffffu, sum, off);
            l[i] = l[i]*c + sum;
            corr[i] = c;
        }
        #pragma unroll
        for (int i = 0; i < 4; i++)
            #pragma unroll
            for (int j = 0; j < 4; j++) o[i][j] *= corr[i];
        __syncthreads();
        #pragma unroll 4
        for (int c = 0; c < 64; c++) {
            float4 v4 = *(const float4*)&vs[c][d0];
            #pragma unroll
            for (int i = 0; i < 4; i++) {
                float pv = ps[r0 + i][c];
                o[i][0] += pv*v4.x; o[i][1] += pv*v4.y;
                o[i][2] += pv*v4.z; o[i][3] += pv*v4.w;
            }
        }
    }
    #pragma unroll
    for (int i = 0; i < 4; i++) {
        float inv = 1.f / l[i];
        float v0 = o[i][0]*inv, v1 = o[i][1]*inv, v2 = o[i][2]*inv, v3 = o[i][3]*inv;
        __nv_bfloat16 hh[4], ll[4];
        bsplit(v0, hh[0], ll[0]); bsplit(v1, hh[1], ll[1]);
        bsplit(v2, hh[2], ll[2]); bsplit(v3, hh[3], ll[3]);
        size_t off = ((size_t)(b*TT + q0 + r0 + i))*DD + h*HD + d0;
        *(__nv_bfloat162*)(Oh + off)     = __nv_bfloat162(hh[0], hh[1]);
        *(__nv_bfloat162*)(Oh + off + 2) = __nv_bfloat162(hh[2], hh[3]);
        *(__nv_bfloat162*)(Ol + off)     = __nv_bfloat162(ll[0], ll[1]);
        *(__nv_bfloat162*)(Ol + off + 2) = __nv_bfloat162(ll[2], ll[3]);
    }
}

// ---------------- salience logits ----------------
__global__ void logits_kernel(const float* __restrict__ X, const float* __restrict__ sal_W,
                              const float* __restrict__ sal_b, const float* __restrict__ temp,
                              float* __restrict__ out) {
    int row = blockIdx.x;
    int e = threadIdx.x >> 5, lane = threadIdx.x & 31;
    const float* xr = X + (size_t)row*DD;
    float acc = 0.f;
    for (int d = lane; d < DD; d += 32)
        acc += xr[d] * sal_W[d*EH + e];
    acc = warpReduceSum(acc);
    if (lane == 0) {
        float tp = log1pf(expf(temp[e])) + 0.3f;
        out[(size_t)row*EH + e] = (acc + sal_b[e]) / tp;
    }
}

// ---------------- masked softmax pool ----------------
__global__ void pool_kernel(const int* __restrict__ tokens, const float* __restrict__ logits,
                            const float* __restrict__ X, const float* __restrict__ gate_W,
                            const float* __restrict__ gate_b,
                            float* __restrict__ wv_out, float* __restrict__ u_out) {
    int b = blockIdx.x >> 2, e = blockIdx.x & 3;
    int tid = threadIdx.x;
    __shared__ float ws[TT];
    float lg4[4]; int mv4[4];
    float lmax = -1e30f; float lvalid = 0.f;
    #pragma unroll
    for (int p = 0; p < 4; p++) {
        int t = tid + p*128;
        int mv = (tokens[b*TT + t] != 0);
        float lgv = logits[((size_t)b*TT + t)*EH + e];
        float sf = mv ? lgv : -1e9f;
        lg4[p] = sf; mv4[p] = mv;
        lmax = fmaxf(lmax, sf);
        lvalid += (float)mv;
    }
    float mx = blockReduceMax128(lmax);
    float lsum = 0.f;
    #pragma unroll
    for (int p = 0; p < 4; p++) {
        int t = tid + p*128;
        float ev = mv4[p] ? expf(lg4[p] - mx) : 0.f;
        ws[t] = ev;
        lsum += ev;
    }
    float ssum = blockReduceSum128(lsum);
    float nvalid = blockReduceSum128(lvalid);
    float wsc = 1.f / (ssum + 1e-6f);
    __syncthreads();
    float acc = 0.f;
    const float* xb = X + ((size_t)b*TT)*DD + e*EHD + tid;
    for (int t = 0; t < TT; t++)
        acc += ws[t] * xb[(size_t)t*DD];
    acc *= wsc;
    wv_out[b*DD + e*EHD + tid] = acc;
    float gsum = blockReduceSum128(acc * gate_W[tid]);
    if (tid == 0) {
        float gl = gsum + gate_b[0];
        float u = (nvalid > 0.f) ? 1.f/(1.f+expf(-gl)) : 0.f;
        u_out[b*EH + e] = u;
    }
}

// ---------------- fast/slow state update ----------------
__global__ void update_kernel(const float* __restrict__ wv, const float* __restrict__ u,
                              const float* __restrict__ sal_rms,
                              const float* __restrict__ fast, const float* __restrict__ slow,
                              float* __restrict__ out_fast, float* __restrict__ out_slow) {
    int b = blockIdx.x, tid = threadIdx.x;
    float4 v = ((const float4*)(wv + b*DD))[tid];
    float ss = blockReduceSum128(v.x*v.x + v.y*v.y + v.z*v.z + v.w*v.w);
    float inv = rsqrtf(ss * (1.f/DD) + 1e-6f);
    float4 sr = ((const float4*)sal_rms)[tid];
    int e = tid >> 5;
    float uu = u[b*EH + e];
    float4 f = ((const float4*)(fast + b*DD))[tid];
    float4 s = ((const float4*)(slow + b*DD))[tid];
    float4 wn;
    wn.x = v.x*inv*sr.x; wn.y = v.y*inv*sr.y; wn.z = v.z*inv*sr.z; wn.w = v.w*inv*sr.w;
    float4 nf, ns;
    nf.x = (1.f-uu)*f.x + uu*wn.x;  nf.y = (1.f-uu)*f.y + uu*wn.y;
    nf.z = (1.f-uu)*f.z + uu*wn.z;  nf.w = (1.f-uu)*f.w + uu*wn.w;
    float ud = 0.1f*uu;
    ns.x = (1.f-ud)*s.x + ud*wn.x;  ns.y = (1.f-ud)*s.y + ud*wn.y;
    ns.z = (1.f-ud)*s.z + ud*wn.z;  ns.w = (1.f-ud)*s.w + ud*wn.w;
    ((float4*)(out_fast + b*DD))[tid] = nf;
    ((float4*)(out_slow + b*DD))[tid] = ns;
}

// ---------------- launch ----------------
extern "C" void kernel_launch(void* const* d_in, const int* in_sizes, int n_in,
                              void* d_out, int out_size) {
    const int*   tokens = (const int*)  d_in[0];
    const int*   prev   = (const int*)  d_in[1];
    const float* fast   = (const float*)d_in[2];
    const float* slow   = (const float*)d_in[3];
    const float* embed  = (const float*)d_in[4];
    const float* ctx_W  = (const float*)d_in[5];
    const float* ctx_b  = (const float*)d_in[6];
    const float* etab   = (const float*)d_in[7];
    const float* egate  = (const float*)d_in[8];
    const float* ln1    = (const float*)d_in[9];
    const float* Wq     = (const float*)d_in[10];
    const float* bq     = (const float*)d_in[11];
    const float* Wk     = (const float*)d_in[12];
    const float* bk     = (const float*)d_in[13];
    const float* Wv     = (const float*)d_in[14];
    const float* bv     = (const float*)d_in[15];
    const float* Wo     = (const float*)d_in[16];
    const float* bo     = (const float*)d_in[17];
    const float* ln2    = (const float*)d_in[18];
    const float* W1     = (const float*)d_in[19];
    const float* W2     = (const float*)d_in[20];
    const float* ln_f   = (const float*)d_in[21];
    const float* sal_W  = (const float*)d_in[22];
    const float* sal_b  = (const float*)d_in[23];
    const float* temp   = (const float*)d_in[24];
    const float* gate_W = (const float*)d_in[25];
    const float* gate_b = (const float*)d_in[26];
    const float* sal_rms= (const float*)d_in[27];
    float* out = (float*)d_out;

    float *gx, *gqkv, *gffg, *gctx, *glog, *gwv, *gu;
    __nv_bfloat16 *nxh, *nxl, *ath, *atl, *ffh, *ffl;
    __nv_bfloat16 *wAh, *wAl, *w1h, *w1l, *w2h, *w2l;
    cudaGetSymbolAddress((void**)&gx,   g_x);
    cudaGetSymbolAddress((void**)&gqkv, g_qkv);
    cudaGetSymbolAddress((void**)&gffg, g_ffg);
    cudaGetSymbolAddress((void**)&gctx, g_ctx);
    cudaGetSymbolAddress((void**)&glog, g_logits);
    cudaGetSymbolAddress((void**)&gwv,  g_wv);
    cudaGetSymbolAddress((void**)&gu,   g_u);
    cudaGetSymbolAddress((void**)&nxh,  g_nxh);
    cudaGetSymbolAddress((void**)&nxl,  g_nxl);
    cudaGetSymbolAddress((void**)&ath,  g_ath);
    cudaGetSymbolAddress((void**)&atl,  g_atl);
    cudaGetSymbolAddress((void**)&ffh,  g_ffh);
    cudaGetSymbolAddress((void**)&ffl,  g_ffl);
    cudaGetSymbolAddress((void**)&wAh,  g_wqkvoh);
    cudaGetSymbolAddress((void**)&wAl,  g_wqkvol);
    cudaGetSymbolAddress((void**)&w1h,  g_w1h);
    cudaGetSymbolAddress((void**)&w1l,  g_w1l);
    cudaGetSymbolAddress((void**)&w2h,  g_w2h);
    cudaGetSymbolAddress((void**)&w2l,  g_w2l);

    cudaFuncSetAttribute(hgemm<0>, cudaFuncAttributeMaxDynamicSharedMemorySize, HSMEM);
    cudaFuncSetAttribute(hgemm<1>, cudaFuncAttributeMaxDynamicSharedMemorySize, HSMEM);
    cudaFuncSetAttribute(hgemm<2>, cudaFuncAttributeMaxDynamicSharedMemorySize, HSMEM);
    cudaFuncSetAttribute(hgemm<3>, cudaFuncAttributeMaxDynamicSharedMemorySize, HSMEM);
    cudaFuncSetAttribute(hgemm<4>, cudaFuncAttributeMaxDynamicSharedMemorySize, HSMEM);
    const int FSMEM = 4*64*68*4;   // 69632
    cudaFuncSetAttribute(flash_kernel, cudaFuncAttributeMaxDynamicSharedMemorySize, FSMEM);

    dim3 tb(32, 8);
    dim3 gD(NTOK/128, DD/128);         // 128 x 4
    dim3 gQKV(NTOK/128, (3*DD)/128);   // 128 x 12
    dim3 gF(NTOK/128, FF/128);         // 128 x 16

    // ncu captures launch #4 -> fused-QKV hgemm.
    tsplit4_kernel<<<dim3(DD/32, DD/32, 4*LL), tb>>>(Wq, Wk, Wv, Wo, wAh, wAl);          // 1
    ctx_kernel<<<BB, 512>>>(fast, slow, ctx_W, ctx_b, gctx);                             // 2
    embed_fused_kernel<<<NTOK, 128>>>(tokens, prev, embed, gctx, etab, egate, ln1,
                                      gx, nxh, nxl);                                     // 3

    for (int l = 0; l < LL; l++) {
        size_t wo  = (size_t)l*4*DD*DD;
        size_t w1o = (size_t)l*2*FF*DD;
        size_t w2o = (size_t)l*DD*FF;
        if (l > 0)
            rmsnorm_split_kernel<<<NTOK, 128>>>(gx, ln1 + l*DD, nxh, nxl);
        hgemm<0><<<gQKV, 256, HSMEM>>>(nxh, nxl, wAh + wo, wAl + wo,
                                       bq + l*DD, bk + l*DD, bv + l*DD,
                                       nullptr, nullptr, gqkv, nullptr, nullptr,
                                       NTOK, 3*DD, DD);
        if (l == 0) {
            tsplitW1_kernel<<<dim3(FF/32, DD/32, 2*LL), tb>>>(W1, w1h, w1l);
            tsplit_kernel<<<dim3(DD/32, FF/32, LL), tb>>>(W2, DD, (size_t)FF*DD, w2h, w2l, (size_t)DD*FF, FF);
        }
        flash_kernel<<<dim3(TT/64, BB*HH), 256, FSMEM>>>(gqkv, ath, atl);
        hgemm<1><<<gD, 256, HSMEM>>>(ath, atl, wAh + wo + (size_t)1536*DD, wAl + wo + (size_t)1536*DD,
                                     bo + l*DD, nullptr, nullptr, gx, nullptr,
                                     gx, nullptr, nullptr, NTOK, DD, DD);
        rmsnorm_split_kernel<<<NTOK, 128>>>(gx, ln2 + l*DD, nxh, nxl);
        hgemm<2><<<gF, 256, HSMEM>>>(nxh, nxl, w1h + w1o, w1l + w1o,
                                     nullptr, nullptr, nullptr, nullptr, nullptr,
                                     gffg, nullptr, nullptr, NTOK, FF, DD);
        hgemm<3><<<gF, 256, HSMEM>>>(nxh, nxl, w1h + w1o + (size_t)FF*DD, w1l + w1o + (size_t)FF*DD,
                                     nullptr, nullptr, nullptr, nullptr, gffg,
                                     nullptr, ffh, ffl, NTOK, FF, DD);
        hgemm<4><<<gD, 256, HSMEM>>>(ffh, ffl, w2h + w2o, w2l + w2o,
                                     nullptr, nullptr, nullptr, gx, nullptr,
                                     gx, nullptr, nullptr, NTOK, DD, FF);
    }
    rmsnorm_kernel<<<NTOK, 128>>>(gx, ln_f, out);
    logits_kernel<<<NTOK, 128>>>(out, sal_W, sal_b, temp, glog);
    pool_kernel<<<BB*EH, 128>>>(tokens, glog, out, gate_W, gate_b, gwv, gu);
    update_kernel<<<BB, 128>>>(gwv, gu, sal_rms, fast, slow,
                               out + (size_t)NTOK*DD,
                               out + (size_t)NTOK*DD + BB*DD);
}

// round 7
// speedup vs baseline: 2.6229x; 1.2594x over previous
#include <cuda_runtime.h>
#include <cuda_fp16.h>
#include <math.h>
#include <stdint.h>

// ---------------- problem constants ----------------
#define BB 32
#define TT 512
#define DD 512
#define LL 6
#define HH 8
#define HD 64
#define FF 2048      // 4*D
#define EH 4
#define EHD 128
#define MM 100000u
#define OVL 64
#define NTOK (BB*TT)   // 16384

// ---------------- scratch ----------------
__device__ float g_x[NTOK*DD];
__device__ float g_qkv[(size_t)NTOK*3*DD];
__device__ float g_ffg[(size_t)NTOK*FF];
__device__ float g_ctx[BB*DD];
__device__ float g_logits[NTOK*EH];
__device__ float g_wv[BB*DD];
__device__ float g_u[BB*EH];
// fp16 activations (single plane; weights carry the split)
__device__ __half g_nx[NTOK*DD];
__device__ __half g_at[NTOK*DD];
__device__ __half g_ff[(size_t)NTOK*FF];
// transposed + split weights: [N][K] fp16 hi/lo planes
__device__ __half g_wqkvoh[(size_t)LL*4*DD*DD];
__device__ __half g_wqkvol[(size_t)LL*4*DD*DD];
__device__ __half g_w1h[(size_t)LL*2*FF*DD];
__device__ __half g_w1l[(size_t)LL*2*FF*DD];
__device__ __half g_w2h[(size_t)LL*DD*FF];
__device__ __half g_w2l[(size_t)LL*DD*FF];

// ---------------- PTX helpers ----------------
__device__ __forceinline__ uint32_t smem_to_u32(const void* p) {
    uint32_t a;
    asm("{ .reg .u64 t; cvta.to.shared.u64 t, %1; cvt.u32.u64 %0, t; }" : "=r"(a) : "l"(p));
    return a;
}
__device__ __forceinline__ void cp16(uint32_t dst, const void* src) {
    asm volatile("cp.async.cg.shared.global [%0], [%1], 16;" :: "r"(dst), "l"(src));
}
#define CP_COMMIT() asm volatile("cp.async.commit_group;" ::: "memory")
#define CP_WAIT1()  asm volatile("cp.async.wait_group 1;" ::: "memory")

#define LDSM4(r, addr) \
    asm volatile("ldmatrix.sync.aligned.m8n8.x4.shared.b16 {%0,%1,%2,%3}, [%4];" \
        : "=r"((r)[0]), "=r"((r)[1]), "=r"((r)[2]), "=r"((r)[3]) : "r"(addr))

#define HMMA(c, a, b0, b1) \
    asm volatile("mma.sync.aligned.m16n8k16.row.col.f32.f16.f16.f32 " \
        "{%0,%1,%2,%3}, {%4,%5,%6,%7}, {%8,%9}, {%0,%1,%2,%3};" \
        : "+f"((c)[0]), "+f"((c)[1]), "+f"((c)[2]), "+f"((c)[3]) \
        : "r"((a)[0]), "r"((a)[1]), "r"((a)[2]), "r"((a)[3]), "r"(b0), "r"(b1))

__device__ __forceinline__ void hsplit(float x, __half& h, __half& l) {
    h = __float2half_rn(x);
    l = __float2half_rn(x - __half2float(h));
}

// ---------------- reduction helpers ----------------
__device__ __forceinline__ float warpReduceSum(float v) {
    #pragma unroll
    for (int o = 16; o; o >>= 1) v += __shfl_xor_sync(0xffffffffu, v, o);
    return v;
}
__device__ __forceinline__ float warpReduceMax(float v) {
    #pragma unroll
    for (int o = 16; o; o >>= 1) v = fmaxf(v, __shfl_xor_sync(0xffffffffu, v, o));
    return v;
}
__device__ __forceinline__ float blockReduceSum128(float v) {
    __shared__ float sm[4];
    __syncthreads();
    v = warpReduceSum(v);
    if ((threadIdx.x & 31) == 0) sm[threadIdx.x >> 5] = v;
    __syncthreads();
    return sm[0] + sm[1] + sm[2] + sm[3];
}
__device__ __forceinline__ float blockReduceMax128(float v) {
    __shared__ float sm[4];
    __syncthreads();
    v = warpReduceMax(v);
    if ((threadIdx.x & 31) == 0) sm[threadIdx.x >> 5] = v;
    __syncthreads();
    return fmaxf(fmaxf(sm[0], sm[1]), fmaxf(sm[2], sm[3]));
}

// ---------------- 4-source transpose+split fp16 (Wq/Wk/Wv/Wo stacked) ----------------
__global__ void tsplit4_kernel(const float* __restrict__ s0, const float* __restrict__ s1,
                               const float* __restrict__ s2, const float* __restrict__ s3,
                               __half* __restrict__ hi, __half* __restrict__ lo) {
    __shared__ float t[32][33];
    int z = blockIdx.z;                 // z = l*4 + sel
    int l = z >> 2, sel = z & 3;
    const float* S = (sel == 0 ? s0 : sel == 1 ? s1 : sel == 2 ? s2 : s3) + (size_t)l*DD*DD;
    __half* Hd = hi + (size_t)z*DD*DD;
    __half* Ld = lo + (size_t)z*DD*DD;
    int n0 = blockIdx.x*32, k0 = blockIdx.y*32;
    int x = threadIdx.x, y = threadIdx.y;
    #pragma unroll
    for (int i = 0; i < 32; i += 8) t[y+i][x] = S[(size_t)(k0+y+i)*DD + n0+x];
    __syncthreads();
    #pragma unroll
    for (int i = 0; i < 32; i += 8) {
        float v = t[x][y+i];
        __half h, lw;
        hsplit(v, h, lw);
        size_t off = (size_t)(n0+y+i)*DD + k0+x;
        Hd[off] = h; Ld[off] = lw;
    }
}

// ---------------- generic transpose+split fp16 ----------------
__global__ void tsplit_kernel(const float* __restrict__ src, int ldsrc, size_t srcStride,
                              __half* __restrict__ hi, __half* __restrict__ lo,
                              size_t dstStride, int K) {
    __shared__ float t[32][33];
    int l = blockIdx.z;
    const float* S = src + (size_t)l*srcStride;
    __half* Hd = hi + (size_t)l*dstStride;
    __half* Ld = lo + (size_t)l*dstStride;
    int n0 = blockIdx.x*32, k0 = blockIdx.y*32;
    int x = threadIdx.x, y = threadIdx.y;
    #pragma unroll
    for (int i = 0; i < 32; i += 8) t[y+i][x] = S[(size_t)(k0+y+i)*ldsrc + n0+x];
    __syncthreads();
    #pragma unroll
    for (int i = 0; i < 32; i += 8) {
        float v = t[x][y+i];
        __half h, lw;
        hsplit(v, h, lw);
        size_t off = (size_t)(n0+y+i)*K + k0+x;
        Hd[off] = h; Ld[off] = lw;
    }
}

// ---------------- W1 transpose+split fp16 (gate/value halves via z) ----------------
__global__ void tsplitW1_kernel(const float* __restrict__ W1,
                                __half* __restrict__ hi, __half* __restrict__ lo) {
    __shared__ float t[32][33];
    int z = blockIdx.z;                  // z = l*2 + half
    int l = z >> 1, half = z & 1;
    const float* S = W1 + (size_t)l*DD*2*FF + (size_t)half*FF;
    size_t doff = (size_t)l*2*FF*DD + (size_t)half*FF*DD;
    __half* Hd = hi + doff;
    __half* Ld = lo + doff;
    int n0 = blockIdx.x*32, k0 = blockIdx.y*32;
    int x = threadIdx.x, y = threadIdx.y;
    #pragma unroll
    for (int i = 0; i < 32; i += 8) t[y+i][x] = S[(size_t)(k0+y+i)*(2*FF) + n0+x];
    __syncthreads();
    #pragma unroll
    for (int i = 0; i < 32; i += 8) {
        float v = t[x][y+i];
        __half h, lw;
        hsplit(v, h, lw);
        size_t off = (size_t)(n0+y+i)*DD + k0+x;
        Hd[off] = h; Ld[off] = lw;
    }
}

// ---------------- fp16 HMMA GEMM (A rounded, W split hi/lo -> 2 passes) ----------------
// C[M,N] = A[M,K] @ B^T.  MODE 0: +bias3 (QKV select) ; 1: +bias +res ;
//                         2: plain (gate) ; 3: Out = half(silu(Gg)*acc) ; 4: +res
#define TILE_B 10240
#define STAGE_B 30720
#define HSMEM (3*STAGE_B)

__device__ __forceinline__ void load_stage(uint32_t sb,
        const __half* A, const __half* Bh, const __half* Bl,
        int K, int kof, int tid) {
    #pragma unroll
    for (int i = 0; i < 2; i++) {
        int e = tid + i*256;              // 0..511
        int row = e >> 2, seg = e & 3;
        uint32_t off = (uint32_t)(row*80 + seg*16);
        size_t g = (size_t)row*K + kof + seg*8;
        cp16(sb + off,            A  + g);
        cp16(sb + TILE_B + off,   Bh + g);
        cp16(sb + 2*TILE_B + off, Bl + g);
    }
}

template<int MODE>
__global__ void __launch_bounds__(256, 2)
hgemm(const __half* __restrict__ A,
      const __half* __restrict__ Bh, const __half* __restrict__ Bl,
      const float* __restrict__ bias, const float* __restrict__ bias2,
      const float* __restrict__ bias3,
      const float* __restrict__ Res, const float* __restrict__ Gg,
      float* __restrict__ C, __half* __restrict__ Out,
      int M, int N, int K) {
    extern __shared__ char dsm[];
    uint32_t sb = smem_to_u32(dsm);
    int tid = threadIdx.x, lane = tid & 31, wid = tid >> 5;
    int m0 = blockIdx.x * 128, n0 = blockIdx.y * 128;
    int wm = (wid & 1) * 64, wn = (wid >> 1) * 32;
    const __half* Ab  = A  + (size_t)m0*K;
    const __half* Bbh = Bh + (size_t)n0*K;
    const __half* Bbl = Bl + (size_t)n0*K;
    int NC = K >> 5;

    load_stage(sb,           Ab, Bbh, Bbl, K, 0,  tid); CP_COMMIT();
    load_stage(sb + STAGE_B, Ab, Bbh, Bbl, K, 32, tid); CP_COMMIT();

    float acc[4][4][4];
    #pragma unroll
    for (int a = 0; a < 4; a++)
        #pragma unroll
        for (int b = 0; b < 4; b++)
            #pragma unroll
            for (int c = 0; c < 4; c++) acc[a][b][c] = 0.f;

    const int a_row = lane & 15;
    const int a_k   = (lane >> 4) * 8;
    const int b_row = (lane & 7) + ((lane >> 4) << 3);
    const int b_k   = ((lane >> 3) & 1) * 8;

    uint32_t slot = 0;   // stage slot of chunk i
    for (int i = 0; i < NC; i++) {
        CP_WAIT1();
        __syncthreads();
        if (i + 2 < NC) {
            uint32_t wslot = slot + 2; if (wslot >= 3) wslot -= 3;
            load_stage(sb + wslot*STAGE_B, Ab, Bbh, Bbl, K, (i+2)*32, tid);
        }
        CP_COMMIT();
        uint32_t st = sb + slot*STAGE_B;
        #pragma unroll
        for (int kk = 0; kk < 32; kk += 16) {
            uint32_t a4[4][4], bh2[2][4], bl2[2][4];
            #pragma unroll
            for (int mt = 0; mt < 4; mt++) {
                uint32_t ad = st + (uint32_t)((wm + mt*16 + a_row)*80 + (kk + a_k)*2);
                LDSM4(a4[mt], ad);
            }
            #pragma unroll
            for (int np = 0; np < 2; np++) {
                uint32_t bd = st + TILE_B + (uint32_t)((wn + np*16 + b_row)*80 + (kk + b_k)*2);
                LDSM4(bh2[np], bd);
                LDSM4(bl2[np], bd + TILE_B);
            }
            #pragma unroll
            for (int mt = 0; mt < 4; mt++)
                #pragma unroll
                for (int nt = 0; nt < 4; nt++) {
                    HMMA(acc[mt][nt], a4[mt], bh2[nt>>1][(nt&1)*2], bh2[nt>>1][(nt&1)*2+1]);
                    HMMA(acc[mt][nt], a4[mt], bl2[nt>>1][(nt&1)*2], bl2[nt>>1][(nt&1)*2+1]);
                }
        }
        if (++slot == 3) slot = 0;
    }

    int gid = lane >> 2, ctg = lane & 3;
    #pragma unroll
    for (int mt = 0; mt < 4; mt++)
        #pragma unroll
        for (int nt = 0; nt < 4; nt++) {
            int r0 = m0 + wm + mt*16 + gid;
            int cc = n0 + wn + nt*8 + ctg*2;
            float2 v0 = make_float2(acc[mt][nt][0], acc[mt][nt][1]);
            float2 v1 = make_float2(acc[mt][nt][2], acc[mt][nt][3]);
            if (MODE == 0) {
                const float* bp = (cc < 512) ? (bias + cc)
                                : (cc < 1024) ? (bias2 + cc - 512) : (bias3 + cc - 1024);
                float2 bb = *(const float2*)bp;
                v0.x += bb.x; v0.y += bb.y; v1.x += bb.x; v1.y += bb.y;
            }
            if (MODE == 1) {
                float2 bb = *(const float2*)(bias + cc);
                v0.x += bb.x; v0.y += bb.y; v1.x += bb.x; v1.y += bb.y;
            }
            if (MODE == 1 || MODE == 4) {
                float2 ra = *(const float2*)(Res + (size_t)r0*N + cc);
                float2 rb = *(const float2*)(Res + (size_t)(r0+8)*N + cc);
                v0.x += ra.x; v0.y += ra.y; v1.x += rb.x; v1.y += rb.y;
            }
            if (MODE == 3) {
                float2 ga = *(const float2*)(Gg + (size_t)r0*N + cc);
                float2 gb = *(const float2*)(Gg + (size_t)(r0+8)*N + cc);
                float s0 = ga.x/(1.f+__expf(-ga.x))*v0.x;
                float s1 = ga.y/(1.f+__expf(-ga.y))*v0.y;
                float s2 = gb.x/(1.f+__expf(-gb.x))*v1.x;
                float s3 = gb.y/(1.f+__expf(-gb.y))*v1.y;
                *(__half2*)(Out + (size_t)r0*N + cc)     = __floats2half2_rn(s0, s1);
                *(__half2*)(Out + (size_t)(r0+8)*N + cc) = __floats2half2_rn(s2, s3);
            } else {
                *(float2*)(C + (size_t)r0*N + cc) = v0;
                *(float2*)(C + (size_t)(r0+8)*N + cc) = v1;
            }
        }
}

// ---------------- context projection ----------------
__global__ void ctx_kernel(const float* __restrict__ fast, const float* __restrict__ slow,
                           const float* __restrict__ W, const float* __restrict__ bias,
                           float* __restrict__ out) {
    int b = blockIdx.x, d = threadIdx.x;
    float acc = bias[d];
    const float* fb = fast + b*DD;
    const float* sb = slow + b*DD;
    for (int k = 0; k < DD; k++) acc += fb[k] * W[(size_t)k*DD + d];
    for (int k = 0; k < DD; k++) acc += sb[k] * W[(size_t)(k+DD)*DD + d];
    out[b*DD + d] = acc;
}

// ---------------- embedding + context + engram + fused layer-0 rmsnorm (fp16 out) ----------------
__global__ void embed_fused_kernel(const int* __restrict__ tokens, const int* __restrict__ prev,
                                   const float* __restrict__ embed, const float* __restrict__ ctxadd,
                                   const float* __restrict__ etab, const float* __restrict__ egate,
                                   const float* __restrict__ ln1,
                                   float* __restrict__ X, __half* __restrict__ H) {
    int row = blockIdx.x;
    int b = row >> 9, t = row & 511;
    __shared__ unsigned int sidx[EH];
    int tid = threadIdx.x;
    if (tid < EH) {
        unsigned int xseed = 131u + (unsigned)tid * 1009u;
        unsigned int hs = 0u;
        #pragma unroll
        for (int i = 0; i < 4; i++) {
            unsigned int p = xseed; xseed = xseed * 31u + 1u;
            int pos = t - i;
            unsigned int tok = (pos >= 0) ? (unsigned)tokens[b*TT + pos]
                                          : (unsigned)prev[b*OVL + OVL + pos];
            hs += tok * p;
        }
        sidx[tid] = hs % MM;
    }
    __syncthreads();
    int d0 = tid * 4;
    int eh = tid >> 5;
    int jj = d0 & 127;
    int tok = tokens[b*TT + t];
    float4 ev = *(const float4*)(embed + (size_t)tok*DD + d0);
    float4 cv = *(const float4*)(ctxadd + b*DD + d0);
    float4 rv = *(const float4*)(etab + ((size_t)sidx[eh]*EH + eh)*EHD + jj);
    float4 gv = *(const float4*)(egate + eh*EHD + jj);
    float4 o;
    o.x = ev.x + cv.x + rv.x * (1.f/(1.f+__expf(-gv.x)));
    o.y = ev.y + cv.y + rv.y * (1.f/(1.f+__expf(-gv.y)));
    o.z = ev.z + cv.z + rv.z * (1.f/(1.f+__expf(-gv.z)));
    o.w = ev.w + cv.w + rv.w * (1.f/(1.f+__expf(-gv.w)));
    *(float4*)(X + (size_t)row*DD + d0) = o;
    float ss = blockReduceSum128(o.x*o.x + o.y*o.y + o.z*o.z + o.w*o.w);
    float inv = rsqrtf(ss * (1.f/DD) + 1e-6f);
    float4 sc = ((const float4*)ln1)[tid];
    size_t off = (size_t)row*DD + d0;
    *(__half2*)(H + off)     = __floats2half2_rn(o.x*inv*sc.x, o.y*inv*sc.y);
    *(__half2*)(H + off + 2) = __floats2half2_rn(o.z*inv*sc.z, o.w*inv*sc.w);
}

// ---------------- RMSNorm -> fp16 plane ----------------
__global__ void rmsnorm_half_kernel(const float* __restrict__ X, const float* __restrict__ scale,
                                    __half* __restrict__ H) {
    int row = blockIdx.x;
    float4 v = ((const float4*)(X + (size_t)row*DD))[threadIdx.x];
    float ss = v.x*v.x + v.y*v.y + v.z*v.z + v.w*v.w;
    ss = blockReduceSum128(ss);
    float inv = rsqrtf(ss * (1.f/DD) + 1e-6f);
    float4 sc = ((const float4*)scale)[threadIdx.x];
    size_t off = (size_t)row*DD + threadIdx.x*4;
    *(__half2*)(H + off)     = __floats2half2_rn(v.x*inv*sc.x, v.y*inv*sc.y);
    *(__half2*)(H + off + 2) = __floats2half2_rn(v.z*inv*sc.z, v.w*inv*sc.w);
}

// ---------------- final RMSNorm (fp32 out) ----------------
__global__ void rmsnorm_kernel(const float* __restrict__ X, const float* __restrict__ scale,
                               float* __restrict__ Out) {
    int row = blockIdx.x;
    float4 v = ((const float4*)(X + (size_t)row*DD))[threadIdx.x];
    float ss = v.x*v.x + v.y*v.y + v.z*v.z + v.w*v.w;
    ss = blockReduceSum128(ss);
    float inv = rsqrtf(ss * (1.f/DD) + 1e-6f);
    float4 sc = ((const float4*)scale)[threadIdx.x];
    float4 o;
    o.x = v.x*inv*sc.x; o.y = v.y*inv*sc.y; o.z = v.z*inv*sc.z; o.w = v.w*inv*sc.w;
    ((float4*)(Out + (size_t)row*DD))[threadIdx.x] = o;
}

// ---------------- rope helper ----------------
__device__ __forceinline__ float4 rope4(float4 v, int t, int dv) {
    const float c = 9.210340371976184f / 64.f;
    float inv0 = __expf(-(float)dv * c);
    float inv1 = __expf(-(float)(dv+2) * c);
    float s0, c0, s1, c1;
    __sincosf((float)t * inv0, &s0, &c0);
    __sincosf((float)t * inv1, &s1, &c1);
    float4 r;
    r.x = v.x*c0 - v.y*s0;  r.y = v.x*s0 + v.y*c0;
    r.z = v.z*c1 - v.w*s1;  r.w = v.z*s1 + v.w*c1;
    return r;
}

// ---------------- causal flash attention w/ fused RoPE: BQ=64, BK=64, fp16 out ----------------
__global__ void __launch_bounds__(256) flash_kernel(const float* __restrict__ QKV,
        __half* __restrict__ Oh) {
    extern __shared__ float fsm[];
    float (*qs)[68] = (float(*)[68])fsm;
    float (*ks)[68] = (float(*)[68])(fsm + 64*68);
    float (*vs)[68] = (float(*)[68])(fsm + 2*64*68);
    float (*ps)[68] = (float(*)[68])(fsm + 3*64*68);
    int bh = blockIdx.y;
    int b = bh >> 3, h = bh & 7;
    int q0 = blockIdx.x * 64;
    int tid = threadIdx.x;
    int tx = tid & 15, ty = tid >> 4;
    size_t base = ((size_t)b*TT)*1536 + h*HD;
    for (int i = tid; i < 64*16; i += 256) {
        int r = i >> 4, dv = (i & 15) * 4;
        float4 v = *(const float4*)(QKV + base + (size_t)(q0 + r)*1536 + dv);
        *(float4*)&qs[r][dv] = rope4(v, q0 + r, dv);
    }
    float m[4], l[4], o[4][4];
    #pragma unroll
    for (int i = 0; i < 4; i++) {
        m[i] = -1e30f; l[i] = 0.f;
        #pragma unroll
        for (int j = 0; j < 4; j++) o[i][j] = 0.f;
    }
    int r0 = ty*4, d0 = tx*4;
    int nkt = (q0 >> 6) + 1;
    const float scl = 0.125f;
    for (int kt = 0; kt < nkt; kt++) {
        int k0 = kt * 64;
        __syncthreads();
        for (int i = tid; i < 64*16; i += 256) {
            int r = i >> 4, dv = (i & 15)*4;
            size_t g = base + (size_t)(k0 + r)*1536 + dv;
            float4 kv = *(const float4*)(QKV + g + 512);
            *(float4*)&ks[r][dv] = rope4(kv, k0 + r, dv);
            *(float4*)&vs[r][dv] = *(const float4*)(QKV + g + 1024);
        }
        __syncthreads();
        float s[4][4];
        #pragma unroll
        for (int i = 0; i < 4; i++)
            #pragma unroll
            for (int j = 0; j < 4; j++) s[i][j] = 0.f;
        #pragma unroll 8
        for (int dd = 0; dd < 64; dd += 2) {
            float2 k2[4], q2[4];
            #pragma unroll
            for (int j = 0; j < 4; j++) k2[j] = *(const float2*)&ks[tx + 16*j][dd];
            #pragma unroll
            for (int i = 0; i < 4; i++) q2[i] = *(const float2*)&qs[r0 + i][dd];
            #pragma unroll
            for (int i = 0; i < 4; i++)
                #pragma unroll
                for (int j = 0; j < 4; j++)
                    s[i][j] += q2[i].x*k2[j].x + q2[i].y*k2[j].y;
        }
        bool diag = (kt == nkt - 1);
        float corr[4];
        #pragma unroll
        for (int i = 0; i < 4; i++) {
            int qq = q0 + r0 + i;
            #pragma unroll
            for (int j = 0; j < 4; j++) {
                int kk = k0 + tx + 16*j;
                s[i][j] = (!diag || kk <= qq) ? s[i][j]*scl : -1e9f;
            }
            float mx = fmaxf(fmaxf(s[i][0], s[i][1]), fmaxf(s[i][2], s[i][3]));
            #pragma unroll
            for (int off = 8; off; off >>= 1) mx = fmaxf(mx, __shfl_xor_sync(0xffffffffu, mx, off));
            float mn = fmaxf(m[i], mx);
            float c = __expf(m[i] - mn);
            m[i] = mn;
            float sum = 0.f;
            #pragma unroll
            for (int j = 0; j < 4; j++) {
                float p = __expf(s[i][j] - mn);
                ps[r0 + i][tx + 16*j] = p;
                sum += p;
            }
            #pragma unroll
            for (int off = 8; off; off >>= 1) sum += __shfl_xor_sync(0xffffffffu, sum, off);
            l[i] = l[i]*c + sum;
            corr[i] = c;
        }
        #pragma unroll
        for (int i = 0; i < 4; i++)
            #pragma unroll
            for (int j = 0; j < 4; j++) o[i][j] *= corr[i];
        __syncthreads();
        #pragma unroll 4
        for (int c = 0; c < 64; c++) {
            float4 v4 = *(const float4*)&vs[c][d0];
            #pragma unroll
            for (int i = 0; i < 4; i++) {
                float pv = ps[r0 + i][c];
                o[i][0] += pv*v4.x; o[i][1] += pv*v4.y;
                o[i][2] += pv*v4.z; o[i][3] += pv*v4.w;
            }
        }
    }
    #pragma unroll
    for (int i = 0; i < 4; i++) {
        float inv = 1.f / l[i];
        size_t off = ((size_t)(b*TT + q0 + r0 + i))*DD + h*HD + d0;
        *(__half2*)(Oh + off)     = __floats2half2_rn(o[i][0]*inv, o[i][1]*inv);
        *(__half2*)(Oh + off + 2) = __floats2half2_rn(o[i][2]*inv, o[i][3]*inv);
    }
}

// ---------------- salience logits ----------------
__global__ void logits_kernel(const float* __restrict__ X, const float* __restrict__ sal_W,
                              const float* __restrict__ sal_b, const float* __restrict__ temp,
                              float* __restrict__ out) {
    int row = blockIdx.x;
    int e = threadIdx.x >> 5, lane = threadIdx.x & 31;
    const float* xr = X + (size_t)row*DD;
    float acc = 0.f;
    for (int d = lane; d < DD; d += 32)
        acc += xr[d] * sal_W[d*EH + e];
    acc = warpReduceSum(acc);
    if (lane == 0) {
        float tp = log1pf(expf(temp[e])) + 0.3f;
        out[(size_t)row*EH + e] = (acc + sal_b[e]) / tp;
    }
}

// ---------------- masked softmax pool ----------------
__global__ void pool_kernel(const int* __restrict__ tokens, const float* __restrict__ logits,
                            const float* __restrict__ X, const float* __restrict__ gate_W,
                            const float* __restrict__ gate_b,
                            float* __restrict__ wv_out, float* __restrict__ u_out) {
    int b = blockIdx.x >> 2, e = blockIdx.x & 3;
    int tid = threadIdx.x;
    __shared__ float ws[TT];
    float lg4[4]; int mv4[4];
    float lmax = -1e30f; float lvalid = 0.f;
    #pragma unroll
    for (int p = 0; p < 4; p++) {
        int t = tid + p*128;
        int mv = (tokens[b*TT + t] != 0);
        float lgv = logits[((size_t)b*TT + t)*EH + e];
        float sf = mv ? lgv : -1e9f;
        lg4[p] = sf; mv4[p] = mv;
        lmax = fmaxf(lmax, sf);
        lvalid += (float)mv;
    }
    float mx = blockReduceMax128(lmax);
    float lsum = 0.f;
    #pragma unroll
    for (int p = 0; p < 4; p++) {
        int t = tid + p*128;
        float ev = mv4[p] ? expf(lg4[p] - mx) : 0.f;
        ws[t] = ev;
        lsum += ev;
    }
    float ssum = blockReduceSum128(lsum);
    float nvalid = blockReduceSum128(lvalid);
    float wsc = 1.f / (ssum + 1e-6f);
    __syncthreads();
    float acc = 0.f;
    const float* xb = X + ((size_t)b*TT)*DD + e*EHD + tid;
    for (int t = 0; t < TT; t++)
        acc += ws[t] * xb[(size_t)t*DD];
    acc *= wsc;
    wv_out[b*DD + e*EHD + tid] = acc;
    float gsum = blockReduceSum128(acc * gate_W[tid]);
    if (tid == 0) {
        float gl = gsum + gate_b[0];
        float u = (nvalid > 0.f) ? 1.f/(1.f+expf(-gl)) : 0.f;
        u_out[b*EH + e] = u;
    }
}

// ---------------- fast/slow state update ----------------
__global__ void update_kernel(const float* __restrict__ wv, const float* __restrict__ u,
                              const float* __restrict__ sal_rms,
                              const float* __restrict__ fast, const float* __restrict__ slow,
                              float* __restrict__ out_fast, float* __restrict__ out_slow) {
    int b = blockIdx.x, tid = threadIdx.x;
    float4 v = ((const float4*)(wv + b*DD))[tid];
    float ss = blockReduceSum128(v.x*v.x + v.y*v.y + v.z*v.z + v.w*v.w);
    float inv = rsqrtf(ss * (1.f/DD) + 1e-6f);
    float4 sr = ((const float4*)sal_rms)[tid];
    int e = tid >> 5;
    float uu = u[b*EH + e];
    float4 f = ((const float4*)(fast + b*DD))[tid];
    float4 s = ((const float4*)(slow + b*DD))[tid];
    float4 wn;
    wn.x = v.x*inv*sr.x; wn.y = v.y*inv*sr.y; wn.z = v.z*inv*sr.z; wn.w = v.w*inv*sr.w;
    float4 nf, ns;
    nf.x = (1.f-uu)*f.x + uu*wn.x;  nf.y = (1.f-uu)*f.y + uu*wn.y;
    nf.z = (1.f-uu)*f.z + uu*wn.z;  nf.w = (1.f-uu)*f.w + uu*wn.w;
    float ud = 0.1f*uu;
    ns.x = (1.f-ud)*s.x + ud*wn.x;  ns.y = (1.f-ud)*s.y + ud*wn.y;
    ns.z = (1.f-ud)*s.z + ud*wn.z;  ns.w = (1.f-ud)*s.w + ud*wn.w;
    ((float4*)(out_fast + b*DD))[tid] = nf;
    ((float4*)(out_slow + b*DD))[tid] = ns;
}

// ---------------- launch ----------------
extern "C" void kernel_launch(void* const* d_in, const int* in_sizes, int n_in,
                              void* d_out, int out_size) {
    const int*   tokens = (const int*)  d_in[0];
    const int*   prev   = (const int*)  d_in[1];
    const float* fast   = (const float*)d_in[2];
    const float* slow   = (const float*)d_in[3];
    const float* embed  = (const float*)d_in[4];
    const float* ctx_W  = (const float*)d_in[5];
    const float* ctx_b  = (const float*)d_in[6];
    const float* etab   = (const float*)d_in[7];
    const float* egate  = (const float*)d_in[8];
    const float* ln1    = (const float*)d_in[9];
    const float* Wq     = (const float*)d_in[10];
    const float* bq     = (const float*)d_in[11];
    const float* Wk     = (const float*)d_in[12];
    const float* bk     = (const float*)d_in[13];
    const float* Wv     = (const float*)d_in[14];
    const float* bv     = (const float*)d_in[15];
    const float* Wo     = (const float*)d_in[16];
    const float* bo     = (const float*)d_in[17];
    const float* ln2    = (const float*)d_in[18];
    const float* W1     = (const float*)d_in[19];
    const float* W2     = (const float*)d_in[20];
    const float* ln_f   = (const float*)d_in[21];
    const float* sal_W  = (const float*)d_in[22];
    const float* sal_b  = (const float*)d_in[23];
    const float* temp   = (const float*)d_in[24];
    const float* gate_W = (const float*)d_in[25];
    const float* gate_b = (const float*)d_in[26];
    const float* sal_rms= (const float*)d_in[27];
    float* out = (float*)d_out;

    float *gx, *gqkv, *gffg, *gctx, *glog, *gwv, *gu;
    __half *nx, *at, *ff;
    __half *wAh, *wAl, *w1h, *w1l, *w2h, *w2l;
    cudaGetSymbolAddress((void**)&gx,   g_x);
    cudaGetSymbolAddress((void**)&gqkv, g_qkv);
    cudaGetSymbolAddress((void**)&gffg, g_ffg);
    cudaGetSymbolAddress((void**)&gctx, g_ctx);
    cudaGetSymbolAddress((void**)&glog, g_logits);
    cudaGetSymbolAddress((void**)&gwv,  g_wv);
    cudaGetSymbolAddress((void**)&gu,   g_u);
    cudaGetSymbolAddress((void**)&nx,   g_nx);
    cudaGetSymbolAddress((void**)&at,   g_at);
    cudaGetSymbolAddress((void**)&ff,   g_ff);
    cudaGetSymbolAddress((void**)&wAh,  g_wqkvoh);
    cudaGetSymbolAddress((void**)&wAl,  g_wqkvol);
    cudaGetSymbolAddress((void**)&w1h,  g_w1h);
    cudaGetSymbolAddress((void**)&w1l,  g_w1l);
    cudaGetSymbolAddress((void**)&w2h,  g_w2h);
    cudaGetSymbolAddress((void**)&w2l,  g_w2l);

    cudaFuncSetAttribute(hgemm<0>, cudaFuncAttributeMaxDynamicSharedMemorySize, HSMEM);
    cudaFuncSetAttribute(hgemm<1>, cudaFuncAttributeMaxDynamicSharedMemorySize, HSMEM);
    cudaFuncSetAttribute(hgemm<2>, cudaFuncAttributeMaxDynamicSharedMemorySize, HSMEM);
    cudaFuncSetAttribute(hgemm<3>, cudaFuncAttributeMaxDynamicSharedMemorySize, HSMEM);
    cudaFuncSetAttribute(hgemm<4>, cudaFuncAttributeMaxDynamicSharedMemorySize, HSMEM);
    const int FSMEM = 4*64*68*4;   // 69632
    cudaFuncSetAttribute(flash_kernel, cudaFuncAttributeMaxDynamicSharedMemorySize, FSMEM);

    dim3 tb(32, 8);
    dim3 gD(NTOK/128, DD/128);         // 128 x 4
    dim3 gQKV(NTOK/128, (3*DD)/128);   // 128 x 12
    dim3 gF(NTOK/128, FF/128);         // 128 x 16

    // ncu captures launch #4 -> fused-QKV hgemm.
    tsplit4_kernel<<<dim3(DD/32, DD/32, 4*LL), tb>>>(Wq, Wk, Wv, Wo, wAh, wAl);          // 1
    ctx_kernel<<<BB, 512>>>(fast, slow, ctx_W, ctx_b, gctx);                             // 2
    embed_fused_kernel<<<NTOK, 128>>>(tokens, prev, embed, gctx, etab, egate, ln1,
                                      gx, nx);                                           // 3

    for (int l = 0; l < LL; l++) {
        size_t wo  = (size_t)l*4*DD*DD;
        size_t w1o = (size_t)l*2*FF*DD;
        size_t w2o = (size_t)l*DD*FF;
        if (l > 0)
            rmsnorm_half_kernel<<<NTOK, 128>>>(gx, ln1 + l*DD, nx);
        hgemm<0><<<gQKV, 256, HSMEM>>>(nx, wAh + wo, wAl + wo,
                                       bq + l*DD, bk + l*DD, bv + l*DD,
                                       nullptr, nullptr, gqkv, nullptr,
                                       NTOK, 3*DD, DD);
        if (l == 0) {
            tsplitW1_kernel<<<dim3(FF/32, DD/32, 2*LL), tb>>>(W1, w1h, w1l);
            tsplit_kernel<<<dim3(DD/32, FF/32, LL), tb>>>(W2, DD, (size_t)FF*DD, w2h, w2l, (size_t)DD*FF, FF);
        }
        flash_kernel<<<dim3(TT/64, BB*HH), 256, FSMEM>>>(gqkv, at);
        hgemm<1><<<gD, 256, HSMEM>>>(at, wAh + wo + (size_t)1536*DD, wAl + wo + (size_t)1536*DD,
                                     bo + l*DD, nullptr, nullptr, gx, nullptr,
                                     gx, nullptr, NTOK, DD, DD);
        rmsnorm_half_kernel<<<NTOK, 128>>>(gx, ln2 + l*DD, nx);
        hgemm<2><<<gF, 256, HSMEM>>>(nx, w1h + w1o, w1l + w1o,
                                     nullptr, nullptr, nullptr, nullptr, nullptr,
                                     gffg, nullptr, NTOK, FF, DD);
        hgemm<3><<<gF, 256, HSMEM>>>(nx, w1h + w1o + (size_t)FF*DD, w1l + w1o + (size_t)FF*DD,
                                     nullptr, nullptr, nullptr, nullptr, gffg,
                                     nullptr, ff, NTOK, FF, DD);
        hgemm<4><<<gD, 256, HSMEM>>>(ff, w2h + w2o, w2l + w2o,
                                     nullptr, nullptr, nullptr, gx, nullptr,
                                     gx, nullptr, NTOK, DD, FF);
    }
    rmsnorm_kernel<<<NTOK, 128>>>(gx, ln_f, out);
    logits_kernel<<<NTOK, 128>>>(out, sal_W, sal_b, temp, glog);
    pool_kernel<<<BB*EH, 128>>>(tokens, glog, out, gate_W, gate_b, gwv, gu);
    update_kernel<<<BB, 128>>>(gwv, gu, sal_rms, fast, slow,
                               out + (size_t)NTOK*DD,
                               out + (size_t)NTOK*DD + BB*DD);
}

// round 8
// speedup vs baseline: 3.5153x; 1.3402x over previous
#include <cuda_runtime.h>
#include <cuda_fp16.h>
#include <math.h>
#include <stdint.h>

// ---------------- problem constants ----------------
#define BB 32
#define TT 512
#define DD 512
#define LL 6
#define HH 8
#define HD 64
#define FF 2048      // 4*D
#define EH 4
#define EHD 128
#define MM 100000u
#define OVL 64
#define NTOK (BB*TT)   // 16384

// ---------------- scratch ----------------
__device__ float g_x[NTOK*DD];
__device__ float g_qkv[(size_t)NTOK*3*DD];
__device__ float g_ffg[(size_t)NTOK*FF];
__device__ float g_ctx[BB*DD];
__device__ float g_logits[NTOK*EH];
__device__ float g_wv[BB*DD];
__device__ float g_u[BB*EH];
// fp16 activations (single plane)
__device__ __half g_nx[NTOK*DD];
__device__ __half g_at[NTOK*DD];
__device__ __half g_ff[(size_t)NTOK*FF];
// transposed fp16 weights: [N][K]
__device__ __half g_wqkvo[(size_t)LL*4*DD*DD];
__device__ __half g_w1[(size_t)LL*2*FF*DD];
__device__ __half g_w2[(size_t)LL*DD*FF];

// ---------------- PTX helpers ----------------
__device__ __forceinline__ uint32_t smem_to_u32(const void* p) {
    uint32_t a;
    asm("{ .reg .u64 t; cvta.to.shared.u64 t, %1; cvt.u32.u64 %0, t; }" : "=r"(a) : "l"(p));
    return a;
}
__device__ __forceinline__ void cp16(uint32_t dst, const void* src) {
    asm volatile("cp.async.cg.shared.global [%0], [%1], 16;" :: "r"(dst), "l"(src));
}
#define CP_COMMIT() asm volatile("cp.async.commit_group;" ::: "memory")
#define CP_WAIT2()  asm volatile("cp.async.wait_group 2;" ::: "memory")

#define LDSM4(r, addr) \
    asm volatile("ldmatrix.sync.aligned.m8n8.x4.shared.b16 {%0,%1,%2,%3}, [%4];" \
        : "=r"((r)[0]), "=r"((r)[1]), "=r"((r)[2]), "=r"((r)[3]) : "r"(addr))

#define HMMA(c, a, b0, b1) \
    asm volatile("mma.sync.aligned.m16n8k16.row.col.f32.f16.f16.f32 " \
        "{%0,%1,%2,%3}, {%4,%5,%6,%7}, {%8,%9}, {%0,%1,%2,%3};" \
        : "+f"((c)[0]), "+f"((c)[1]), "+f"((c)[2]), "+f"((c)[3]) \
        : "r"((a)[0]), "r"((a)[1]), "r"((a)[2]), "r"((a)[3]), "r"(b0), "r"(b1))

// ---------------- reduction helpers ----------------
__device__ __forceinline__ float warpReduceSum(float v) {
    #pragma unroll
    for (int o = 16; o; o >>= 1) v += __shfl_xor_sync(0xffffffffu, v, o);
    return v;
}
__device__ __forceinline__ float warpReduceMax(float v) {
    #pragma unroll
    for (int o = 16; o; o >>= 1) v = fmaxf(v, __shfl_xor_sync(0xffffffffu, v, o));
    return v;
}
__device__ __forceinline__ float blockReduceSum128(float v) {
    __shared__ float sm[4];
    __syncthreads();
    v = warpReduceSum(v);
    if ((threadIdx.x & 31) == 0) sm[threadIdx.x >> 5] = v;
    __syncthreads();
    return sm[0] + sm[1] + sm[2] + sm[3];
}
__device__ __forceinline__ float blockReduceMax128(float v) {
    __shared__ float sm[4];
    __syncthreads();
    v = warpReduceMax(v);
    if ((threadIdx.x & 31) == 0) sm[threadIdx.x >> 5] = v;
    __syncthreads();
    return fmaxf(fmaxf(sm[0], sm[1]), fmaxf(sm[2], sm[3]));
}

// ---------------- 4-source transpose to fp16 (Wq/Wk/Wv/Wo stacked) ----------------
__global__ void tsplit4_kernel(const float* __restrict__ s0, const float* __restrict__ s1,
                               const float* __restrict__ s2, const float* __restrict__ s3,
                               __half* __restrict__ dst) {
    __shared__ float t[32][33];
    int z = blockIdx.z;                 // z = l*4 + sel
    int l = z >> 2, sel = z & 3;
    const float* S = (sel == 0 ? s0 : sel == 1 ? s1 : sel == 2 ? s2 : s3) + (size_t)l*DD*DD;
    __half* Hd = dst + (size_t)z*DD*DD;
    int n0 = blockIdx.x*32, k0 = blockIdx.y*32;
    int x = threadIdx.x, y = threadIdx.y;
    #pragma unroll
    for (int i = 0; i < 32; i += 8) t[y+i][x] = S[(size_t)(k0+y+i)*DD + n0+x];
    __syncthreads();
    #pragma unroll
    for (int i = 0; i < 32; i += 8)
        Hd[(size_t)(n0+y+i)*DD + k0+x] = __float2half_rn(t[x][y+i]);
}

// ---------------- generic transpose to fp16 ----------------
__global__ void tsplit_kernel(const float* __restrict__ src, int ldsrc, size_t srcStride,
                              __half* __restrict__ dst, size_t dstStride, int K) {
    __shared__ float t[32][33];
    int l = blockIdx.z;
    const float* S = src + (size_t)l*srcStride;
    __half* Hd = dst + (size_t)l*dstStride;
    int n0 = blockIdx.x*32, k0 = blockIdx.y*32;
    int x = threadIdx.x, y = threadIdx.y;
    #pragma unroll
    for (int i = 0; i < 32; i += 8) t[y+i][x] = S[(size_t)(k0+y+i)*ldsrc + n0+x];
    __syncthreads();
    #pragma unroll
    for (int i = 0; i < 32; i += 8)
        Hd[(size_t)(n0+y+i)*K + k0+x] = __float2half_rn(t[x][y+i]);
}

// ---------------- W1 transpose to fp16 (gate/value halves via z) ----------------
__global__ void tsplitW1_kernel(const float* __restrict__ W1, __half* __restrict__ dst) {
    __shared__ float t[32][33];
    int z = blockIdx.z;                  // z = l*2 + half
    int l = z >> 1, half = z & 1;
    const float* S = W1 + (size_t)l*DD*2*FF + (size_t)half*FF;
    __half* Hd = dst + (size_t)l*2*FF*DD + (size_t)half*FF*DD;
    int n0 = blockIdx.x*32, k0 = blockIdx.y*32;
    int x = threadIdx.x, y = threadIdx.y;
    #pragma unroll
    for (int i = 0; i < 32; i += 8) t[y+i][x] = S[(size_t)(k0+y+i)*(2*FF) + n0+x];
    __syncthreads();
    #pragma unroll
    for (int i = 0; i < 32; i += 8)
        Hd[(size_t)(n0+y+i)*DD + k0+x] = __float2half_rn(t[x][y+i]);
}

// ---------------- fp16 HMMA GEMM (single pass, 4-stage cp.async) ----------------
// C[M,N] = A[M,K] @ B^T.  MODE 0: +bias3 (QKV select) ; 1: +bias +res ;
//                         2: plain (gate) ; 3: Out = half(silu(Gg)*acc) ; 4: +res
#define TILE_B 10240
#define STAGE_B 20480
#define HSMEM (4*STAGE_B)

__device__ __forceinline__ void load_stage(uint32_t sb,
        const __half* A, const __half* B, int K, int kof, int tid) {
    #pragma unroll
    for (int i = 0; i < 2; i++) {
        int e = tid + i*256;              // 0..511
        int row = e >> 2, seg = e & 3;
        uint32_t off = (uint32_t)(row*80 + seg*16);
        size_t g = (size_t)row*K + kof + seg*8;
        cp16(sb + off,          A + g);
        cp16(sb + TILE_B + off, B + g);
    }
}

template<int MODE>
__global__ void __launch_bounds__(256, 2)
hgemm(const __half* __restrict__ A, const __half* __restrict__ B,
      const float* __restrict__ bias, const float* __restrict__ bias2,
      const float* __restrict__ bias3,
      const float* __restrict__ Res, const float* __restrict__ Gg,
      float* __restrict__ C, __half* __restrict__ Out,
      int M, int N, int K) {
    extern __shared__ char dsm[];
    uint32_t sb = smem_to_u32(dsm);
    int tid = threadIdx.x, lane = tid & 31, wid = tid >> 5;
    int m0 = blockIdx.x * 128, n0 = blockIdx.y * 128;
    int wm = (wid & 1) * 64, wn = (wid >> 1) * 32;
    const __half* Ab = A + (size_t)m0*K;
    const __half* Bb = B + (size_t)n0*K;
    int NC = K >> 5;

    load_stage(sb,             Ab, Bb, K, 0,  tid); CP_COMMIT();
    load_stage(sb + STAGE_B,   Ab, Bb, K, 32, tid); CP_COMMIT();
    load_stage(sb + 2*STAGE_B, Ab, Bb, K, 64, tid); CP_COMMIT();

    float acc[4][4][4];
    #pragma unroll
    for (int a = 0; a < 4; a++)
        #pragma unroll
        for (int b = 0; b < 4; b++)
            #pragma unroll
            for (int c = 0; c < 4; c++) acc[a][b][c] = 0.f;

    const int a_row = lane & 15;
    const int a_k   = (lane >> 4) * 8;
    const int b_row = (lane & 7) + ((lane >> 4) << 3);
    const int b_k   = ((lane >> 3) & 1) * 8;

    for (int i = 0; i < NC; i++) {
        CP_WAIT2();
        __syncthreads();
        if (i + 3 < NC)
            load_stage(sb + (uint32_t)((i+3) & 3)*STAGE_B, Ab, Bb, K, (i+3)*32, tid);
        CP_COMMIT();
        uint32_t st = sb + (uint32_t)(i & 3)*STAGE_B;
        #pragma unroll
        for (int kk = 0; kk < 32; kk += 16) {
            uint32_t a4[4][4], b2[2][4];
            #pragma unroll
            for (int mt = 0; mt < 4; mt++) {
                uint32_t ad = st + (uint32_t)((wm + mt*16 + a_row)*80 + (kk + a_k)*2);
                LDSM4(a4[mt], ad);
            }
            #pragma unroll
            for (int np = 0; np < 2; np++) {
                uint32_t bd = st + TILE_B + (uint32_t)((wn + np*16 + b_row)*80 + (kk + b_k)*2);
                LDSM4(b2[np], bd);
            }
            #pragma unroll
            for (int mt = 0; mt < 4; mt++)
                #pragma unroll
                for (int nt = 0; nt < 4; nt++)
                    HMMA(acc[mt][nt], a4[mt], b2[nt>>1][(nt&1)*2], b2[nt>>1][(nt&1)*2+1]);
        }
    }

    int gid = lane >> 2, ctg = lane & 3;
    #pragma unroll
    for (int mt = 0; mt < 4; mt++)
        #pragma unroll
        for (int nt = 0; nt < 4; nt++) {
            int r0 = m0 + wm + mt*16 + gid;
            int cc = n0 + wn + nt*8 + ctg*2;
            float2 v0 = make_float2(acc[mt][nt][0], acc[mt][nt][1]);
            float2 v1 = make_float2(acc[mt][nt][2], acc[mt][nt][3]);
            if (MODE == 0) {
                const float* bp = (cc < 512) ? (bias + cc)
                                : (cc < 1024) ? (bias2 + cc - 512) : (bias3 + cc - 1024);
                float2 bb = *(const float2*)bp;
                v0.x += bb.x; v0.y += bb.y; v1.x += bb.x; v1.y += bb.y;
            }
            if (MODE == 1) {
                float2 bb = *(const float2*)(bias + cc);
                v0.x += bb.x; v0.y += bb.y; v1.x += bb.x; v1.y += bb.y;
            }
            if (MODE == 1 || MODE == 4) {
                float2 ra = *(const float2*)(Res + (size_t)r0*N + cc);
                float2 rb = *(const float2*)(Res + (size_t)(r0+8)*N + cc);
                v0.x += ra.x; v0.y += ra.y; v1.x += rb.x; v1.y += rb.y;
            }
            if (MODE == 3) {
                float2 ga = *(const float2*)(Gg + (size_t)r0*N + cc);
                float2 gb = *(const float2*)(Gg + (size_t)(r0+8)*N + cc);
                float s0 = ga.x/(1.f+__expf(-ga.x))*v0.x;
                float s1 = ga.y/(1.f+__expf(-ga.y))*v0.y;
                float s2 = gb.x/(1.f+__expf(-gb.x))*v1.x;
                float s3 = gb.y/(1.f+__expf(-gb.y))*v1.y;
                *(__half2*)(Out + (size_t)r0*N + cc)     = __floats2half2_rn(s0, s1);
                *(__half2*)(Out + (size_t)(r0+8)*N + cc) = __floats2half2_rn(s2, s3);
            } else {
                *(float2*)(C + (size_t)r0*N + cc) = v0;
                *(float2*)(C + (size_t)(r0+8)*N + cc) = v1;
            }
        }
}

// ---------------- context projection ----------------
__global__ void ctx_kernel(const float* __restrict__ fast, const float* __restrict__ slow,
                           const float* __restrict__ W, const float* __restrict__ bias,
                           float* __restrict__ out) {
    int b = blockIdx.x, d = threadIdx.x;
    float acc = bias[d];
    const float* fb = fast + b*DD;
    const float* sb = slow + b*DD;
    for (int k = 0; k < DD; k++) acc += fb[k] * W[(size_t)k*DD + d];
    for (int k = 0; k < DD; k++) acc += sb[k] * W[(size_t)(k+DD)*DD + d];
    out[b*DD + d] = acc;
}

// ---------------- embedding + context + engram + fused layer-0 rmsnorm (fp16 out) ----------------
__global__ void embed_fused_kernel(const int* __restrict__ tokens, const int* __restrict__ prev,
                                   const float* __restrict__ embed, const float* __restrict__ ctxadd,
                                   const float* __restrict__ etab, const float* __restrict__ egate,
                                   const float* __restrict__ ln1,
                                   float* __restrict__ X, __half* __restrict__ H) {
    int row = blockIdx.x;
    int b = row >> 9, t = row & 511;
    __shared__ unsigned int sidx[EH];
    int tid = threadIdx.x;
    if (tid < EH) {
        unsigned int xseed = 131u + (unsigned)tid * 1009u;
        unsigned int hs = 0u;
        #pragma unroll
        for (int i = 0; i < 4; i++) {
            unsigned int p = xseed; xseed = xseed * 31u + 1u;
            int pos = t - i;
            unsigned int tok = (pos >= 0) ? (unsigned)tokens[b*TT + pos]
                                          : (unsigned)prev[b*OVL + OVL + pos];
            hs += tok * p;
        }
        sidx[tid] = hs % MM;
    }
    __syncthreads();
    int d0 = tid * 4;
    int eh = tid >> 5;
    int jj = d0 & 127;
    int tok = tokens[b*TT + t];
    float4 ev = *(const float4*)(embed + (size_t)tok*DD + d0);
    float4 cv = *(const float4*)(ctxadd + b*DD + d0);
    float4 rv = *(const float4*)(etab + ((size_t)sidx[eh]*EH + eh)*EHD + jj);
    float4 gv = *(const float4*)(egate + eh*EHD + jj);
    float4 o;
    o.x = ev.x + cv.x + rv.x * (1.f/(1.f+__expf(-gv.x)));
    o.y = ev.y + cv.y + rv.y * (1.f/(1.f+__expf(-gv.y)));
    o.z = ev.z + cv.z + rv.z * (1.f/(1.f+__expf(-gv.z)));
    o.w = ev.w + cv.w + rv.w * (1.f/(1.f+__expf(-gv.w)));
    *(float4*)(X + (size_t)row*DD + d0) = o;
    float ss = blockReduceSum128(o.x*o.x + o.y*o.y + o.z*o.z + o.w*o.w);
    float inv = rsqrtf(ss * (1.f/DD) + 1e-6f);
    float4 sc = ((const float4*)ln1)[tid];
    size_t off = (size_t)row*DD + d0;
    *(__half2*)(H + off)     = __floats2half2_rn(o.x*inv*sc.x, o.y*inv*sc.y);
    *(__half2*)(H + off + 2) = __floats2half2_rn(o.z*inv*sc.z, o.w*inv*sc.w);
}

// ---------------- RMSNorm -> fp16 plane ----------------
__global__ void rmsnorm_half_kernel(const float* __restrict__ X, const float* __restrict__ scale,
                                    __half* __restrict__ H) {
    int row = blockIdx.x;
    float4 v = ((const float4*)(X + (size_t)row*DD))[threadIdx.x];
    float ss = v.x*v.x + v.y*v.y + v.z*v.z + v.w*v.w;
    ss = blockReduceSum128(ss);
    float inv = rsqrtf(ss * (1.f/DD) + 1e-6f);
    float4 sc = ((const float4*)scale)[threadIdx.x];
    size_t off = (size_t)row*DD + threadIdx.x*4;
    *(__half2*)(H + off)     = __floats2half2_rn(v.x*inv*sc.x, v.y*inv*sc.y);
    *(__half2*)(H + off + 2) = __floats2half2_rn(v.z*inv*sc.z, v.w*inv*sc.w);
}

// ---------------- final RMSNorm (fp32 out) ----------------
__global__ void rmsnorm_kernel(const float* __restrict__ X, const float* __restrict__ scale,
                               float* __restrict__ Out) {
    int row = blockIdx.x;
    float4 v = ((const float4*)(X + (size_t)row*DD))[threadIdx.x];
    float ss = v.x*v.x + v.y*v.y + v.z*v.z + v.w*v.w;
    ss = blockReduceSum128(ss);
    float inv = rsqrtf(ss * (1.f/DD) + 1e-6f);
    float4 sc = ((const float4*)scale)[threadIdx.x];
    float4 o;
    o.x = v.x*inv*sc.x; o.y = v.y*inv*sc.y; o.z = v.z*inv*sc.z; o.w = v.w*inv*sc.w;
    ((float4*)(Out + (size_t)row*DD))[threadIdx.x] = o;
}

// ---------------- rope helper ----------------
__device__ __forceinline__ float4 rope4(float4 v, int t, int dv) {
    const float c = 9.210340371976184f / 64.f;
    float inv0 = __expf(-(float)dv * c);
    float inv1 = __expf(-(float)(dv+2) * c);
    float s0, c0, s1, c1;
    __sincosf((float)t * inv0, &s0, &c0);
    __sincosf((float)t * inv1, &s1, &c1);
    float4 r;
    r.x = v.x*c0 - v.y*s0;  r.y = v.x*s0 + v.y*c0;
    r.z = v.z*c1 - v.w*s1;  r.w = v.z*s1 + v.w*c1;
    return r;
}

// ---------------- causal flash attention w/ fused RoPE: BQ=64, BK=64, fp16 out ----------------
__global__ void __launch_bounds__(256) flash_kernel(const float* __restrict__ QKV,
        __half* __restrict__ Oh) {
    extern __shared__ float fsm[];
    float (*qs)[68] = (float(*)[68])fsm;
    float (*ks)[68] = (float(*)[68])(fsm + 64*68);
    float (*vs)[68] = (float(*)[68])(fsm + 2*64*68);
    float (*ps)[68] = (float(*)[68])(fsm + 3*64*68);
    int bh = blockIdx.y;
    int b = bh >> 3, h = bh & 7;
    int q0 = blockIdx.x * 64;
    int tid = threadIdx.x;
    int tx = tid & 15, ty = tid >> 4;
    size_t base = ((size_t)b*TT)*1536 + h*HD;
    for (int i = tid; i < 64*16; i += 256) {
        int r = i >> 4, dv = (i & 15) * 4;
        float4 v = *(const float4*)(QKV + base + (size_t)(q0 + r)*1536 + dv);
        *(float4*)&qs[r][dv] = rope4(v, q0 + r, dv);
    }
    float m[4], l[4], o[4][4];
    #pragma unroll
    for (int i = 0; i < 4; i++) {
        m[i] = -1e30f; l[i] = 0.f;
        #pragma unroll
        for (int j = 0; j < 4; j++) o[i][j] = 0.f;
    }
    int r0 = ty*4, d0 = tx*4;
    int nkt = (q0 >> 6) + 1;
    const float scl = 0.125f;
    for (int kt = 0; kt < nkt; kt++) {
        int k0 = kt * 64;
        __syncthreads();
        for (int i = tid; i < 64*16; i += 256) {
            int r = i >> 4, dv = (i & 15)*4;
            size_t g = base + (size_t)(k0 + r)*1536 + dv;
            float4 kv = *(const float4*)(QKV + g + 512);
            *(float4*)&ks[r][dv] = rope4(kv, k0 + r, dv);
            *(float4*)&vs[r][dv] = *(const float4*)(QKV + g + 1024);
        }
        __syncthreads();
        float s[4][4];
        #pragma unroll
        for (int i = 0; i < 4; i++)
            #pragma unroll
            for (int j = 0; j < 4; j++) s[i][j] = 0.f;
        #pragma unroll 8
        for (int dd = 0; dd < 64; dd += 2) {
            float2 k2[4], q2[4];
            #pragma unroll
            for (int j = 0; j < 4; j++) k2[j] = *(const float2*)&ks[tx + 16*j][dd];
            #pragma unroll
            for (int i = 0; i < 4; i++) q2[i] = *(const float2*)&qs[r0 + i][dd];
            #pragma unroll
            for (int i = 0; i < 4; i++)
                #pragma unroll
                for (int j = 0; j < 4; j++)
                    s[i][j] += q2[i].x*k2[j].x + q2[i].y*k2[j].y;
        }
        bool diag = (kt == nkt - 1);
        float corr[4];
        #pragma unroll
        for (int i = 0; i < 4; i++) {
            int qq = q0 + r0 + i;
            #pragma unroll
            for (int j = 0; j < 4; j++) {
                int kk = k0 + tx + 16*j;
                s[i][j] = (!diag || kk <= qq) ? s[i][j]*scl : -1e9f;
            }
            float mx = fmaxf(fmaxf(s[i][0], s[i][1]), fmaxf(s[i][2], s[i][3]));
            #pragma unroll
            for (int off = 8; off; off >>= 1) mx = fmaxf(mx, __shfl_xor_sync(0xffffffffu, mx, off));
            float mn = fmaxf(m[i], mx);
            float c = __expf(m[i] - mn);
            m[i] = mn;
            float sum = 0.f;
            #pragma unroll
            for (int j = 0; j < 4; j++) {
                float p = __expf(s[i][j] - mn);
                ps[r0 + i][tx + 16*j] = p;
                sum += p;
            }
            #pragma unroll
            for (int off = 8; off; off >>= 1) sum += __shfl_xor_sync(0xffffffffu, sum, off);
            l[i] = l[i]*c + sum;
            corr[i] = c;
        }
        #pragma unroll
        for (int i = 0; i < 4; i++)
            #pragma unroll
            for (int j = 0; j < 4; j++) o[i][j] *= corr[i];
        __syncthreads();
        #pragma unroll 4
        for (int c = 0; c < 64; c++) {
            float4 v4 = *(const float4*)&vs[c][d0];
            #pragma unroll
            for (int i = 0; i < 4; i++) {
                float pv = ps[r0 + i][c];
                o[i][0] += pv*v4.x; o[i][1] += pv*v4.y;
                o[i][2] += pv*v4.z; o[i][3] += pv*v4.w;
            }
        }
    }
    #pragma unroll
    for (int i = 0; i < 4; i++) {
        float inv = 1.f / l[i];
        size_t off = ((size_t)(b*TT + q0 + r0 + i))*DD + h*HD + d0;
        *(__half2*)(Oh + off)     = __floats2half2_rn(o[i][0]*inv, o[i][1]*inv);
        *(__half2*)(Oh + off + 2) = __floats2half2_rn(o[i][2]*inv, o[i][3]*inv);
    }
}

// ---------------- salience logits ----------------
__global__ void logits_kernel(const float* __restrict__ X, const float* __restrict__ sal_W,
                              const float* __restrict__ sal_b, const float* __restrict__ temp,
                              float* __restrict__ out) {
    int row = blockIdx.x;
    int e = threadIdx.x >> 5, lane = threadIdx.x & 31;
    const float* xr = X + (size_t)row*DD;
    float acc = 0.f;
    for (int d = lane; d < DD; d += 32)
        acc += xr[d] * sal_W[d*EH + e];
    acc = warpReduceSum(acc);
    if (lane == 0) {
        float tp = log1pf(expf(temp[e])) + 0.3f;
        out[(size_t)row*EH + e] = (acc + sal_b[e]) / tp;
    }
}

// ---------------- masked softmax pool ----------------
__global__ void pool_kernel(const int* __restrict__ tokens, const float* __restrict__ logits,
                            const float* __restrict__ X, const float* __restrict__ gate_W,
                            const float* __restrict__ gate_b,
                            float* __restrict__ wv_out, float* __restrict__ u_out) {
    int b = blockIdx.x >> 2, e = blockIdx.x & 3;
    int tid = threadIdx.x;
    __shared__ float ws[TT];
    float lg4[4]; int mv4[4];
    float lmax = -1e30f; float lvalid = 0.f;
    #pragma unroll
    for (int p = 0; p < 4; p++) {
        int t = tid + p*128;
        int mv = (tokens[b*TT + t] != 0);
        float lgv = logits[((size_t)b*TT + t)*EH + e];
        float sf = mv ? lgv : -1e9f;
        lg4[p] = sf; mv4[p] = mv;
        lmax = fmaxf(lmax, sf);
        lvalid += (float)mv;
    }
    float mx = blockReduceMax128(lmax);
    float lsum = 0.f;
    #pragma unroll
    for (int p = 0; p < 4; p++) {
        int t = tid + p*128;
        float ev = mv4[p] ? expf(lg4[p] - mx) : 0.f;
        ws[t] = ev;
        lsum += ev;
    }
    float ssum = blockReduceSum128(lsum);
    float nvalid = blockReduceSum128(lvalid);
    float wsc = 1.f / (ssum + 1e-6f);
    __syncthreads();
    float acc = 0.f;
    const float* xb = X + ((size_t)b*TT)*DD + e*EHD + tid;
    for (int t = 0; t < TT; t++)
        acc += ws[t] * xb[(size_t)t*DD];
    acc *= wsc;
    wv_out[b*DD + e*EHD + tid] = acc;
    float gsum = blockReduceSum128(acc * gate_W[tid]);
    if (tid == 0) {
        float gl = gsum + gate_b[0];
        float u = (nvalid > 0.f) ? 1.f/(1.f+expf(-gl)) : 0.f;
        u_out[b*EH + e] = u;
    }
}

// ---------------- fast/slow state update ----------------
__global__ void update_kernel(const float* __restrict__ wv, const float* __restrict__ u,
                              const float* __restrict__ sal_rms,
                              const float* __restrict__ fast, const float* __restrict__ slow,
                              float* __restrict__ out_fast, float* __restrict__ out_slow) {
    int b = blockIdx.x, tid = threadIdx.x;
    float4 v = ((const float4*)(wv + b*DD))[tid];
    float ss = blockReduceSum128(v.x*v.x + v.y*v.y + v.z*v.z + v.w*v.w);
    float inv = rsqrtf(ss * (1.f/DD) + 1e-6f);
    float4 sr = ((const float4*)sal_rms)[tid];
    int e = tid >> 5;
    float uu = u[b*EH + e];
    float4 f = ((const float4*)(fast + b*DD))[tid];
    float4 s = ((const float4*)(slow + b*DD))[tid];
    float4 wn;
    wn.x = v.x*inv*sr.x; wn.y = v.y*inv*sr.y; wn.z = v.z*inv*sr.z; wn.w = v.w*inv*sr.w;
    float4 nf, ns;
    nf.x = (1.f-uu)*f.x + uu*wn.x;  nf.y = (1.f-uu)*f.y + uu*wn.y;
    nf.z = (1.f-uu)*f.z + uu*wn.z;  nf.w = (1.f-uu)*f.w + uu*wn.w;
    float ud = 0.1f*uu;
    ns.x = (1.f-ud)*s.x + ud*wn.x;  ns.y = (1.f-ud)*s.y + ud*wn.y;
    ns.z = (1.f-ud)*s.z + ud*wn.z;  ns.w = (1.f-ud)*s.w + ud*wn.w;
    ((float4*)(out_fast + b*DD))[tid] = nf;
    ((float4*)(out_slow + b*DD))[tid] = ns;
}

// ---------------- launch ----------------
extern "C" void kernel_launch(void* const* d_in, const int* in_sizes, int n_in,
                              void* d_out, int out_size) {
    const int*   tokens = (const int*)  d_in[0];
    const int*   prev   = (const int*)  d_in[1];
    const float* fast   = (const float*)d_in[2];
    const float* slow   = (const float*)d_in[3];
    const float* embed  = (const float*)d_in[4];
    const float* ctx_W  = (const float*)d_in[5];
    const float* ctx_b  = (const float*)d_in[6];
    const float* etab   = (const float*)d_in[7];
    const float* egate  = (const float*)d_in[8];
    const float* ln1    = (const float*)d_in[9];
    const float* Wq     = (const float*)d_in[10];
    const float* bq     = (const float*)d_in[11];
    const float* Wk     = (const float*)d_in[12];
    const float* bk     = (const float*)d_in[13];
    const float* Wv     = (const float*)d_in[14];
    const float* bv     = (const float*)d_in[15];
    const float* Wo     = (const float*)d_in[16];
    const float* bo     = (const float*)d_in[17];
    const float* ln2    = (const float*)d_in[18];
    const float* W1     = (const float*)d_in[19];
    const float* W2     = (const float*)d_in[20];
    const float* ln_f   = (const float*)d_in[21];
    const float* sal_W  = (const float*)d_in[22];
    const float* sal_b  = (const float*)d_in[23];
    const float* temp   = (const float*)d_in[24];
    const float* gate_W = (const float*)d_in[25];
    const float* gate_b = (const float*)d_in[26];
    const float* sal_rms= (const float*)d_in[27];
    float* out = (float*)d_out;

    float *gx, *gqkv, *gffg, *gctx, *glog, *gwv, *gu;
    __half *nx, *at, *ff;
    __half *wA, *w1, *w2;
    cudaGetSymbolAddress((void**)&gx,   g_x);
    cudaGetSymbolAddress((void**)&gqkv, g_qkv);
    cudaGetSymbolAddress((void**)&gffg, g_ffg);
    cudaGetSymbolAddress((void**)&gctx, g_ctx);
    cudaGetSymbolAddress((void**)&glog, g_logits);
    cudaGetSymbolAddress((void**)&gwv,  g_wv);
    cudaGetSymbolAddress((void**)&gu,   g_u);
    cudaGetSymbolAddress((void**)&nx,   g_nx);
    cudaGetSymbolAddress((void**)&at,   g_at);
    cudaGetSymbolAddress((void**)&ff,   g_ff);
    cudaGetSymbolAddress((void**)&wA,   g_wqkvo);
    cudaGetSymbolAddress((void**)&w1,   g_w1);
    cudaGetSymbolAddress((void**)&w2,   g_w2);

    cudaFuncSetAttribute(hgemm<0>, cudaFuncAttributeMaxDynamicSharedMemorySize, HSMEM);
    cudaFuncSetAttribute(hgemm<1>, cudaFuncAttributeMaxDynamicSharedMemorySize, HSMEM);
    cudaFuncSetAttribute(hgemm<2>, cudaFuncAttributeMaxDynamicSharedMemorySize, HSMEM);
    cudaFuncSetAttribute(hgemm<3>, cudaFuncAttributeMaxDynamicSharedMemorySize, HSMEM);
    cudaFuncSetAttribute(hgemm<4>, cudaFuncAttributeMaxDynamicSharedMemorySize, HSMEM);
    const int FSMEM = 4*64*68*4;   // 69632
    cudaFuncSetAttribute(flash_kernel, cudaFuncAttributeMaxDynamicSharedMemorySize, FSMEM);

    dim3 tb(32, 8);
    dim3 gD(NTOK/128, DD/128);         // 128 x 4
    dim3 gQKV(NTOK/128, (3*DD)/128);   // 128 x 12
    dim3 gF(NTOK/128, FF/128);         // 128 x 16

    // ncu captures launch #4 -> fused-QKV hgemm.
    tsplit4_kernel<<<dim3(DD/32, DD/32, 4*LL), tb>>>(Wq, Wk, Wv, Wo, wA);                // 1
    ctx_kernel<<<BB, 512>>>(fast, slow, ctx_W, ctx_b, gctx);                             // 2
    embed_fused_kernel<<<NTOK, 128>>>(tokens, prev, embed, gctx, etab, egate, ln1,
                                      gx, nx);                                           // 3

    for (int l = 0; l < LL; l++) {
        size_t wo  = (size_t)l*4*DD*DD;
        size_t w1o = (size_t)l*2*FF*DD;
        size_t w2o = (size_t)l*DD*FF;
        if (l > 0)
            rmsnorm_half_kernel<<<NTOK, 128>>>(gx, ln1 + l*DD, nx);
        hgemm<0><<<gQKV, 256, HSMEM>>>(nx, wA + wo,
                                       bq + l*DD, bk + l*DD, bv + l*DD,
                                       nullptr, nullptr, gqkv, nullptr,
                                       NTOK, 3*DD, DD);
        if (l == 0) {
            tsplitW1_kernel<<<dim3(FF/32, DD/32, 2*LL), tb>>>(W1, w1);
            tsplit_kernel<<<dim3(DD/32, FF/32, LL), tb>>>(W2, DD, (size_t)FF*DD, w2, (size_t)DD*FF, FF);
        }
        flash_kernel<<<dim3(TT/64, BB*HH), 256, FSMEM>>>(gqkv, at);
        hgemm<1><<<gD, 256, HSMEM>>>(at, wA + wo + (size_t)1536*DD,
                                     bo + l*DD, nullptr, nullptr, gx, nullptr,
                                     gx, nullptr, NTOK, DD, DD);
        rmsnorm_half_kernel<<<NTOK, 128>>>(gx, ln2 + l*DD, nx);
        hgemm<2><<<gF, 256, HSMEM>>>(nx, w1 + w1o,
                                     nullptr, nullptr, nullptr, nullptr, nullptr,
                                     gffg, nullptr, NTOK, FF, DD);
        hgemm<3><<<gF, 256, HSMEM>>>(nx, w1 + w1o + (size_t)FF*DD,
                                     nullptr, nullptr, nullptr, nullptr, gffg,
                                     nullptr, ff, NTOK, FF, DD);
        hgemm<4><<<gD, 256, HSMEM>>>(ff, w2 + w2o,
                                     nullptr, nullptr, nullptr, gx, nullptr,
                                     gx, nullptr, NTOK, DD, FF);
    }
    rmsnorm_kernel<<<NTOK, 128>>>(gx, ln_f, out);
    logits_kernel<<<NTOK, 128>>>(out, sal_W, sal_b, temp, glog);
    pool_kernel<<<BB*EH, 128>>>(tokens, glog, out, gate_W, gate_b, gwv, gu);
    update_kernel<<<BB, 128>>>(gwv, gu, sal_rms, fast, slow,
                               out + (size_t)NTOK*DD,
                               out + (size_t)NTOK*DD + BB*DD);
}

// round 9
// speedup vs baseline: 4.5299x; 1.2886x over previous
#include <cuda_runtime.h>
#include <cuda_fp16.h>
#include <math.h>
#include <stdint.h>

// ---------------- problem constants ----------------
#define BB 32
#define TT 512
#define DD 512
#define LL 6
#define HH 8
#define HD 64
#define FF 2048      // 4*D
#define EH 4
#define EHD 128
#define MM 100000u
#define OVL 64
#define NTOK (BB*TT)   // 16384

// ---------------- scratch ----------------
__device__ float g_x[NTOK*DD];
__device__ float g_qkv[(size_t)NTOK*3*DD];
__device__ float g_ffg[(size_t)NTOK*FF];
__device__ float g_ctx[BB*DD];
__device__ float g_logits[NTOK*EH];
__device__ float g_wv[BB*DD];
__device__ float g_u[BB*EH];
// fp16 activations (single plane)
__device__ __half g_nx[NTOK*DD];
__device__ __half g_at[NTOK*DD];
__device__ __half g_ff[(size_t)NTOK*FF];
// transposed fp16 weights: [N][K]
__device__ __half g_wqkvo[(size_t)LL*4*DD*DD];
__device__ __half g_w1[(size_t)LL*2*FF*DD];
__device__ __half g_w2[(size_t)LL*DD*FF];

// ---------------- PTX helpers ----------------
__device__ __forceinline__ uint32_t smem_to_u32(const void* p) {
    uint32_t a;
    asm("{ .reg .u64 t; cvta.to.shared.u64 t, %1; cvt.u32.u64 %0, t; }" : "=r"(a) : "l"(p));
    return a;
}
__device__ __forceinline__ void cp16(uint32_t dst, const void* src) {
    asm volatile("cp.async.cg.shared.global [%0], [%1], 16;" :: "r"(dst), "l"(src));
}
#define CP_COMMIT() asm volatile("cp.async.commit_group;" ::: "memory")
#define CP_WAIT2()  asm volatile("cp.async.wait_group 2;" ::: "memory")

#define LDSM4(r, addr) \
    asm volatile("ldmatrix.sync.aligned.m8n8.x4.shared.b16 {%0,%1,%2,%3}, [%4];" \
        : "=r"((r)[0]), "=r"((r)[1]), "=r"((r)[2]), "=r"((r)[3]) : "r"(addr))

#define HMMA(c, a, b0, b1) \
    asm volatile("mma.sync.aligned.m16n8k16.row.col.f32.f16.f16.f32 " \
        "{%0,%1,%2,%3}, {%4,%5,%6,%7}, {%8,%9}, {%0,%1,%2,%3};" \
        : "+f"((c)[0]), "+f"((c)[1]), "+f"((c)[2]), "+f"((c)[3]) \
        : "r"((a)[0]), "r"((a)[1]), "r"((a)[2]), "r"((a)[3]), "r"(b0), "r"(b1))

__device__ __forceinline__ uint32_t f22u(float a, float b) {
    __half2 h = __floats2half2_rn(a, b);
    return *(uint32_t*)&h;
}

// ---------------- reduction helpers ----------------
__device__ __forceinline__ float warpReduceSum(float v) {
    #pragma unroll
    for (int o = 16; o; o >>= 1) v += __shfl_xor_sync(0xffffffffu, v, o);
    return v;
}
__device__ __forceinline__ float warpReduceMax(float v) {
    #pragma unroll
    for (int o = 16; o; o >>= 1) v = fmaxf(v, __shfl_xor_sync(0xffffffffu, v, o));
    return v;
}
__device__ __forceinline__ float blockReduceSum128(float v) {
    __shared__ float sm[4];
    __syncthreads();
    v = warpReduceSum(v);
    if ((threadIdx.x & 31) == 0) sm[threadIdx.x >> 5] = v;
    __syncthreads();
    return sm[0] + sm[1] + sm[2] + sm[3];
}
__device__ __forceinline__ float blockReduceMax128(float v) {
    __shared__ float sm[4];
    __syncthreads();
    v = warpReduceMax(v);
    if ((threadIdx.x & 31) == 0) sm[threadIdx.x >> 5] = v;
    __syncthreads();
    return fmaxf(fmaxf(sm[0], sm[1]), fmaxf(sm[2], sm[3]));
}

// ---------------- 4-source transpose to fp16 (Wq/Wk/Wv/Wo stacked) ----------------
__global__ void tsplit4_kernel(const float* __restrict__ s0, const float* __restrict__ s1,
                               const float* __restrict__ s2, const float* __restrict__ s3,
                               __half* __restrict__ dst) {
    __shared__ float t[32][33];
    int z = blockIdx.z;
    int l = z >> 2, sel = z & 3;
    const float* S = (sel == 0 ? s0 : sel == 1 ? s1 : sel == 2 ? s2 : s3) + (size_t)l*DD*DD;
    __half* Hd = dst + (size_t)z*DD*DD;
    int n0 = blockIdx.x*32, k0 = blockIdx.y*32;
    int x = threadIdx.x, y = threadIdx.y;
    #pragma unroll
    for (int i = 0; i < 32; i += 8) t[y+i][x] = S[(size_t)(k0+y+i)*DD + n0+x];
    __syncthreads();
    #pragma unroll
    for (int i = 0; i < 32; i += 8)
        Hd[(size_t)(n0+y+i)*DD + k0+x] = __float2half_rn(t[x][y+i]);
}

// ---------------- generic transpose to fp16 ----------------
__global__ void tsplit_kernel(const float* __restrict__ src, int ldsrc, size_t srcStride,
                              __half* __restrict__ dst, size_t dstStride, int K) {
    __shared__ float t[32][33];
    int l = blockIdx.z;
    const float* S = src + (size_t)l*srcStride;
    __half* Hd = dst + (size_t)l*dstStride;
    int n0 = blockIdx.x*32, k0 = blockIdx.y*32;
    int x = threadIdx.x, y = threadIdx.y;
    #pragma unroll
    for (int i = 0; i < 32; i += 8) t[y+i][x] = S[(size_t)(k0+y+i)*ldsrc + n0+x];
    __syncthreads();
    #pragma unroll
    for (int i = 0; i < 32; i += 8)
        Hd[(size_t)(n0+y+i)*K + k0+x] = __float2half_rn(t[x][y+i]);
}

// ---------------- W1 transpose to fp16 ----------------
__global__ void tsplitW1_kernel(const float* __restrict__ W1, __half* __restrict__ dst) {
    __shared__ float t[32][33];
    int z = blockIdx.z;
    int l = z >> 1, half = z & 1;
    const float* S = W1 + (size_t)l*DD*2*FF + (size_t)half*FF;
    __half* Hd = dst + (size_t)l*2*FF*DD + (size_t)half*FF*DD;
    int n0 = blockIdx.x*32, k0 = blockIdx.y*32;
    int x = threadIdx.x, y = threadIdx.y;
    #pragma unroll
    for (int i = 0; i < 32; i += 8) t[y+i][x] = S[(size_t)(k0+y+i)*(2*FF) + n0+x];
    __syncthreads();
    #pragma unroll
    for (int i = 0; i < 32; i += 8)
        Hd[(size_t)(n0+y+i)*DD + k0+x] = __float2half_rn(t[x][y+i]);
}

// ---------------- fp16 HMMA GEMM (single pass, 4-stage cp.async) ----------------
#define TILE_B 10240
#define STAGE_B 20480
#define HSMEM (4*STAGE_B)

__device__ __forceinline__ void load_stage(uint32_t sb,
        const __half* A, const __half* B, int K, int kof, int tid) {
    #pragma unroll
    for (int i = 0; i < 2; i++) {
        int e = tid + i*256;
        int row = e >> 2, seg = e & 3;
        uint32_t off = (uint32_t)(row*80 + seg*16);
        size_t g = (size_t)row*K + kof + seg*8;
        cp16(sb + off,          A + g);
        cp16(sb + TILE_B + off, B + g);
    }
}

template<int MODE>
__global__ void __launch_bounds__(256, 2)
hgemm(const __half* __restrict__ A, const __half* __restrict__ B,
      const float* __restrict__ bias, const float* __restrict__ bias2,
      const float* __restrict__ bias3,
      const float* __restrict__ Res, const float* __restrict__ Gg,
      float* __restrict__ C, __half* __restrict__ Out,
      int M, int N, int K) {
    extern __shared__ char dsm[];
    uint32_t sb = smem_to_u32(dsm);
    int tid = threadIdx.x, lane = tid & 31, wid = tid >> 5;
    int m0 = blockIdx.x * 128, n0 = blockIdx.y * 128;
    int wm = (wid & 1) * 64, wn = (wid >> 1) * 32;
    const __half* Ab = A + (size_t)m0*K;
    const __half* Bb = B + (size_t)n0*K;
    int NC = K >> 5;

    load_stage(sb,             Ab, Bb, K, 0,  tid); CP_COMMIT();
    load_stage(sb + STAGE_B,   Ab, Bb, K, 32, tid); CP_COMMIT();
    load_stage(sb + 2*STAGE_B, Ab, Bb, K, 64, tid); CP_COMMIT();

    float acc[4][4][4];
    #pragma unroll
    for (int a = 0; a < 4; a++)
        #pragma unroll
        for (int b = 0; b < 4; b++)
            #pragma unroll
            for (int c = 0; c < 4; c++) acc[a][b][c] = 0.f;

    const int a_row = lane & 15;
    const int a_k   = (lane >> 4) * 8;
    const int b_row = (lane & 7) + ((lane >> 4) << 3);
    const int b_k   = ((lane >> 3) & 1) * 8;

    for (int i = 0; i < NC; i++) {
        CP_WAIT2();
        __syncthreads();
        if (i + 3 < NC)
            load_stage(sb + (uint32_t)((i+3) & 3)*STAGE_B, Ab, Bb, K, (i+3)*32, tid);
        CP_COMMIT();
        uint32_t st = sb + (uint32_t)(i & 3)*STAGE_B;
        #pragma unroll
        for (int kk = 0; kk < 32; kk += 16) {
            uint32_t a4[4][4], b2[2][4];
            #pragma unroll
            for (int mt = 0; mt < 4; mt++) {
                uint32_t ad = st + (uint32_t)((wm + mt*16 + a_row)*80 + (kk + a_k)*2);
                LDSM4(a4[mt], ad);
            }
            #pragma unroll
            for (int np = 0; np < 2; np++) {
                uint32_t bd = st + TILE_B + (uint32_t)((wn + np*16 + b_row)*80 + (kk + b_k)*2);
                LDSM4(b2[np], bd);
            }
            #pragma unroll
            for (int mt = 0; mt < 4; mt++)
                #pragma unroll
                for (int nt = 0; nt < 4; nt++)
                    HMMA(acc[mt][nt], a4[mt], b2[nt>>1][(nt&1)*2], b2[nt>>1][(nt&1)*2+1]);
        }
    }

    int gid = lane >> 2, ctg = lane & 3;
    #pragma unroll
    for (int mt = 0; mt < 4; mt++)
        #pragma unroll
        for (int nt = 0; nt < 4; nt++) {
            int r0 = m0 + wm + mt*16 + gid;
            int cc = n0 + wn + nt*8 + ctg*2;
            float2 v0 = make_float2(acc[mt][nt][0], acc[mt][nt][1]);
            float2 v1 = make_float2(acc[mt][nt][2], acc[mt][nt][3]);
            if (MODE == 0) {
                const float* bp = (cc < 512) ? (bias + cc)
                                : (cc < 1024) ? (bias2 + cc - 512) : (bias3 + cc - 1024);
                float2 bb = *(const float2*)bp;
                v0.x += bb.x; v0.y += bb.y; v1.x += bb.x; v1.y += bb.y;
            }
            if (MODE == 1) {
                float2 bb = *(const float2*)(bias + cc);
                v0.x += bb.x; v0.y += bb.y; v1.x += bb.x; v1.y += bb.y;
            }
            if (MODE == 1 || MODE == 4) {
                float2 ra = *(const float2*)(Res + (size_t)r0*N + cc);
                float2 rb = *(const float2*)(Res + (size_t)(r0+8)*N + cc);
                v0.x += ra.x; v0.y += ra.y; v1.x += rb.x; v1.y += rb.y;
            }
            if (MODE == 3) {
                float2 ga = *(const float2*)(Gg + (size_t)r0*N + cc);
                float2 gb = *(const float2*)(Gg + (size_t)(r0+8)*N + cc);
                float s0 = ga.x/(1.f+__expf(-ga.x))*v0.x;
                float s1 = ga.y/(1.f+__expf(-ga.y))*v0.y;
                float s2 = gb.x/(1.f+__expf(-gb.x))*v1.x;
                float s3 = gb.y/(1.f+__expf(-gb.y))*v1.y;
                *(__half2*)(Out + (size_t)r0*N + cc)     = __floats2half2_rn(s0, s1);
                *(__half2*)(Out + (size_t)(r0+8)*N + cc) = __floats2half2_rn(s2, s3);
            } else {
                *(float2*)(C + (size_t)r0*N + cc) = v0;
                *(float2*)(C + (size_t)(r0+8)*N + cc) = v1;
            }
        }
}

// ---------------- context projection ----------------
__global__ void ctx_kernel(const float* __restrict__ fast, const float* __restrict__ slow,
                           const float* __restrict__ W, const float* __restrict__ bias,
                           float* __restrict__ out) {
    int b = blockIdx.x, d = threadIdx.x;
    float acc = bias[d];
    const float* fb = fast + b*DD;
    const float* sb = slow + b*DD;
    for (int k = 0; k < DD; k++) acc += fb[k] * W[(size_t)k*DD + d];
    for (int k = 0; k < DD; k++) acc += sb[k] * W[(size_t)(k+DD)*DD + d];
    out[b*DD + d] = acc;
}

// ---------------- embedding + context + engram + fused layer-0 rmsnorm ----------------
__global__ void embed_fused_kernel(const int* __restrict__ tokens, const int* __restrict__ prev,
                                   const float* __restrict__ embed, const float* __restrict__ ctxadd,
                                   const float* __restrict__ etab, const float* __restrict__ egate,
                                   const float* __restrict__ ln1,
                                   float* __restrict__ X, __half* __restrict__ H) {
    int row = blockIdx.x;
    int b = row >> 9, t = row & 511;
    __shared__ unsigned int sidx[EH];
    int tid = threadIdx.x;
    if (tid < EH) {
        unsigned int xseed = 131u + (unsigned)tid * 1009u;
        unsigned int hs = 0u;
        #pragma unroll
        for (int i = 0; i < 4; i++) {
            unsigned int p = xseed; xseed = xseed * 31u + 1u;
            int pos = t - i;
            unsigned int tok = (pos >= 0) ? (unsigned)tokens[b*TT + pos]
                                          : (unsigned)prev[b*OVL + OVL + pos];
            hs += tok * p;
        }
        sidx[tid] = hs % MM;
    }
    __syncthreads();
    int d0 = tid * 4;
    int eh = tid >> 5;
    int jj = d0 & 127;
    int tok = tokens[b*TT + t];
    float4 ev = *(const float4*)(embed + (size_t)tok*DD + d0);
    float4 cv = *(const float4*)(ctxadd + b*DD + d0);
    float4 rv = *(const float4*)(etab + ((size_t)sidx[eh]*EH + eh)*EHD + jj);
    float4 gv = *(const float4*)(egate + eh*EHD + jj);
    float4 o;
    o.x = ev.x + cv.x + rv.x * (1.f/(1.f+__expf(-gv.x)));
    o.y = ev.y + cv.y + rv.y * (1.f/(1.f+__expf(-gv.y)));
    o.z = ev.z + cv.z + rv.z * (1.f/(1.f+__expf(-gv.z)));
    o.w = ev.w + cv.w + rv.w * (1.f/(1.f+__expf(-gv.w)));
    *(float4*)(X + (size_t)row*DD + d0) = o;
    float ss = blockReduceSum128(o.x*o.x + o.y*o.y + o.z*o.z + o.w*o.w);
    float inv = rsqrtf(ss * (1.f/DD) + 1e-6f);
    float4 sc = ((const float4*)ln1)[tid];
    size_t off = (size_t)row*DD + d0;
    *(__half2*)(H + off)     = __floats2half2_rn(o.x*inv*sc.x, o.y*inv*sc.y);
    *(__half2*)(H + off + 2) = __floats2half2_rn(o.z*inv*sc.z, o.w*inv*sc.w);
}

// ---------------- RMSNorm -> fp16 plane ----------------
__global__ void rmsnorm_half_kernel(const float* __restrict__ X, const float* __restrict__ scale,
                                    __half* __restrict__ H) {
    int row = blockIdx.x;
    float4 v = ((const float4*)(X + (size_t)row*DD))[threadIdx.x];
    float ss = v.x*v.x + v.y*v.y + v.z*v.z + v.w*v.w;
    ss = blockReduceSum128(ss);
    float inv = rsqrtf(ss * (1.f/DD) + 1e-6f);
    float4 sc = ((const float4*)scale)[threadIdx.x];
    size_t off = (size_t)row*DD + threadIdx.x*4;
    *(__half2*)(H + off)     = __floats2half2_rn(v.x*inv*sc.x, v.y*inv*sc.y);
    *(__half2*)(H + off + 2) = __floats2half2_rn(v.z*inv*sc.z, v.w*inv*sc.w);
}

// ---------------- final RMSNorm (fp32 out) ----------------
__global__ void rmsnorm_kernel(const float* __restrict__ X, const float* __restrict__ scale,
                               float* __restrict__ Out) {
    int row = blockIdx.x;
    float4 v = ((const float4*)(X + (size_t)row*DD))[threadIdx.x];
    float ss = v.x*v.x + v.y*v.y + v.z*v.z + v.w*v.w;
    ss = blockReduceSum128(ss);
    float inv = rsqrtf(ss * (1.f/DD) + 1e-6f);
    float4 sc = ((const float4*)scale)[threadIdx.x];
    float4 o;
    o.x = v.x*inv*sc.x; o.y = v.y*inv*sc.y; o.z = v.z*inv*sc.z; o.w = v.w*inv*sc.w;
    ((float4*)(Out + (size_t)row*DD))[threadIdx.x] = o;
}

// ---------------- rope helper ----------------
__device__ __forceinline__ float4 rope4(float4 v, int t, int dv) {
    const float c = 9.210340371976184f / 64.f;
    float inv0 = __expf(-(float)dv * c);
    float inv1 = __expf(-(float)(dv+2) * c);
    float s0, c0, s1, c1;
    __sincosf((float)t * inv0, &s0, &c0);
    __sincosf((float)t * inv1, &s1, &c1);
    float4 r;
    r.x = v.x*c0 - v.y*s0;  r.y = v.x*s0 + v.y*c0;
    r.z = v.z*c1 - v.w*s1;  r.w = v.z*s1 + v.w*c1;
    return r;
}

// ---------------- HMMA causal flash attention: BQ=64, BK=64, HD=64, 256 threads ----------------
// smem: Qh[64][72]h, Kh[64][72]h, Vt[64][72]h (row=hd,col=k), smax[2][64]f, ssum[2][64]f, obuf[64][64]f
#define FPAD 72
#define FSMEM (3*64*FPAD*2 + 2*128*4 + 64*64*4)   // 27648 + 1024 + 16384 = 45056

__global__ void __launch_bounds__(256) flash_kernel(const float* __restrict__ QKV,
        __half* __restrict__ Oh) {
    extern __shared__ char fsm[];
    __half* Qh = (__half*)fsm;
    __half* Kh = Qh + 64*FPAD;
    __half* Vt = Kh + 64*FPAD;
    float* smax = (float*)(Vt + 64*FPAD);
    float* ssum = smax + 128;
    float* obuf = ssum + 128;
    uint32_t uq = smem_to_u32(Qh);
    uint32_t uk = smem_to_u32(Kh);
    uint32_t uv = smem_to_u32(Vt);

    int bh = blockIdx.y;
    int b = bh >> 3, h = bh & 7;
    int q0 = blockIdx.x * 64;
    int tid = threadIdx.x, lane = tid & 31, wid = tid >> 5;
    int wm = wid & 3, wk2 = wid >> 2;
    int gid = lane >> 2, ctg = lane & 3;
    const int a_row = lane & 15;
    const int a_k   = (lane >> 4) * 8;
    const int b_row = (lane & 7) + ((lane >> 4) << 3);
    const int b_k   = ((lane >> 3) & 1) * 8;
    size_t base = ((size_t)b*TT)*1536 + h*HD;
    const float scl = 0.125f;

    // load Q (rope, fp16)
    for (int i = tid; i < 64*16; i += 256) {
        int r = i >> 4, dv = (i & 15) * 4;
        float4 v = rope4(*(const float4*)(QKV + base + (size_t)(q0 + r)*1536 + dv), q0 + r, dv);
        __half2* dst = (__half2*)(Qh + r*FPAD + dv);
        dst[0] = __floats2half2_rn(v.x, v.y);
        dst[1] = __floats2half2_rn(v.z, v.w);
    }

    float m0 = -1e30f, m1 = -1e30f, l0 = 0.f, l1 = 0.f;
    float oacc[8][4];
    #pragma unroll
    for (int i = 0; i < 8; i++)
        #pragma unroll
        for (int j = 0; j < 4; j++) oacc[i][j] = 0.f;

    int row0 = q0 + wm*16 + gid;
    int nkt = (q0 >> 6) + 1;
    for (int kt = 0; kt < nkt; kt++) {
        int k0 = kt * 64;
        __syncthreads();
        for (int i = tid; i < 64*16; i += 256) {
            int r = i >> 4, dv = (i & 15)*4;
            size_t g = base + (size_t)(k0 + r)*1536 + dv;
            float4 kv = rope4(*(const float4*)(QKV + g + 512), k0 + r, dv);
            __half2* kd = (__half2*)(Kh + r*FPAD + dv);
            kd[0] = __floats2half2_rn(kv.x, kv.y);
            kd[1] = __floats2half2_rn(kv.z, kv.w);
            float4 vv = *(const float4*)(QKV + g + 1024);
            Vt[(dv+0)*FPAD + r] = __float2half_rn(vv.x);
            Vt[(dv+1)*FPAD + r] = __float2half_rn(vv.y);
            Vt[(dv+2)*FPAD + r] = __float2half_rn(vv.z);
            Vt[(dv+3)*FPAD + r] = __float2half_rn(vv.w);
        }
        __syncthreads();
        // S = Q @ K^T
        float sacc[4][4];
        #pragma unroll
        for (int nt = 0; nt < 4; nt++)
            #pragma unroll
            for (int j = 0; j < 4; j++) sacc[nt][j] = 0.f;
        #pragma unroll
        for (int kk = 0; kk < 64; kk += 16) {
            uint32_t af[4], bf[2][4];
            LDSM4(af, uq + (uint32_t)((wm*16 + a_row)*FPAD + kk + a_k)*2);
            #pragma unroll
            for (int np = 0; np < 2; np++)
                LDSM4(bf[np], uk + (uint32_t)((wk2*32 + np*16 + b_row)*FPAD + kk + b_k)*2);
            #pragma unroll
            for (int nt = 0; nt < 4; nt++)
                HMMA(sacc[nt], af, bf[nt>>1][(nt&1)*2], bf[nt>>1][(nt&1)*2+1]);
        }
        // scale + causal mask
        bool diag = (kt == nkt - 1);
        #pragma unroll
        for (int nt = 0; nt < 4; nt++) {
            int col = k0 + wk2*32 + nt*8 + ctg*2;
            #pragma unroll
            for (int j = 0; j < 4; j++) {
                int cc = col + (j & 1);
                int rr = row0 + ((j >> 1) << 3);
                sacc[nt][j] = (!diag || cc <= rr) ? sacc[nt][j]*scl : -1e9f;
            }
        }
        // row max over this warp's 32 cols
        float rm0 = fmaxf(fmaxf(sacc[0][0], sacc[0][1]), fmaxf(sacc[1][0], sacc[1][1]));
        rm0 = fmaxf(rm0, fmaxf(fmaxf(sacc[2][0], sacc[2][1]), fmaxf(sacc[3][0], sacc[3][1])));
        float rm1 = fmaxf(fmaxf(sacc[0][2], sacc[0][3]), fmaxf(sacc[1][2], sacc[1][3]));
        rm1 = fmaxf(rm1, fmaxf(fmaxf(sacc[2][2], sacc[2][3]), fmaxf(sacc[3][2], sacc[3][3])));
        rm0 = fmaxf(rm0, __shfl_xor_sync(0xffffffffu, rm0, 1));
        rm0 = fmaxf(rm0, __shfl_xor_sync(0xffffffffu, rm0, 2));
        rm1 = fmaxf(rm1, __shfl_xor_sync(0xffffffffu, rm1, 1));
        rm1 = fmaxf(rm1, __shfl_xor_sync(0xffffffffu, rm1, 2));
        if (ctg == 0) {
            smax[wk2*64 + wm*16 + gid]     = rm0;
            smax[wk2*64 + wm*16 + gid + 8] = rm1;
        }
        __syncthreads();
        float mx0 = fmaxf(smax[wm*16 + gid],     smax[64 + wm*16 + gid]);
        float mx1 = fmaxf(smax[wm*16 + gid + 8], smax[64 + wm*16 + gid + 8]);
        float mn0 = fmaxf(m0, mx0), mn1 = fmaxf(m1, mx1);
        float c0 = __expf(m0 - mn0), c1 = __expf(m1 - mn1);
        m0 = mn0; m1 = mn1;
        // p = exp(s - mn), row sums
        float rs0 = 0.f, rs1 = 0.f;
        #pragma unroll
        for (int nt = 0; nt < 4; nt++) {
            sacc[nt][0] = __expf(sacc[nt][0] - mn0); rs0 += sacc[nt][0];
            sacc[nt][1] = __expf(sacc[nt][1] - mn0); rs0 += sacc[nt][1];
            sacc[nt][2] = __expf(sacc[nt][2] - mn1); rs1 += sacc[nt][2];
            sacc[nt][3] = __expf(sacc[nt][3] - mn1); rs1 += sacc[nt][3];
        }
        rs0 += __shfl_xor_sync(0xffffffffu, rs0, 1);
        rs0 += __shfl_xor_sync(0xffffffffu, rs0, 2);
        rs1 += __shfl_xor_sync(0xffffffffu, rs1, 1);
        rs1 += __shfl_xor_sync(0xffffffffu, rs1, 2);
        if (ctg == 0) {
            ssum[wk2*64 + wm*16 + gid]     = rs0;
            ssum[wk2*64 + wm*16 + gid + 8] = rs1;
        }
        // rescale o
        #pragma unroll
        for (int nh = 0; nh < 8; nh++) {
            oacc[nh][0] *= c0; oacc[nh][1] *= c0;
            oacc[nh][2] *= c1; oacc[nh][3] *= c1;
        }
        __syncthreads();
        l0 = l0*c0 + ssum[wm*16 + gid]     + ssum[64 + wm*16 + gid];
        l1 = l1*c1 + ssum[wm*16 + gid + 8] + ssum[64 + wm*16 + gid + 8];
        // PV: A = P (m16 k32 this warp's k-range), B = Vt
        #pragma unroll
        for (int g = 0; g < 2; g++) {
            uint32_t pf[4];
            pf[0] = f22u(sacc[2*g][0],   sacc[2*g][1]);
            pf[1] = f22u(sacc[2*g][2],   sacc[2*g][3]);
            pf[2] = f22u(sacc[2*g+1][0], sacc[2*g+1][1]);
            pf[3] = f22u(sacc[2*g+1][2], sacc[2*g+1][3]);
            int kof = wk2*32 + g*16;
            #pragma unroll
            for (int nh = 0; nh < 4; nh++) {
                uint32_t bf2[4];
                LDSM4(bf2, uv + (uint32_t)((nh*16 + b_row)*FPAD + kof + b_k)*2);
                HMMA(oacc[2*nh],   pf, bf2[0], bf2[1]);
                HMMA(oacc[2*nh+1], pf, bf2[2], bf2[3]);
            }
        }
    }
    // combine wk2 partials
    __syncthreads();
    if (wk2 == 1) {
        #pragma unroll
        for (int nh = 0; nh < 8; nh++) {
            int c = nh*8 + ctg*2;
            float* o0 = obuf + (wm*16 + gid)*64 + c;
            float* o1 = obuf + (wm*16 + gid + 8)*64 + c;
            o0[0] = oacc[nh][0]; o0[1] = oacc[nh][1];
            o1[0] = oacc[nh][2]; o1[1] = oacc[nh][3];
        }
    }
    __syncthreads();
    if (wk2 == 0) {
        float inv0 = 1.f / l0, inv1 = 1.f / l1;
        #pragma unroll
        for (int nh = 0; nh < 8; nh++) {
            int c = nh*8 + ctg*2;
            const float* o0 = obuf + (wm*16 + gid)*64 + c;
            const float* o1 = obuf + (wm*16 + gid + 8)*64 + c;
            float x0 = (oacc[nh][0] + o0[0]) * inv0;
            float x1 = (oacc[nh][1] + o0[1]) * inv0;
            float y0 = (oacc[nh][2] + o1[0]) * inv1;
            float y1 = (oacc[nh][3] + o1[1]) * inv1;
            size_t r0 = (size_t)(b*TT + q0 + wm*16 + gid)*DD + h*HD + c;
            size_t r1 = (size_t)(b*TT + q0 + wm*16 + gid + 8)*DD + h*HD + c;
            *(__half2*)(Oh + r0) = __floats2half2_rn(x0, x1);
            *(__half2*)(Oh + r1) = __floats2half2_rn(y0, y1);
        }
    }
}

// ---------------- salience logits ----------------
__global__ void logits_kernel(const float* __restrict__ X, const float* __restrict__ sal_W,
                              const float* __restrict__ sal_b, const float* __restrict__ temp,
                              float* __restrict__ out) {
    int row = blockIdx.x;
    int e = threadIdx.x >> 5, lane = threadIdx.x & 31;
    const float* xr = X + (size_t)row*DD;
    float acc = 0.f;
    for (int d = lane; d < DD; d += 32)
        acc += xr[d] * sal_W[d*EH + e];
    acc = warpReduceSum(acc);
    if (lane == 0) {
        float tp = log1pf(expf(temp[e])) + 0.3f;
        out[(size_t)row*EH + e] = (acc + sal_b[e]) / tp;
    }
}

// ---------------- masked softmax pool ----------------
__global__ void pool_kernel(const int* __restrict__ tokens, const float* __restrict__ logits,
                            const float* __restrict__ X, const float* __restrict__ gate_W,
                            const float* __restrict__ gate_b,
                            float* __restrict__ wv_out, float* __restrict__ u_out) {
    int b = blockIdx.x >> 2, e = blockIdx.x & 3;
    int tid = threadIdx.x;
    __shared__ float ws[TT];
    float lg4[4]; int mv4[4];
    float lmax = -1e30f; float lvalid = 0.f;
    #pragma unroll
    for (int p = 0; p < 4; p++) {
        int t = tid + p*128;
        int mv = (tokens[b*TT + t] != 0);
        float lgv = logits[((size_t)b*TT + t)*EH + e];
        float sf = mv ? lgv : -1e9f;
        lg4[p] = sf; mv4[p] = mv;
        lmax = fmaxf(lmax, sf);
        lvalid += (float)mv;
    }
    float mx = blockReduceMax128(lmax);
    float lsum = 0.f;
    #pragma unroll
    for (int p = 0; p < 4; p++) {
        int t = tid + p*128;
        float ev = mv4[p] ? expf(lg4[p] - mx) : 0.f;
        ws[t] = ev;
        lsum += ev;
    }
    float ssum = blockReduceSum128(lsum);
    float nvalid = blockReduceSum128(lvalid);
    float wsc = 1.f / (ssum + 1e-6f);
    __syncthreads();
    float acc = 0.f;
    const float* xb = X + ((size_t)b*TT)*DD + e*EHD + tid;
    for (int t = 0; t < TT; t++)
        acc += ws[t] * xb[(size_t)t*DD];
    acc *= wsc;
    wv_out[b*DD + e*EHD + tid] = acc;
    float gsum = blockReduceSum128(acc * gate_W[tid]);
    if (tid == 0) {
        float gl = gsum + gate_b[0];
        float u = (nvalid > 0.f) ? 1.f/(1.f+expf(-gl)) : 0.f;
        u_out[b*EH + e] = u;
    }
}

// ---------------- fast/slow state update ----------------
__global__ void update_kernel(const float* __restrict__ wv, const float* __restrict__ u,
                              const float* __restrict__ sal_rms,
                              const float* __restrict__ fast, const float* __restrict__ slow,
                              float* __restrict__ out_fast, float* __restrict__ out_slow) {
    int b = blockIdx.x, tid = threadIdx.x;
    float4 v = ((const float4*)(wv + b*DD))[tid];
    float ss = blockReduceSum128(v.x*v.x + v.y*v.y + v.z*v.z + v.w*v.w);
    float inv = rsqrtf(ss * (1.f/DD) + 1e-6f);
    float4 sr = ((const float4*)sal_rms)[tid];
    int e = tid >> 5;
    float uu = u[b*EH + e];
    float4 f = ((const float4*)(fast + b*DD))[tid];
    float4 s = ((const float4*)(slow + b*DD))[tid];
    float4 wn;
    wn.x = v.x*inv*sr.x; wn.y = v.y*inv*sr.y; wn.z = v.z*inv*sr.z; wn.w = v.w*inv*sr.w;
    float4 nf, ns;
    nf.x = (1.f-uu)*f.x + uu*wn.x;  nf.y = (1.f-uu)*f.y + uu*wn.y;
    nf.z = (1.f-uu)*f.z + uu*wn.z;  nf.w = (1.f-uu)*f.w + uu*wn.w;
    float ud = 0.1f*uu;
    ns.x = (1.f-ud)*s.x + ud*wn.x;  ns.y = (1.f-ud)*s.y + ud*wn.y;
    ns.z = (1.f-ud)*s.z + ud*wn.z;  ns.w = (1.f-ud)*s.w + ud*wn.w;
    ((float4*)(out_fast + b*DD))[tid] = nf;
    ((float4*)(out_slow + b*DD))[tid] = ns;
}

// ---------------- launch ----------------
extern "C" void kernel_launch(void* const* d_in, const int* in_sizes, int n_in,
                              void* d_out, int out_size) {
    const int*   tokens = (const int*)  d_in[0];
    const int*   prev   = (const int*)  d_in[1];
    const float* fast   = (const float*)d_in[2];
    const float* slow   = (const float*)d_in[3];
    const float* embed  = (const float*)d_in[4];
    const float* ctx_W  = (const float*)d_in[5];
    const float* ctx_b  = (const float*)d_in[6];
    const float* etab   = (const float*)d_in[7];
    const float* egate  = (const float*)d_in[8];
    const float* ln1    = (const float*)d_in[9];
    const float* Wq     = (const float*)d_in[10];
    const float* bq     = (const float*)d_in[11];
    const float* Wk     = (const float*)d_in[12];
    const float* bk     = (const float*)d_in[13];
    const float* Wv     = (const float*)d_in[14];
    const float* bv     = (const float*)d_in[15];
    const float* Wo     = (const float*)d_in[16];
    const float* bo     = (const float*)d_in[17];
    const float* ln2    = (const float*)d_in[18];
    const float* W1     = (const float*)d_in[19];
    const float* W2     = (const float*)d_in[20];
    const float* ln_f   = (const float*)d_in[21];
    const float* sal_W  = (const float*)d_in[22];
    const float* sal_b  = (const float*)d_in[23];
    const float* temp   = (const float*)d_in[24];
    const float* gate_W = (const float*)d_in[25];
    const float* gate_b = (const float*)d_in[26];
    const float* sal_rms= (const float*)d_in[27];
    float* out = (float*)d_out;

    float *gx, *gqkv, *gffg, *gctx, *glog, *gwv, *gu;
    __half *nx, *at, *ff;
    __half *wA, *w1, *w2;
    cudaGetSymbolAddress((void**)&gx,   g_x);
    cudaGetSymbolAddress((void**)&gqkv, g_qkv);
    cudaGetSymbolAddress((void**)&gffg, g_ffg);
    cudaGetSymbolAddress((void**)&gctx, g_ctx);
    cudaGetSymbolAddress((void**)&glog, g_logits);
    cudaGetSymbolAddress((void**)&gwv,  g_wv);
    cudaGetSymbolAddress((void**)&gu,   g_u);
    cudaGetSymbolAddress((void**)&nx,   g_nx);
    cudaGetSymbolAddress((void**)&at,   g_at);
    cudaGetSymbolAddress((void**)&ff,   g_ff);
    cudaGetSymbolAddress((void**)&wA,   g_wqkvo);
    cudaGetSymbolAddress((void**)&w1,   g_w1);
    cudaGetSymbolAddress((void**)&w2,   g_w2);

    cudaFuncSetAttribute(hgemm<0>, cudaFuncAttributeMaxDynamicSharedMemorySize, HSMEM);
    cudaFuncSetAttribute(hgemm<1>, cudaFuncAttributeMaxDynamicSharedMemorySize, HSMEM);
    cudaFuncSetAttribute(hgemm<2>, cudaFuncAttributeMaxDynamicSharedMemorySize, HSMEM);
    cudaFuncSetAttribute(hgemm<3>, cudaFuncAttributeMaxDynamicSharedMemorySize, HSMEM);
    cudaFuncSetAttribute(hgemm<4>, cudaFuncAttributeMaxDynamicSharedMemorySize, HSMEM);
    cudaFuncSetAttribute(flash_kernel, cudaFuncAttributeMaxDynamicSharedMemorySize, FSMEM);

    dim3 tb(32, 8);
    dim3 gD(NTOK/128, DD/128);
    dim3 gQKV(NTOK/128, (3*DD)/128);
    dim3 gF(NTOK/128, FF/128);

    // ncu captures launch #4 -> fused-QKV hgemm.
    tsplit4_kernel<<<dim3(DD/32, DD/32, 4*LL), tb>>>(Wq, Wk, Wv, Wo, wA);                // 1
    ctx_kernel<<<BB, 512>>>(fast, slow, ctx_W, ctx_b, gctx);                             // 2
    embed_fused_kernel<<<NTOK, 128>>>(tokens, prev, embed, gctx, etab, egate, ln1,
                                      gx, nx);                                           // 3

    for (int l = 0; l < LL; l++) {
        size_t wo  = (size_t)l*4*DD*DD;
        size_t w1o = (size_t)l*2*FF*DD;
        size_t w2o = (size_t)l*DD*FF;
        if (l > 0)
            rmsnorm_half_kernel<<<NTOK, 128>>>(gx, ln1 + l*DD, nx);
        hgemm<0><<<gQKV, 256, HSMEM>>>(nx, wA + wo,
                                       bq + l*DD, bk + l*DD, bv + l*DD,
                                       nullptr, nullptr, gqkv, nullptr,
                                       NTOK, 3*DD, DD);
        if (l == 0) {
            tsplitW1_kernel<<<dim3(FF/32, DD/32, 2*LL), tb>>>(W1, w1);
            tsplit_kernel<<<dim3(DD/32, FF/32, LL), tb>>>(W2, DD, (size_t)FF*DD, w2, (size_t)DD*FF, FF);
        }
        flash_kernel<<<dim3(TT/64, BB*HH), 256, FSMEM>>>(gqkv, at);
        hgemm<1><<<gD, 256, HSMEM>>>(at, wA + wo + (size_t)1536*DD,
                                     bo + l*DD, nullptr, nullptr, gx, nullptr,
                                     gx, nullptr, NTOK, DD, DD);
        rmsnorm_half_kernel<<<NTOK, 128>>>(gx, ln2 + l*DD, nx);
        hgemm<2><<<gF, 256, HSMEM>>>(nx, w1 + w1o,
                                     nullptr, nullptr, nullptr, nullptr, nullptr,
                                     gffg, nullptr, NTOK, FF, DD);
        hgemm<3><<<gF, 256, HSMEM>>>(nx, w1 + w1o + (size_t)FF*DD,
                                     nullptr, nullptr, nullptr, nullptr, gffg,
                                     nullptr, ff, NTOK, FF, DD);
        hgemm<4><<<gD, 256, HSMEM>>>(ff, w2 + w2o,
                                     nullptr, nullptr, nullptr, gx, nullptr,
                                     gx, nullptr, NTOK, DD, FF);
    }
    rmsnorm_kernel<<<NTOK, 128>>>(gx, ln_f, out);
    logits_kernel<<<NTOK, 128>>>(out, sal_W, sal_b, temp, glog);
    pool_kernel<<<BB*EH, 128>>>(tokens, glog, out, gate_W, gate_b, gwv, gu);
    update_kernel<<<BB, 128>>>(gwv, gu, sal_rms, fast, slow,
                               out + (size_t)NTOK*DD,
                               out + (size_t)NTOK*DD + BB*DD);
}